// round 8
// baseline (speedup 1.0000x reference)
#include <cuda_runtime.h>
#include <cuda_bf16.h>
#include <math.h>
#include <stdint.h>

#define NN 1024
#define TT 12
#define LD 4352   // padded cols; GEMM covers 33*128 = 4224

// ---------------- scratch ----------------
__device__ float g_M [2 * NN * NN];             // [A ; A2] fp32
__device__ __nv_bfloat16 g_Mh[2 * NN * NN];     // bf16 hi of [A ; 2*A2]
__device__ __nv_bfloat16 g_Ml[2 * NN * NN];     // bf16 lo
__device__ float g_cat1[NN * LD];
__device__ float g_cat2[NN * LD];
__device__ __nv_bfloat16 g_c1h[NN * LD];
__device__ __nv_bfloat16 g_c1l[NN * LD];
__device__ __nv_bfloat16 g_c2h[NN * LD];
__device__ __nv_bfloat16 g_c2l[NN * LD];
__device__ float g_Y1  [NN * LD];
__device__ float g_Y2  [NN * LD];
__device__ float g_h [NN * 64 * 64];
__device__ float g_r [NN * 64 * 64];
__device__ float g_go[NN * 64];

// ---------------- helpers ----------------
__device__ __forceinline__ uint32_t smem_u32(const void* p) {
    uint32_t a;
    asm("{ .reg .u64 t; cvta.to.shared.u64 t, %1; cvt.u32.u64 %0, t; }" : "=r"(a) : "l"(p));
    return a;
}
__device__ __forceinline__ void cpa16(uint32_t dst, const void* src) {
    asm volatile("cp.async.cg.shared.global [%0], [%1], 16;" :: "r"(dst), "l"(src));
}
__device__ __forceinline__ void ldsm4(uint32_t* r, uint32_t a) {
    asm volatile("ldmatrix.sync.aligned.m8n8.x4.shared.b16 {%0,%1,%2,%3}, [%4];"
        : "=r"(r[0]), "=r"(r[1]), "=r"(r[2]), "=r"(r[3]) : "r"(a));
}
__device__ __forceinline__ void ldsm4t(uint32_t* r, uint32_t a) {
    asm volatile("ldmatrix.sync.aligned.m8n8.x4.trans.shared.b16 {%0,%1,%2,%3}, [%4];"
        : "=r"(r[0]), "=r"(r[1]), "=r"(r[2]), "=r"(r[3]) : "r"(a));
}
__device__ __forceinline__ void mma_bf16(float* d, const uint32_t* a, uint32_t b0, uint32_t b1) {
    asm volatile("mma.sync.aligned.m16n8k16.row.col.f32.bf16.bf16.f32 "
        "{%0,%1,%2,%3},{%4,%5,%6,%7},{%8,%9},{%0,%1,%2,%3};"
        : "+f"(d[0]), "+f"(d[1]), "+f"(d[2]), "+f"(d[3])
        : "r"(a[0]), "r"(a[1]), "r"(a[2]), "r"(a[3]), "r"(b0), "r"(b1));
}
__device__ __forceinline__ void bsplit(float v, __nv_bfloat16& h16, __nv_bfloat16& l16) {
    h16 = __float2bfloat16(v);
    l16 = __float2bfloat16(v - __bfloat162float(h16));
}
__device__ __forceinline__ uint32_t swA(uint32_t off) { return off ^ ((off >> 3) & 0x70); }
__device__ __forceinline__ uint32_t swB(uint32_t off) { return off ^ (((off >> 8) & 7) << 4); }

// ---------------- support: A = softmax(relu(E E^T), rows) ----------------
__global__ void build_support_kernel(const float* __restrict__ emb, float* __restrict__ A) {
    __shared__ float se[NN * 8];
    __shared__ float row[NN];
    __shared__ float wred[8];
    __shared__ float red;
    int n = blockIdx.x, tid = threadIdx.x;
    for (int i = tid; i < NN * 8; i += 256) se[i] = emb[i];
    __syncthreads();
    float e[8];
    #pragma unroll
    for (int j = 0; j < 8; j++) e[j] = se[n * 8 + j];
    float mx = 0.f;
    for (int m = tid; m < NN; m += 256) {
        const float* em = &se[m * 8];
        float s = 0.f;
        #pragma unroll
        for (int j = 0; j < 8; j++) s += e[j] * em[j];
        s = fmaxf(s, 0.f);
        row[m] = s;
        mx = fmaxf(mx, s);
    }
    #pragma unroll
    for (int o = 16; o; o >>= 1) mx = fmaxf(mx, __shfl_xor_sync(0xffffffffu, mx, o));
    if ((tid & 31) == 0) wred[tid >> 5] = mx;
    __syncthreads();
    if (tid == 0) { float v = wred[0]; for (int w = 1; w < 8; w++) v = fmaxf(v, wred[w]); red = v; }
    __syncthreads();
    float bmax = red, sum = 0.f;
    for (int m = tid; m < NN; m += 256) { float v = expf(row[m] - bmax); row[m] = v; sum += v; }
    #pragma unroll
    for (int o = 16; o; o >>= 1) sum += __shfl_xor_sync(0xffffffffu, sum, o);
    if ((tid & 31) == 0) wred[tid >> 5] = sum;
    __syncthreads();
    if (tid == 0) { float v = 0.f; for (int w = 0; w < 8; w++) v += wred[w]; red = v; }
    __syncthreads();
    float inv = 1.f / red;
    for (int m = tid; m < NN; m += 256) A[n * NN + m] = row[m] * inv;
}

// ---------------- A2 = A @ A ----------------
__global__ void __launch_bounds__(256, 2) gemmA2(const float* __restrict__ A, float* __restrict__ A2) {
    __shared__ __align__(16) float As[2][8][132];
    __shared__ __align__(16) float Bs[2][8][128];
    int tid = threadIdx.x;
    int row0 = blockIdx.y * 128, col0 = blockIdx.x * 128;
    int arow = tid >> 1, acol4 = (tid & 1) << 2;
    int brow = tid >> 5, bcol4 = (tid & 31) << 2;
    int tx = tid & 15, ty = tid >> 4;
    const float* Ap = A + (size_t)(row0 + arow) * NN + acol4;
    const float* Xp = A + (size_t)brow * NN + col0 + bcol4;
    float acc[8][8];
    #pragma unroll
    for (int i = 0; i < 8; i++)
        #pragma unroll
        for (int j = 0; j < 8; j++) acc[i][j] = 0.f;
    float4 av = *(const float4*)Ap;
    float4 bv = *(const float4*)Xp;
    int buf = 0;
    As[0][acol4 + 0][arow] = av.x; As[0][acol4 + 1][arow] = av.y;
    As[0][acol4 + 2][arow] = av.z; As[0][acol4 + 3][arow] = av.w;
    *(float4*)&Bs[0][brow][bcol4] = bv;
    __syncthreads();
    for (int kt = 1; kt < 128; kt++) {
        av = *(const float4*)(Ap + kt * 8);
        bv = *(const float4*)(Xp + (size_t)(kt * 8) * NN);
        #pragma unroll
        for (int kk = 0; kk < 8; kk++) {
            float4 a0 = *(const float4*)&As[buf][kk][ty * 4];
            float4 a1 = *(const float4*)&As[buf][kk][64 + ty * 4];
            float4 b0 = *(const float4*)&Bs[buf][kk][tx * 4];
            float4 b1 = *(const float4*)&Bs[buf][kk][64 + tx * 4];
            float a[8] = {a0.x,a0.y,a0.z,a0.w,a1.x,a1.y,a1.z,a1.w};
            float b[8] = {b0.x,b0.y,b0.z,b0.w,b1.x,b1.y,b1.z,b1.w};
            #pragma unroll
            for (int i = 0; i < 8; i++)
                #pragma unroll
                for (int j = 0; j < 8; j++) acc[i][j] = fmaf(a[i], b[j], acc[i][j]);
        }
        buf ^= 1;
        As[buf][acol4 + 0][arow] = av.x; As[buf][acol4 + 1][arow] = av.y;
        As[buf][acol4 + 2][arow] = av.z; As[buf][acol4 + 3][arow] = av.w;
        *(float4*)&Bs[buf][brow][bcol4] = bv;
        __syncthreads();
    }
    #pragma unroll
    for (int kk = 0; kk < 8; kk++) {
        float4 a0 = *(const float4*)&As[buf][kk][ty * 4];
        float4 a1 = *(const float4*)&As[buf][kk][64 + ty * 4];
        float4 b0 = *(const float4*)&Bs[buf][kk][tx * 4];
        float4 b1 = *(const float4*)&Bs[buf][kk][64 + tx * 4];
        float a[8] = {a0.x,a0.y,a0.z,a0.w,a1.x,a1.y,a1.z,a1.w};
        float b[8] = {b0.x,b0.y,b0.z,b0.w,b1.x,b1.y,b1.z,b1.w};
        #pragma unroll
        for (int i = 0; i < 8; i++)
            #pragma unroll
            for (int j = 0; j < 8; j++) acc[i][j] = fmaf(a[i], b[j], acc[i][j]);
    }
    #pragma unroll
    for (int i = 0; i < 8; i++) {
        int grow = row0 + ((i < 4) ? (ty * 4 + i) : (64 + ty * 4 + i - 4));
        float* yp = A2 + (size_t)grow * NN;
        *(float4*)(yp + col0 + tx * 4)       = make_float4(acc[i][0], acc[i][1], acc[i][2], acc[i][3]);
        *(float4*)(yp + col0 + 64 + tx * 4)  = make_float4(acc[i][4], acc[i][5], acc[i][6], acc[i][7]);
    }
}

// ---------------- M -> bf16 hi/lo (fold 2x into bottom half) ----------------
__global__ void convert_M(const float* __restrict__ M,
                          __nv_bfloat16* __restrict__ Mh, __nv_bfloat16* __restrict__ Ml) {
    int i = blockIdx.x * 256 + threadIdx.x;
    float v = M[i];
    if (i >= NN * NN) v *= 2.f;
    __nv_bfloat16 h, l;
    bsplit(v, h, l);
    Mh[i] = h;
    Ml[i] = l;
}

// ---------------- HMMA split-bf16 diffusion GEMM ----------------
// M-tile 256 x N-tile 128, KC=32, 512 threads (16 warps: wm 0..7, wn 0..1),
// 2-stage cp.async. Stage (48KB): A 256 rows x [hi 64B | lo 64B] 32KB | Bh 8KB | Bl 8KB
// grid (33, 8): col0 = bx*128, row0 = by*256 over [A ; 2*A2] (2048 rows)
#define KC 32
#define STG 49152
#define NIT 32
__global__ void __launch_bounds__(512, 1) hmma_gemm(
    const __nv_bfloat16* __restrict__ Mh, const __nv_bfloat16* __restrict__ Ml,
    const __nv_bfloat16* __restrict__ Xh, const __nv_bfloat16* __restrict__ Xl,
    const float* __restrict__ Xf, float* __restrict__ Y1, float* __restrict__ Y2)
{
    extern __shared__ __align__(1024) char smem[];
    uint32_t sb = smem_u32(smem);
    int tid = threadIdx.x;
    int lane = tid & 31, wid = tid >> 5;
    int wm = wid >> 1, wn = wid & 1;
    int row0 = blockIdx.y * 256;
    int col0 = blockIdx.x * 128;

    float acc[2][8][4];
    #pragma unroll
    for (int mt = 0; mt < 2; mt++)
        #pragma unroll
        for (int nt = 0; nt < 8; nt++)
            #pragma unroll
            for (int j = 0; j < 4; j++) acc[mt][nt][j] = 0.f;

    auto load_stage = [&](int it) {
        uint32_t base = sb + (it & 1) * STG;
        int k0 = it * KC;
        // A: 256 rows x 128B (hi 64B | lo 64B) -> 2048 16B chunks
        #pragma unroll
        for (int i = tid; i < 2048; i += 512) {
            int r = i >> 3, c = i & 7;
            uint32_t sw = swA((uint32_t)(r * 128 + c * 16));
            const __nv_bfloat16* src = (c < 4)
                ? (Mh + (size_t)(row0 + r) * NN + k0 + c * 8)
                : (Ml + (size_t)(row0 + r) * NN + k0 + (c - 4) * 8);
            cpa16(base + sw, src);
        }
        // B: 32 k-rows x 256B, hi then lo -> 1024 chunks
        #pragma unroll
        for (int i = tid; i < 1024; i += 512) {
            int half = i >> 9;
            int j = i & 511;
            int k = j >> 4, c = j & 15;
            uint32_t sw = swB((uint32_t)(k * 256 + c * 16));
            const __nv_bfloat16* src = half
                ? (Xl + (size_t)(k0 + k) * LD + col0 + c * 8)
                : (Xh + (size_t)(k0 + k) * LD + col0 + c * 8);
            cpa16(base + 32768 + half * 8192 + sw, src);
        }
        asm volatile("cp.async.commit_group;" ::: "memory");
    };

    load_stage(0);
    load_stage(1);

    int a_r = wm * 32 + (lane & 15);
    int a_ch = (lane >> 4);
    int b_k = (lane & 7) + ((lane >> 3) & 1) * 8;
    int b_n8 = ((lane >> 4) & 1) * 8;

    #pragma unroll 1
    for (int it = 0; it < NIT; it++) {
        int buf = it & 1;
        if (it + 1 < NIT) asm volatile("cp.async.wait_group 1;" ::: "memory");
        else              asm volatile("cp.async.wait_group 0;" ::: "memory");
        __syncthreads();
        uint32_t base = sb + buf * STG;
        #pragma unroll
        for (int kk = 0; kk < 2; kk++) {
            uint32_t aH[2][4], aL[2][4];
            #pragma unroll
            for (int mt = 0; mt < 2; mt++) {
                uint32_t roff = (uint32_t)((a_r + mt * 16) * 128);
                ldsm4(aH[mt], base + swA(roff + (kk * 2 + a_ch) * 16));
                ldsm4(aL[mt], base + swA(roff + 64 + (kk * 2 + a_ch) * 16));
            }
            #pragma unroll
            for (int p = 0; p < 4; p++) {
                uint32_t bH[4], bL[4];
                int nb = wn * 64 + p * 16 + b_n8;
                uint32_t off = swB((uint32_t)((kk * 16 + b_k) * 256 + nb * 2));
                ldsm4t(bH, base + 32768 + off);
                ldsm4t(bL, base + 40960 + off);
                #pragma unroll
                for (int mt = 0; mt < 2; mt++) {
                    mma_bf16(acc[mt][2 * p],     aH[mt], bH[0], bH[1]);
                    mma_bf16(acc[mt][2 * p],     aH[mt], bL[0], bL[1]);
                    mma_bf16(acc[mt][2 * p],     aL[mt], bH[0], bH[1]);
                    mma_bf16(acc[mt][2 * p + 1], aH[mt], bH[2], bH[3]);
                    mma_bf16(acc[mt][2 * p + 1], aH[mt], bL[2], bL[3]);
                    mma_bf16(acc[mt][2 * p + 1], aL[mt], bH[2], bH[3]);
                }
            }
        }
        __syncthreads();
        if (it + 2 < NIT) load_stage(it + 2);
    }

    // epilogue
    int r_lo = lane >> 2;
    int c_lo = (lane & 3) * 2;
    if (blockIdx.y < 4) {
        #pragma unroll
        for (int mt = 0; mt < 2; mt++) {
            int r = row0 + wm * 32 + mt * 16 + r_lo;
            #pragma unroll
            for (int nt = 0; nt < 8; nt++) {
                int c = col0 + wn * 64 + nt * 8 + c_lo;
                *(float2*)(Y1 + (size_t)r * LD + c)       = make_float2(acc[mt][nt][0], acc[mt][nt][1]);
                *(float2*)(Y1 + (size_t)(r + 8) * LD + c) = make_float2(acc[mt][nt][2], acc[mt][nt][3]);
            }
        }
    } else {
        #pragma unroll
        for (int mt = 0; mt < 2; mt++) {
            int r = row0 - 1024 + wm * 32 + mt * 16 + r_lo;
            #pragma unroll
            for (int nt = 0; nt < 8; nt++) {
                int c = col0 + wn * 64 + nt * 8 + c_lo;
                float2 x0 = *(const float2*)(Xf + (size_t)r * LD + c);
                float2 x1 = *(const float2*)(Xf + (size_t)(r + 8) * LD + c);
                *(float2*)(Y2 + (size_t)r * LD + c)       = make_float2(acc[mt][nt][0] - x0.x, acc[mt][nt][1] - x0.y);
                *(float2*)(Y2 + (size_t)(r + 8) * LD + c) = make_float2(acc[mt][nt][2] - x1.x, acc[mt][nt][3] - x1.y);
            }
        }
    }
}

// ---------------- fused gate ----------------
template <int C>
__global__ void __launch_bounds__(256) gate_kernel(
    const float* __restrict__ F0, const float* __restrict__ F1, const float* __restrict__ F2,
    const float* __restrict__ W, const float* __restrict__ bias,
    const float* __restrict__ h, float* __restrict__ rbuf,
    float* __restrict__ cat2, __nv_bfloat16* __restrict__ c2h, __nv_bfloat16* __restrict__ c2l)
{
    constexpr int K3  = 3 * C;
    constexpr int LDF = ((K3 + 3) / 4) * 4;
    extern __shared__ float sm[];
    float* feats = sm;
    float* Ws    = sm + 64 * LDF;
    float* bs    = Ws + K3 * 128;
    int nblk = blockIdx.x, tid = threadIdx.x;
    size_t base = (size_t)nblk * LD;
    for (int idx = tid; idx < 64 * C; idx += 256) {
        int r = idx / C, c = idx - r * C;
        float* fd = &feats[r * LDF + c];
        fd[0]     = F0[base + idx];
        fd[C]     = F1[base + idx];
        fd[2 * C] = F2[base + idx];
    }
    for (int idx = tid; idx < K3 * 128; idx += 256) Ws[idx] = W[idx];
    if (tid < 128) bs[tid] = bias[tid];
    __syncthreads();

    int ft = tid & 15, rt = tid >> 4;
    int f0 = ft * 4, r0 = rt * 4;
    float acc[4][8];
    #pragma unroll
    for (int i = 0; i < 4; i++)
        #pragma unroll
        for (int j = 0; j < 4; j++) { acc[i][j] = bs[f0 + j]; acc[i][j + 4] = bs[64 + f0 + j]; }
    int k = 0;
    for (; k + 4 <= K3; k += 4) {
        float4 a4[4];
        #pragma unroll
        for (int i = 0; i < 4; i++) a4[i] = *(const float4*)&feats[(r0 + i) * LDF + k];
        #pragma unroll
        for (int kk = 0; kk < 4; kk++) {
            float4 wz = *(const float4*)&Ws[(k + kk) * 128 + f0];
            float4 wr = *(const float4*)&Ws[(k + kk) * 128 + 64 + f0];
            float wv[8] = {wz.x,wz.y,wz.z,wz.w,wr.x,wr.y,wr.z,wr.w};
            #pragma unroll
            for (int i = 0; i < 4; i++) {
                float ai = ((const float*)&a4[i])[kk];
                #pragma unroll
                for (int j = 0; j < 8; j++) acc[i][j] = fmaf(ai, wv[j], acc[i][j]);
            }
        }
    }
    for (; k < K3; k++) {
        #pragma unroll
        for (int i = 0; i < 4; i++) {
            float ai = feats[(r0 + i) * LDF + k];
            #pragma unroll
            for (int j = 0; j < 4; j++) {
                acc[i][j]     = fmaf(ai, Ws[k * 128 + f0 + j], acc[i][j]);
                acc[i][j + 4] = fmaf(ai, Ws[k * 128 + 64 + f0 + j], acc[i][j + 4]);
            }
        }
    }
    #pragma unroll
    for (int i = 0; i < 4; i++) {
        int b = r0 + i;
        int grow = nblk * 64 + b;
        #pragma unroll
        for (int j = 0; j < 4; j++) {
            int f = f0 + j;
            float z = 1.f / (1.f + expf(-acc[i][j]));
            float v = z * h[grow * 64 + f];
            size_t pos = base + b * C + (C - 64) + f;
            cat2[pos] = v;
            __nv_bfloat16 hh, ll;
            bsplit(v, hh, ll);
            c2h[pos] = hh;
            c2l[pos] = ll;
            float rr = 1.f / (1.f + expf(-acc[i][j + 4]));
            rbuf[grow * 64 + f] = rr;
        }
    }
}

// ---------------- fused update (+ next-cat1 write, + optional proj) ----------------
template <int C, bool PROJ>
__global__ void __launch_bounds__(256) update_kernel(
    const float* __restrict__ F0, const float* __restrict__ F1, const float* __restrict__ F2,
    const float* __restrict__ W, const float* __restrict__ bias,
    const float* __restrict__ rbuf, float* __restrict__ h,
    float* __restrict__ cat1, __nv_bfloat16* __restrict__ c1h, __nv_bfloat16* __restrict__ c1l,
    int Cn, int offn,
    const float* __restrict__ pW, const float* __restrict__ pb,
    float* __restrict__ go, float* __restrict__ out, int t)
{
    constexpr int K3  = 3 * C;
    constexpr int LDF = ((K3 + 3) / 4) * 4;
    extern __shared__ float sm[];
    float* feats = sm;
    float* Ws    = sm + 64 * LDF;
    float* bs    = Ws + K3 * 64;
    float* pWs   = bs + 64;
    int nblk = blockIdx.x, tid = threadIdx.x;
    size_t base = (size_t)nblk * LD;
    for (int idx = tid; idx < 64 * C; idx += 256) {
        int r = idx / C, c = idx - r * C;
        float* fd = &feats[r * LDF + c];
        fd[0]     = F0[base + idx];
        fd[C]     = F1[base + idx];
        fd[2 * C] = F2[base + idx];
    }
    for (int idx = tid; idx < K3 * 64; idx += 256) Ws[idx] = W[idx];
    if (tid < 64) {
        bs[tid] = bias[tid];
        if (PROJ) pWs[tid] = pW[tid];
    }
    __syncthreads();

    int ft = tid & 15, rt = tid >> 4;
    int f0 = ft * 4, r0 = rt * 4;
    float acc[4][4];
    #pragma unroll
    for (int i = 0; i < 4; i++)
        #pragma unroll
        for (int j = 0; j < 4; j++) acc[i][j] = bs[f0 + j];
    int k = 0;
    for (; k + 4 <= K3; k += 4) {
        float4 a4[4];
        #pragma unroll
        for (int i = 0; i < 4; i++) a4[i] = *(const float4*)&feats[(r0 + i) * LDF + k];
        #pragma unroll
        for (int kk = 0; kk < 4; kk++) {
            float4 w4 = *(const float4*)&Ws[(k + kk) * 64 + f0];
            float wj[4] = {w4.x, w4.y, w4.z, w4.w};
            #pragma unroll
            for (int i = 0; i < 4; i++) {
                float ai = ((const float*)&a4[i])[kk];
                #pragma unroll
                for (int j = 0; j < 4; j++) acc[i][j] = fmaf(ai, wj[j], acc[i][j]);
            }
        }
    }
    for (; k < K3; k++) {
        #pragma unroll
        for (int i = 0; i < 4; i++) {
            float ai = feats[(r0 + i) * LDF + k];
            #pragma unroll
            for (int j = 0; j < 4; j++) acc[i][j] = fmaf(ai, Ws[k * 64 + f0 + j], acc[i][j]);
        }
    }
    #pragma unroll
    for (int i = 0; i < 4; i++) {
        int b = r0 + i;
        int grow = nblk * 64 + b;
        float s = 0.f;
        #pragma unroll
        for (int j = 0; j < 4; j++) {
            int f = f0 + j;
            float hc = tanhf(acc[i][j]);
            float rr = rbuf[grow * 64 + f];
            float ho = h[grow * 64 + f];
            float hn = rr * ho + (1.f - rr) * hc;
            h[grow * 64 + f] = hn;
            size_t pos = base + (size_t)b * Cn + offn + f;
            cat1[pos] = hn;
            __nv_bfloat16 hh, ll;
            bsplit(hn, hh, ll);
            c1h[pos] = hh;
            c1l[pos] = ll;
            if (PROJ) s = fmaf(hn, pWs[f], s);
        }
        if (PROJ) {
            #pragma unroll
            for (int o = 8; o; o >>= 1) s += __shfl_xor_sync(0xffffffffu, s, o);
            if (ft == 0) {
                float v = s + pb[0];
                go[grow] = v;
                out[(size_t)(b * TT + t) * NN + nblk] = v;
            }
        }
    }
}

// ---------------- per-step column injection ----------------
__global__ void inject_enc(const float* __restrict__ x, int t,
                           float* __restrict__ cat1, __nv_bfloat16* __restrict__ c1h, __nv_bfloat16* __restrict__ c1l,
                           float* __restrict__ cat2, __nv_bfloat16* __restrict__ c2h, __nv_bfloat16* __restrict__ c2l) {
    int b = blockIdx.x, n = threadIdx.x;
    float v = x[(size_t)(b * TT + t) * NN + n];
    __nv_bfloat16 hh, ll;
    bsplit(v, hh, ll);
    size_t pos = (size_t)n * LD + b * 65;
    cat1[pos] = v; c1h[pos] = hh; c1l[pos] = ll;
    cat2[pos] = v; c2h[pos] = hh; c2l[pos] = ll;
}
__global__ void inject_dec(const float* __restrict__ yc, int t, const float* __restrict__ go,
                           float* __restrict__ cat1, __nv_bfloat16* __restrict__ c1h, __nv_bfloat16* __restrict__ c1l,
                           float* __restrict__ cat2, __nv_bfloat16* __restrict__ c2h, __nv_bfloat16* __restrict__ c2l) {
    int b = blockIdx.x, n = threadIdx.x;
    float v0 = go[n * 64 + b];
    float v1 = yc[(size_t)(b * TT + t) * NN + n];
    __nv_bfloat16 h0, l0, h1, l1;
    bsplit(v0, h0, l0);
    bsplit(v1, h1, l1);
    size_t pos = (size_t)n * LD + b * 66;
    cat1[pos] = v0; c1h[pos] = h0; c1l[pos] = l0;
    cat2[pos] = v0; c2h[pos] = h0; c2l[pos] = l0;
    cat1[pos + 1] = v1; c1h[pos + 1] = h1; c1l[pos + 1] = l1;
    cat2[pos + 1] = v1; c2h[pos + 1] = h1; c2l[pos + 1] = l1;
}

// ---------------- orchestration ----------------
extern "C" void kernel_launch(void* const* d_in, const int* in_sizes, int n_in,
                              void* d_out, int out_size) {
    const float* x    = (const float*)d_in[0];
    const float* ycov = (const float*)d_in[1];
    const float* emb  = (const float*)d_in[2];
    const float* egW  = (const float*)d_in[3];
    const float* egb  = (const float*)d_in[4];
    const float* euW  = (const float*)d_in[5];
    const float* eub  = (const float*)d_in[6];
    const float* dgW  = (const float*)d_in[7];
    const float* dgb  = (const float*)d_in[8];
    const float* duW  = (const float*)d_in[9];
    const float* dub  = (const float*)d_in[10];
    const float* pW   = (const float*)d_in[11];
    const float* pb   = (const float*)d_in[12];
    float* out = (float*)d_out;

    float *pM, *pc1, *pc2, *pY1, *pY2, *ph, *pr, *pgo;
    __nv_bfloat16 *pMh, *pMl, *p1h, *p1l, *p2h, *p2l;
    cudaGetSymbolAddress((void**)&pM,  g_M);
    cudaGetSymbolAddress((void**)&pMh, g_Mh);
    cudaGetSymbolAddress((void**)&pMl, g_Ml);
    cudaGetSymbolAddress((void**)&pc1, g_cat1);
    cudaGetSymbolAddress((void**)&pc2, g_cat2);
    cudaGetSymbolAddress((void**)&p1h, g_c1h);
    cudaGetSymbolAddress((void**)&p1l, g_c1l);
    cudaGetSymbolAddress((void**)&p2h, g_c2h);
    cudaGetSymbolAddress((void**)&p2l, g_c2l);
    cudaGetSymbolAddress((void**)&pY1, g_Y1);
    cudaGetSymbolAddress((void**)&pY2, g_Y2);
    cudaGetSymbolAddress((void**)&ph,  g_h);
    cudaGetSymbolAddress((void**)&pr,  g_r);
    cudaGetSymbolAddress((void**)&pgo, g_go);

    const int smG65 = (64 * 196 + 195 * 128 + 128) * 4;
    const int smG66 = (64 * 200 + 198 * 128 + 128) * 4;
    const int smU65 = (64 * 196 + 195 * 64 + 64 + 80) * 4;
    const int smU66 = (64 * 200 + 198 * 64 + 64 + 80) * 4;
    const int smHM  = 2 * STG;   // 98304
    cudaFuncSetAttribute((const void*)gate_kernel<65>,          cudaFuncAttributeMaxDynamicSharedMemorySize, smG65);
    cudaFuncSetAttribute((const void*)gate_kernel<66>,          cudaFuncAttributeMaxDynamicSharedMemorySize, smG66);
    cudaFuncSetAttribute((const void*)update_kernel<65, false>, cudaFuncAttributeMaxDynamicSharedMemorySize, smU65);
    cudaFuncSetAttribute((const void*)update_kernel<66, true>,  cudaFuncAttributeMaxDynamicSharedMemorySize, smU66);
    cudaFuncSetAttribute((const void*)hmma_gemm,                cudaFuncAttributeMaxDynamicSharedMemorySize, smHM);

    cudaMemsetAsync(ph,  0, (size_t)NN * 64 * 64 * sizeof(float));
    cudaMemsetAsync(pgo, 0, (size_t)NN * 64 * sizeof(float));
    cudaMemsetAsync(pc1, 0, (size_t)NN * LD * sizeof(float));
    cudaMemsetAsync(p1h, 0, (size_t)NN * LD * sizeof(__nv_bfloat16));
    cudaMemsetAsync(p1l, 0, (size_t)NN * LD * sizeof(__nv_bfloat16));

    build_support_kernel<<<NN, 256>>>(emb, pM);
    gemmA2<<<dim3(8, 8), 256>>>(pM, pM + (size_t)NN * NN);
    convert_M<<<2 * NN * NN / 256, 256>>>(pM, pMh, pMl);

    dim3 gg(33, 8);
    for (int t = 0; t < TT; t++) {
        inject_enc<<<64, 1024>>>(x, t, pc1, p1h, p1l, pc2, p2h, p2l);
        hmma_gemm<<<gg, 512, smHM>>>(pMh, pMl, p1h, p1l, pc1, pY1, pY2);
        gate_kernel<65><<<NN, 256, smG65>>>(pc1, pY1, pY2, egW, egb, ph, pr, pc2, p2h, p2l);
        hmma_gemm<<<gg, 512, smHM>>>(pMh, pMl, p2h, p2l, pc2, pY1, pY2);
        int Cn = (t == TT - 1) ? 66 : 65;
        int offn = (t == TT - 1) ? 2 : 1;
        update_kernel<65, false><<<NN, 256, smU65>>>(pc2, pY1, pY2, euW, eub, pr, ph,
                                                     pc1, p1h, p1l, Cn, offn,
                                                     nullptr, nullptr, nullptr, nullptr, 0);
    }
    for (int t = 0; t < TT; t++) {
        inject_dec<<<64, 1024>>>(ycov, t, pgo, pc1, p1h, p1l, pc2, p2h, p2l);
        hmma_gemm<<<gg, 512, smHM>>>(pMh, pMl, p1h, p1l, pc1, pY1, pY2);
        gate_kernel<66><<<NN, 256, smG66>>>(pc1, pY1, pY2, dgW, dgb, ph, pr, pc2, p2h, p2l);
        hmma_gemm<<<gg, 512, smHM>>>(pMh, pMl, p2h, p2l, pc2, pY1, pY2);
        update_kernel<66, true><<<NN, 256, smU66>>>(pc2, pY1, pY2, duW, dub, pr, ph,
                                                    pc1, p1h, p1l, 66, 2,
                                                    pW, pb, pgo, out, t);
    }
}

// round 9
// speedup vs baseline: 1.0640x; 1.0640x over previous
#include <cuda_runtime.h>
#include <cuda_bf16.h>
#include <math.h>
#include <stdint.h>

#define NN 1024
#define TT 12
#define LD 4352   // padded cols; GEMM covers 33*128 = 4224

// ---------------- scratch ----------------
__device__ float g_M [2 * NN * NN];             // [A ; A2] fp32
__device__ __nv_bfloat16 g_Mh[2 * NN * NN];     // bf16 hi of [A ; 2*A2]
__device__ __nv_bfloat16 g_Ml[2 * NN * NN];     // bf16 lo
__device__ float g_cat1[NN * LD];
__device__ float g_cat2[NN * LD];
__device__ __nv_bfloat16 g_c1h[NN * LD];
__device__ __nv_bfloat16 g_c1l[NN * LD];
__device__ __nv_bfloat16 g_c2h[NN * LD];
__device__ __nv_bfloat16 g_c2l[NN * LD];
__device__ float g_Y1  [NN * LD];
__device__ float g_Y2  [NN * LD];
__device__ float g_h [NN * 64 * 64];
__device__ float g_r [NN * 64 * 64];
__device__ float g_go[NN * 64];

// ---------------- helpers ----------------
__device__ __forceinline__ uint32_t smem_u32(const void* p) {
    uint32_t a;
    asm("{ .reg .u64 t; cvta.to.shared.u64 t, %1; cvt.u32.u64 %0, t; }" : "=r"(a) : "l"(p));
    return a;
}
__device__ __forceinline__ void cpa16(uint32_t dst, const void* src) {
    asm volatile("cp.async.cg.shared.global [%0], [%1], 16;" :: "r"(dst), "l"(src));
}
__device__ __forceinline__ void ldsm4(uint32_t* r, uint32_t a) {
    asm volatile("ldmatrix.sync.aligned.m8n8.x4.shared.b16 {%0,%1,%2,%3}, [%4];"
        : "=r"(r[0]), "=r"(r[1]), "=r"(r[2]), "=r"(r[3]) : "r"(a));
}
__device__ __forceinline__ void ldsm4t(uint32_t* r, uint32_t a) {
    asm volatile("ldmatrix.sync.aligned.m8n8.x4.trans.shared.b16 {%0,%1,%2,%3}, [%4];"
        : "=r"(r[0]), "=r"(r[1]), "=r"(r[2]), "=r"(r[3]) : "r"(a));
}
__device__ __forceinline__ void mma_bf16(float* d, const uint32_t* a, uint32_t b0, uint32_t b1) {
    asm volatile("mma.sync.aligned.m16n8k16.row.col.f32.bf16.bf16.f32 "
        "{%0,%1,%2,%3},{%4,%5,%6,%7},{%8,%9},{%0,%1,%2,%3};"
        : "+f"(d[0]), "+f"(d[1]), "+f"(d[2]), "+f"(d[3])
        : "r"(a[0]), "r"(a[1]), "r"(a[2]), "r"(a[3]), "r"(b0), "r"(b1));
}
__device__ __forceinline__ void bsplit(float v, __nv_bfloat16& h16, __nv_bfloat16& l16) {
    h16 = __float2bfloat16(v);
    l16 = __float2bfloat16(v - __bfloat162float(h16));
}
__device__ __forceinline__ uint32_t swA(uint32_t off) { return off ^ ((off >> 3) & 0x70); }
__device__ __forceinline__ uint32_t swB(uint32_t off) { return off ^ (((off >> 8) & 7) << 4); }

// ---------------- support: A = softmax(relu(E E^T), rows) ----------------
__global__ void build_support_kernel(const float* __restrict__ emb, float* __restrict__ A) {
    __shared__ float se[NN * 8];
    __shared__ float row[NN];
    __shared__ float wred[8];
    __shared__ float red;
    int n = blockIdx.x, tid = threadIdx.x;
    for (int i = tid; i < NN * 8; i += 256) se[i] = emb[i];
    __syncthreads();
    float e[8];
    #pragma unroll
    for (int j = 0; j < 8; j++) e[j] = se[n * 8 + j];
    float mx = 0.f;
    for (int m = tid; m < NN; m += 256) {
        const float* em = &se[m * 8];
        float s = 0.f;
        #pragma unroll
        for (int j = 0; j < 8; j++) s += e[j] * em[j];
        s = fmaxf(s, 0.f);
        row[m] = s;
        mx = fmaxf(mx, s);
    }
    #pragma unroll
    for (int o = 16; o; o >>= 1) mx = fmaxf(mx, __shfl_xor_sync(0xffffffffu, mx, o));
    if ((tid & 31) == 0) wred[tid >> 5] = mx;
    __syncthreads();
    if (tid == 0) { float v = wred[0]; for (int w = 1; w < 8; w++) v = fmaxf(v, wred[w]); red = v; }
    __syncthreads();
    float bmax = red, sum = 0.f;
    for (int m = tid; m < NN; m += 256) { float v = expf(row[m] - bmax); row[m] = v; sum += v; }
    #pragma unroll
    for (int o = 16; o; o >>= 1) sum += __shfl_xor_sync(0xffffffffu, sum, o);
    if ((tid & 31) == 0) wred[tid >> 5] = sum;
    __syncthreads();
    if (tid == 0) { float v = 0.f; for (int w = 0; w < 8; w++) v += wred[w]; red = v; }
    __syncthreads();
    float inv = 1.f / red;
    for (int m = tid; m < NN; m += 256) A[n * NN + m] = row[m] * inv;
}

// ---------------- A2 = A @ A ----------------
__global__ void __launch_bounds__(256, 2) gemmA2(const float* __restrict__ A, float* __restrict__ A2) {
    __shared__ __align__(16) float As[2][8][132];
    __shared__ __align__(16) float Bs[2][8][128];
    int tid = threadIdx.x;
    int row0 = blockIdx.y * 128, col0 = blockIdx.x * 128;
    int arow = tid >> 1, acol4 = (tid & 1) << 2;
    int brow = tid >> 5, bcol4 = (tid & 31) << 2;
    int tx = tid & 15, ty = tid >> 4;
    const float* Ap = A + (size_t)(row0 + arow) * NN + acol4;
    const float* Xp = A + (size_t)brow * NN + col0 + bcol4;
    float acc[8][8];
    #pragma unroll
    for (int i = 0; i < 8; i++)
        #pragma unroll
        for (int j = 0; j < 8; j++) acc[i][j] = 0.f;
    float4 av = *(const float4*)Ap;
    float4 bv = *(const float4*)Xp;
    int buf = 0;
    As[0][acol4 + 0][arow] = av.x; As[0][acol4 + 1][arow] = av.y;
    As[0][acol4 + 2][arow] = av.z; As[0][acol4 + 3][arow] = av.w;
    *(float4*)&Bs[0][brow][bcol4] = bv;
    __syncthreads();
    for (int kt = 1; kt < 128; kt++) {
        av = *(const float4*)(Ap + kt * 8);
        bv = *(const float4*)(Xp + (size_t)(kt * 8) * NN);
        #pragma unroll
        for (int kk = 0; kk < 8; kk++) {
            float4 a0 = *(const float4*)&As[buf][kk][ty * 4];
            float4 a1 = *(const float4*)&As[buf][kk][64 + ty * 4];
            float4 b0 = *(const float4*)&Bs[buf][kk][tx * 4];
            float4 b1 = *(const float4*)&Bs[buf][kk][64 + tx * 4];
            float a[8] = {a0.x,a0.y,a0.z,a0.w,a1.x,a1.y,a1.z,a1.w};
            float b[8] = {b0.x,b0.y,b0.z,b0.w,b1.x,b1.y,b1.z,b1.w};
            #pragma unroll
            for (int i = 0; i < 8; i++)
                #pragma unroll
                for (int j = 0; j < 8; j++) acc[i][j] = fmaf(a[i], b[j], acc[i][j]);
        }
        buf ^= 1;
        As[buf][acol4 + 0][arow] = av.x; As[buf][acol4 + 1][arow] = av.y;
        As[buf][acol4 + 2][arow] = av.z; As[buf][acol4 + 3][arow] = av.w;
        *(float4*)&Bs[buf][brow][bcol4] = bv;
        __syncthreads();
    }
    #pragma unroll
    for (int kk = 0; kk < 8; kk++) {
        float4 a0 = *(const float4*)&As[buf][kk][ty * 4];
        float4 a1 = *(const float4*)&As[buf][kk][64 + ty * 4];
        float4 b0 = *(const float4*)&Bs[buf][kk][tx * 4];
        float4 b1 = *(const float4*)&Bs[buf][kk][64 + tx * 4];
        float a[8] = {a0.x,a0.y,a0.z,a0.w,a1.x,a1.y,a1.z,a1.w};
        float b[8] = {b0.x,b0.y,b0.z,b0.w,b1.x,b1.y,b1.z,b1.w};
        #pragma unroll
        for (int i = 0; i < 8; i++)
            #pragma unroll
            for (int j = 0; j < 8; j++) acc[i][j] = fmaf(a[i], b[j], acc[i][j]);
    }
    #pragma unroll
    for (int i = 0; i < 8; i++) {
        int grow = row0 + ((i < 4) ? (ty * 4 + i) : (64 + ty * 4 + i - 4));
        float* yp = A2 + (size_t)grow * NN;
        *(float4*)(yp + col0 + tx * 4)       = make_float4(acc[i][0], acc[i][1], acc[i][2], acc[i][3]);
        *(float4*)(yp + col0 + 64 + tx * 4)  = make_float4(acc[i][4], acc[i][5], acc[i][6], acc[i][7]);
    }
}

// ---------------- M -> bf16 hi/lo (fold 2x into bottom half) ----------------
__global__ void convert_M(const float* __restrict__ M,
                          __nv_bfloat16* __restrict__ Mh, __nv_bfloat16* __restrict__ Ml) {
    int i = blockIdx.x * 256 + threadIdx.x;
    float v = M[i];
    if (i >= NN * NN) v *= 2.f;
    __nv_bfloat16 h, l;
    bsplit(v, h, l);
    Mh[i] = h;
    Ml[i] = l;
}

// ---------------- HMMA split-bf16 diffusion GEMM (round-4 exact) ----------------
// KC=64, 2-stage cp.async double buffer.
// stage layout (64KB): Ah 16K | Al 16K | Bh 16K | Bl 16K
// grid (33, 16): col0 = bx*128, row0 = by*128 over [A ; 2*A2]
#define KC 64
#define STG 65536
__global__ void __launch_bounds__(256, 1) hmma_gemm(
    const __nv_bfloat16* __restrict__ Mh, const __nv_bfloat16* __restrict__ Ml,
    const __nv_bfloat16* __restrict__ Xh, const __nv_bfloat16* __restrict__ Xl,
    const float* __restrict__ Xf, float* __restrict__ Y1, float* __restrict__ Y2)
{
    extern __shared__ __align__(1024) char smem[];
    uint32_t sb = smem_u32(smem);
    int tid = threadIdx.x;
    int lane = tid & 31, wid = tid >> 5;
    int wm = wid >> 1, wn = wid & 1;
    int row0 = blockIdx.y * 128;
    int col0 = blockIdx.x * 128;

    float acc[2][8][4];
    #pragma unroll
    for (int mt = 0; mt < 2; mt++)
        #pragma unroll
        for (int nt = 0; nt < 8; nt++)
            #pragma unroll
            for (int j = 0; j < 4; j++) acc[mt][nt][j] = 0.f;

    auto load_stage = [&](int it) {
        uint32_t base = sb + (it & 1) * STG;
        int k0 = it * KC;
        #pragma unroll
        for (int i = tid; i < 1024; i += 256) {
            int r = i >> 3, c = i & 7;
            uint32_t sw = swA((uint32_t)(r * 128 + c * 16));
            size_t g = (size_t)(row0 + r) * NN + k0 + c * 8;
            cpa16(base + sw, Mh + g);
            cpa16(base + 16384 + sw, Ml + g);
        }
        #pragma unroll
        for (int i = tid; i < 1024; i += 256) {
            int k = i >> 4, c = i & 15;
            uint32_t sw = swB((uint32_t)(k * 256 + c * 16));
            size_t g = (size_t)(k0 + k) * LD + col0 + c * 8;
            cpa16(base + 32768 + sw, Xh + g);
            cpa16(base + 49152 + sw, Xl + g);
        }
        asm volatile("cp.async.commit_group;" ::: "memory");
    };

    load_stage(0);
    load_stage(1);

    int a_r = wm * 32 + (lane & 15);
    int a_ch = (lane >> 4);
    int b_k = (lane & 7) + ((lane >> 3) & 1) * 8;
    int b_n8 = ((lane >> 4) & 1) * 8;

    #pragma unroll 1
    for (int it = 0; it < 16; it++) {
        int buf = it & 1;
        if (it < 15) asm volatile("cp.async.wait_group 1;" ::: "memory");
        else         asm volatile("cp.async.wait_group 0;" ::: "memory");
        __syncthreads();
        uint32_t base = sb + buf * STG;
        #pragma unroll
        for (int kk = 0; kk < 4; kk++) {
            uint32_t aH[2][4], aL[2][4];
            #pragma unroll
            for (int mt = 0; mt < 2; mt++) {
                uint32_t off = swA((uint32_t)((a_r + mt * 16) * 128 + (kk * 2 + a_ch) * 16));
                ldsm4(aH[mt], base + off);
                ldsm4(aL[mt], base + 16384 + off);
            }
            uint32_t bH[4][4], bL[4][4];
            #pragma unroll
            for (int p = 0; p < 4; p++) {
                int nb = wn * 64 + p * 16 + b_n8;
                uint32_t off = swB((uint32_t)((kk * 16 + b_k) * 256 + nb * 2));
                ldsm4t(bH[p], base + 32768 + off);
                ldsm4t(bL[p], base + 49152 + off);
            }
            #pragma unroll
            for (int mt = 0; mt < 2; mt++) {
                #pragma unroll
                for (int p = 0; p < 4; p++) {
                    mma_bf16(acc[mt][2 * p],     aH[mt], bH[p][0], bH[p][1]);
                    mma_bf16(acc[mt][2 * p],     aH[mt], bL[p][0], bL[p][1]);
                    mma_bf16(acc[mt][2 * p],     aL[mt], bH[p][0], bH[p][1]);
                    mma_bf16(acc[mt][2 * p + 1], aH[mt], bH[p][2], bH[p][3]);
                    mma_bf16(acc[mt][2 * p + 1], aH[mt], bL[p][2], bL[p][3]);
                    mma_bf16(acc[mt][2 * p + 1], aL[mt], bH[p][2], bH[p][3]);
                }
            }
        }
        __syncthreads();
        if (it + 2 < 16) load_stage(it + 2);
    }

    // epilogue
    int r_lo = lane >> 2;
    int c_lo = (lane & 3) * 2;
    if (row0 < 1024) {
        #pragma unroll
        for (int mt = 0; mt < 2; mt++) {
            int r = row0 + wm * 32 + mt * 16 + r_lo;
            #pragma unroll
            for (int nt = 0; nt < 8; nt++) {
                int c = col0 + wn * 64 + nt * 8 + c_lo;
                *(float2*)(Y1 + (size_t)r * LD + c)       = make_float2(acc[mt][nt][0], acc[mt][nt][1]);
                *(float2*)(Y1 + (size_t)(r + 8) * LD + c) = make_float2(acc[mt][nt][2], acc[mt][nt][3]);
            }
        }
    } else {
        #pragma unroll
        for (int mt = 0; mt < 2; mt++) {
            int r = row0 - 1024 + wm * 32 + mt * 16 + r_lo;
            #pragma unroll
            for (int nt = 0; nt < 8; nt++) {
                int c = col0 + wn * 64 + nt * 8 + c_lo;
                float2 x0 = *(const float2*)(Xf + (size_t)r * LD + c);
                float2 x1 = *(const float2*)(Xf + (size_t)(r + 8) * LD + c);
                *(float2*)(Y2 + (size_t)r * LD + c)       = make_float2(acc[mt][nt][0] - x0.x, acc[mt][nt][1] - x0.y);
                *(float2*)(Y2 + (size_t)(r + 8) * LD + c) = make_float2(acc[mt][nt][2] - x1.x, acc[mt][nt][3] - x1.y);
            }
        }
    }
}

// ---------------- fused gate ----------------
template <int C>
__global__ void __launch_bounds__(256) gate_kernel(
    const float* __restrict__ F0, const float* __restrict__ F1, const float* __restrict__ F2,
    const float* __restrict__ W, const float* __restrict__ bias,
    const float* __restrict__ h, float* __restrict__ rbuf,
    float* __restrict__ cat2, __nv_bfloat16* __restrict__ c2h, __nv_bfloat16* __restrict__ c2l)
{
    constexpr int K3  = 3 * C;
    constexpr int LDF = ((K3 + 3) / 4) * 4;
    extern __shared__ float sm[];
    float* feats = sm;
    float* Ws    = sm + 64 * LDF;
    float* bs    = Ws + K3 * 128;
    int nblk = blockIdx.x, tid = threadIdx.x;
    size_t base = (size_t)nblk * LD;
    for (int idx = tid; idx < 64 * C; idx += 256) {
        int r = idx / C, c = idx - r * C;
        float* fd = &feats[r * LDF + c];
        fd[0]     = F0[base + idx];
        fd[C]     = F1[base + idx];
        fd[2 * C] = F2[base + idx];
    }
    for (int idx = tid; idx < K3 * 128; idx += 256) Ws[idx] = W[idx];
    if (tid < 128) bs[tid] = bias[tid];
    __syncthreads();

    int ft = tid & 15, rt = tid >> 4;
    int f0 = ft * 4, r0 = rt * 4;
    float acc[4][8];
    #pragma unroll
    for (int i = 0; i < 4; i++)
        #pragma unroll
        for (int j = 0; j < 4; j++) { acc[i][j] = bs[f0 + j]; acc[i][j + 4] = bs[64 + f0 + j]; }
    int k = 0;
    for (; k + 4 <= K3; k += 4) {
        float4 a4[4];
        #pragma unroll
        for (int i = 0; i < 4; i++) a4[i] = *(const float4*)&feats[(r0 + i) * LDF + k];
        #pragma unroll
        for (int kk = 0; kk < 4; kk++) {
            float4 wz = *(const float4*)&Ws[(k + kk) * 128 + f0];
            float4 wr = *(const float4*)&Ws[(k + kk) * 128 + 64 + f0];
            float wv[8] = {wz.x,wz.y,wz.z,wz.w,wr.x,wr.y,wr.z,wr.w};
            #pragma unroll
            for (int i = 0; i < 4; i++) {
                float ai = ((const float*)&a4[i])[kk];
                #pragma unroll
                for (int j = 0; j < 8; j++) acc[i][j] = fmaf(ai, wv[j], acc[i][j]);
            }
        }
    }
    for (; k < K3; k++) {
        #pragma unroll
        for (int i = 0; i < 4; i++) {
            float ai = feats[(r0 + i) * LDF + k];
            #pragma unroll
            for (int j = 0; j < 4; j++) {
                acc[i][j]     = fmaf(ai, Ws[k * 128 + f0 + j], acc[i][j]);
                acc[i][j + 4] = fmaf(ai, Ws[k * 128 + 64 + f0 + j], acc[i][j + 4]);
            }
        }
    }
    #pragma unroll
    for (int i = 0; i < 4; i++) {
        int b = r0 + i;
        int grow = nblk * 64 + b;
        #pragma unroll
        for (int j = 0; j < 4; j++) {
            int f = f0 + j;
            float z = 1.f / (1.f + expf(-acc[i][j]));
            float v = z * h[grow * 64 + f];
            size_t pos = base + b * C + (C - 64) + f;
            cat2[pos] = v;
            __nv_bfloat16 hh, ll;
            bsplit(v, hh, ll);
            c2h[pos] = hh;
            c2l[pos] = ll;
            float rr = 1.f / (1.f + expf(-acc[i][j + 4]));
            rbuf[grow * 64 + f] = rr;
        }
    }
}

// ---------------- fused update ----------------
template <int C>
__global__ void __launch_bounds__(256) update_kernel(
    const float* __restrict__ F0, const float* __restrict__ F1, const float* __restrict__ F2,
    const float* __restrict__ W, const float* __restrict__ bias,
    const float* __restrict__ rbuf, float* __restrict__ h)
{
    constexpr int K3  = 3 * C;
    constexpr int LDF = ((K3 + 3) / 4) * 4;
    extern __shared__ float sm[];
    float* feats = sm;
    float* Ws    = sm + 64 * LDF;
    float* bs    = Ws + K3 * 64;
    int nblk = blockIdx.x, tid = threadIdx.x;
    size_t base = (size_t)nblk * LD;
    for (int idx = tid; idx < 64 * C; idx += 256) {
        int r = idx / C, c = idx - r * C;
        float* fd = &feats[r * LDF + c];
        fd[0]     = F0[base + idx];
        fd[C]     = F1[base + idx];
        fd[2 * C] = F2[base + idx];
    }
    for (int idx = tid; idx < K3 * 64; idx += 256) Ws[idx] = W[idx];
    if (tid < 64) bs[tid] = bias[tid];
    __syncthreads();

    int ft = tid & 15, rt = tid >> 4;
    int f0 = ft * 4, r0 = rt * 4;
    float acc[4][4];
    #pragma unroll
    for (int i = 0; i < 4; i++)
        #pragma unroll
        for (int j = 0; j < 4; j++) acc[i][j] = bs[f0 + j];
    int k = 0;
    for (; k + 4 <= K3; k += 4) {
        float4 a4[4];
        #pragma unroll
        for (int i = 0; i < 4; i++) a4[i] = *(const float4*)&feats[(r0 + i) * LDF + k];
        #pragma unroll
        for (int kk = 0; kk < 4; kk++) {
            float4 w4 = *(const float4*)&Ws[(k + kk) * 64 + f0];
            float wj[4] = {w4.x, w4.y, w4.z, w4.w};
            #pragma unroll
            for (int i = 0; i < 4; i++) {
                float ai = ((const float*)&a4[i])[kk];
                #pragma unroll
                for (int j = 0; j < 4; j++) acc[i][j] = fmaf(ai, wj[j], acc[i][j]);
            }
        }
    }
    for (; k < K3; k++) {
        #pragma unroll
        for (int i = 0; i < 4; i++) {
            float ai = feats[(r0 + i) * LDF + k];
            #pragma unroll
            for (int j = 0; j < 4; j++) acc[i][j] = fmaf(ai, Ws[k * 64 + f0 + j], acc[i][j]);
        }
    }
    #pragma unroll
    for (int i = 0; i < 4; i++) {
        int grow = nblk * 64 + r0 + i;
        #pragma unroll
        for (int j = 0; j < 4; j++) {
            int f = f0 + j;
            float hc = tanhf(acc[i][j]);
            float rr = rbuf[grow * 64 + f];
            float ho = h[grow * 64 + f];
            h[grow * 64 + f] = rr * ho + (1.f - rr) * hc;
        }
    }
}

// ---------------- concat builders (fp32 + bf16 hi/lo) ----------------
__global__ void build_cat_enc(const float* __restrict__ x, int t,
                              const float* __restrict__ h,
                              float* __restrict__ cat1,
                              __nv_bfloat16* __restrict__ c1h, __nv_bfloat16* __restrict__ c1l,
                              float* __restrict__ cat2,
                              __nv_bfloat16* __restrict__ c2h, __nv_bfloat16* __restrict__ c2l) {
    const int C = 65;
    int n = blockIdx.x;
    size_t base = (size_t)n * LD;
    for (int idx = threadIdx.x; idx < 64 * C; idx += 256) {
        int b = idx / C, c = idx - b * C;
        float v;
        __nv_bfloat16 hh, ll;
        if (c == 0) {
            v = x[(size_t)(b * TT + t) * NN + n];
            bsplit(v, hh, ll);
            cat2[base + idx] = v;
            c2h[base + idx] = hh;
            c2l[base + idx] = ll;
        } else {
            v = h[(n * 64 + b) * 64 + (c - 1)];
            bsplit(v, hh, ll);
        }
        cat1[base + idx] = v;
        c1h[base + idx] = hh;
        c1l[base + idx] = ll;
    }
}
__global__ void build_cat_dec(const float* __restrict__ yc, int t,
                              const float* __restrict__ go,
                              const float* __restrict__ h,
                              float* __restrict__ cat1,
                              __nv_bfloat16* __restrict__ c1h, __nv_bfloat16* __restrict__ c1l,
                              float* __restrict__ cat2,
                              __nv_bfloat16* __restrict__ c2h, __nv_bfloat16* __restrict__ c2l) {
    const int C = 66;
    int n = blockIdx.x;
    size_t base = (size_t)n * LD;
    for (int idx = threadIdx.x; idx < 64 * C; idx += 256) {
        int b = idx / C, c = idx - b * C;
        float v;
        if (c == 0)      v = go[n * 64 + b];
        else if (c == 1) v = yc[(size_t)(b * TT + t) * NN + n];
        else             v = h[(n * 64 + b) * 64 + (c - 2)];
        __nv_bfloat16 hh, ll;
        bsplit(v, hh, ll);
        if (c < 2) {
            cat2[base + idx] = v;
            c2h[base + idx] = hh;
            c2l[base + idx] = ll;
        }
        cat1[base + idx] = v;
        c1h[base + idx] = hh;
        c1l[base + idx] = ll;
    }
}

// ---------------- projection ----------------
__global__ void proj_kernel(const float* __restrict__ h, const float* __restrict__ pW,
                            const float* __restrict__ pb, float* __restrict__ go,
                            float* __restrict__ out, int t) {
    int row  = blockIdx.x * 8 + (threadIdx.x >> 5);
    int lane = threadIdx.x & 31;
    float s = h[row * 64 + lane] * pW[lane] + h[row * 64 + 32 + lane] * pW[32 + lane];
    #pragma unroll
    for (int o = 16; o; o >>= 1) s += __shfl_xor_sync(0xffffffffu, s, o);
    if (lane == 0) {
        float v = s + pb[0];
        go[row] = v;
        int n = row >> 6, b = row & 63;
        out[(size_t)(b * TT + t) * NN + n] = v;
    }
}

// ---------------- orchestration ----------------
extern "C" void kernel_launch(void* const* d_in, const int* in_sizes, int n_in,
                              void* d_out, int out_size) {
    const float* x    = (const float*)d_in[0];
    const float* ycov = (const float*)d_in[1];
    const float* emb  = (const float*)d_in[2];
    const float* egW  = (const float*)d_in[3];
    const float* egb  = (const float*)d_in[4];
    const float* euW  = (const float*)d_in[5];
    const float* eub  = (const float*)d_in[6];
    const float* dgW  = (const float*)d_in[7];
    const float* dgb  = (const float*)d_in[8];
    const float* duW  = (const float*)d_in[9];
    const float* dub  = (const float*)d_in[10];
    const float* pW   = (const float*)d_in[11];
    const float* pb   = (const float*)d_in[12];
    float* out = (float*)d_out;

    float *pM, *pc1, *pc2, *pY1, *pY2, *ph, *pr, *pgo;
    __nv_bfloat16 *pMh, *pMl, *p1h, *p1l, *p2h, *p2l;
    cudaGetSymbolAddress((void**)&pM,  g_M);
    cudaGetSymbolAddress((void**)&pMh, g_Mh);
    cudaGetSymbolAddress((void**)&pMl, g_Ml);
    cudaGetSymbolAddress((void**)&pc1, g_cat1);
    cudaGetSymbolAddress((void**)&pc2, g_cat2);
    cudaGetSymbolAddress((void**)&p1h, g_c1h);
    cudaGetSymbolAddress((void**)&p1l, g_c1l);
    cudaGetSymbolAddress((void**)&p2h, g_c2h);
    cudaGetSymbolAddress((void**)&p2l, g_c2l);
    cudaGetSymbolAddress((void**)&pY1, g_Y1);
    cudaGetSymbolAddress((void**)&pY2, g_Y2);
    cudaGetSymbolAddress((void**)&ph,  g_h);
    cudaGetSymbolAddress((void**)&pr,  g_r);
    cudaGetSymbolAddress((void**)&pgo, g_go);

    const int smG65 = (64 * 196 + 195 * 128 + 128) * 4;
    const int smG66 = (64 * 200 + 198 * 128 + 128) * 4;
    const int smU65 = (64 * 196 + 195 * 64 + 64) * 4;
    const int smU66 = (64 * 200 + 198 * 64 + 64) * 4;
    const int smHM  = 2 * STG;   // 131072
    cudaFuncSetAttribute((const void*)gate_kernel<65>,   cudaFuncAttributeMaxDynamicSharedMemorySize, smG65);
    cudaFuncSetAttribute((const void*)gate_kernel<66>,   cudaFuncAttributeMaxDynamicSharedMemorySize, smG66);
    cudaFuncSetAttribute((const void*)update_kernel<65>, cudaFuncAttributeMaxDynamicSharedMemorySize, smU65);
    cudaFuncSetAttribute((const void*)update_kernel<66>, cudaFuncAttributeMaxDynamicSharedMemorySize, smU66);
    cudaFuncSetAttribute((const void*)hmma_gemm,         cudaFuncAttributeMaxDynamicSharedMemorySize, smHM);

    cudaMemsetAsync(ph,  0, (size_t)NN * 64 * 64 * sizeof(float));
    cudaMemsetAsync(pgo, 0, (size_t)NN * 64 * sizeof(float));
    cudaMemsetAsync(pc1, 0, (size_t)NN * LD * sizeof(float));
    cudaMemsetAsync(pc2, 0, (size_t)NN * LD * sizeof(float));
    cudaMemsetAsync(p1h, 0, (size_t)NN * LD * sizeof(__nv_bfloat16));
    cudaMemsetAsync(p1l, 0, (size_t)NN * LD * sizeof(__nv_bfloat16));
    cudaMemsetAsync(p2h, 0, (size_t)NN * LD * sizeof(__nv_bfloat16));
    cudaMemsetAsync(p2l, 0, (size_t)NN * LD * sizeof(__nv_bfloat16));

    build_support_kernel<<<NN, 256>>>(emb, pM);
    gemmA2<<<dim3(8, 8), 256>>>(pM, pM + (size_t)NN * NN);
    convert_M<<<2 * NN * NN / 256, 256>>>(pM, pMh, pMl);

    dim3 gg(33, 16);
    for (int t = 0; t < TT; t++) {
        build_cat_enc<<<NN, 256>>>(x, t, ph, pc1, p1h, p1l, pc2, p2h, p2l);
        hmma_gemm<<<gg, 256, smHM>>>(pMh, pMl, p1h, p1l, pc1, pY1, pY2);
        gate_kernel<65><<<NN, 256, smG65>>>(pc1, pY1, pY2, egW, egb, ph, pr, pc2, p2h, p2l);
        hmma_gemm<<<gg, 256, smHM>>>(pMh, pMl, p2h, p2l, pc2, pY1, pY2);
        update_kernel<65><<<NN, 256, smU65>>>(pc2, pY1, pY2, euW, eub, pr, ph);
    }
    for (int t = 0; t < TT; t++) {
        build_cat_dec<<<NN, 256>>>(ycov, t, pgo, ph, pc1, p1h, p1l, pc2, p2h, p2l);
        hmma_gemm<<<gg, 256, smHM>>>(pMh, pMl, p1h, p1l, pc1, pY1, pY2);
        gate_kernel<66><<<NN, 256, smG66>>>(pc1, pY1, pY2, dgW, dgb, ph, pr, pc2, p2h, p2l);
        hmma_gemm<<<gg, 256, smHM>>>(pMh, pMl, p2h, p2l, pc2, pY1, pY2);
        update_kernel<66><<<NN, 256, smU66>>>(pc2, pY1, pY2, duW, dub, pr, ph);
        proj_kernel<<<8192, 256>>>(ph, pW, pb, pgo, out, t);
    }
}

// round 10
// speedup vs baseline: 1.5216x; 1.4301x over previous
#include <cuda_runtime.h>
#include <cuda_bf16.h>
#include <math.h>
#include <stdint.h>

#define NN 1024
#define TT 12
#define LD 4352   // padded cols; GEMM covers 33*128 = 4224

// ---------------- scratch ----------------
__device__ float g_M [2 * NN * NN];
__device__ __align__(256) __nv_bfloat16 g_Mh[2 * NN * NN];
__device__ __align__(256) __nv_bfloat16 g_Ml[2 * NN * NN];
__device__ float g_cat1[NN * LD];                 // fp32, c-major: [n][c*64+b]
__device__ float g_cat2[NN * LD];
__device__ __align__(256) __nv_bfloat16 g_c1h[NN * LD];
__device__ __align__(256) __nv_bfloat16 g_c1l[NN * LD];
__device__ __align__(256) __nv_bfloat16 g_c2h[NN * LD];
__device__ __align__(256) __nv_bfloat16 g_c2l[NN * LD];
__device__ __align__(256) float g_Y1[NN * LD];    // aliased: bf16 Y1h | Y1l
__device__ __align__(256) float g_Y2[NN * LD];    // aliased: bf16 Y2h | Y2l
__device__ float g_h [NN * 64 * 64];              // [n][f*64+b]
__device__ float g_r [NN * 64 * 64];              // [n][f*64+b]
__device__ float g_go[NN * 64];                   // [n*64+b]
// W images: [h|l], each [Fall][216] bf16 (k padded to 216, zero beyond K3)
__device__ __align__(256) __nv_bfloat16 g_WgE[2 * 128 * 216];
__device__ __align__(256) __nv_bfloat16 g_WgD[2 * 128 * 216];
__device__ __align__(256) __nv_bfloat16 g_WuE[2 * 64 * 216];
__device__ __align__(256) __nv_bfloat16 g_WuD[2 * 64 * 216];

// ---------------- helpers ----------------
__device__ __forceinline__ uint32_t smem_u32(const void* p) {
    uint32_t a;
    asm("{ .reg .u64 t; cvta.to.shared.u64 t, %1; cvt.u32.u64 %0, t; }" : "=r"(a) : "l"(p));
    return a;
}
__device__ __forceinline__ void cpa16(uint32_t dst, const void* src) {
    asm volatile("cp.async.cg.shared.global [%0], [%1], 16;" :: "r"(dst), "l"(src));
}
__device__ __forceinline__ void ldsm4(uint32_t* r, uint32_t a) {
    asm volatile("ldmatrix.sync.aligned.m8n8.x4.shared.b16 {%0,%1,%2,%3}, [%4];"
        : "=r"(r[0]), "=r"(r[1]), "=r"(r[2]), "=r"(r[3]) : "r"(a));
}
__device__ __forceinline__ void ldsm4t(uint32_t* r, uint32_t a) {
    asm volatile("ldmatrix.sync.aligned.m8n8.x4.trans.shared.b16 {%0,%1,%2,%3}, [%4];"
        : "=r"(r[0]), "=r"(r[1]), "=r"(r[2]), "=r"(r[3]) : "r"(a));
}
__device__ __forceinline__ void mma_bf16(float* d, const uint32_t* a, uint32_t b0, uint32_t b1) {
    asm volatile("mma.sync.aligned.m16n8k16.row.col.f32.bf16.bf16.f32 "
        "{%0,%1,%2,%3},{%4,%5,%6,%7},{%8,%9},{%0,%1,%2,%3};"
        : "+f"(d[0]), "+f"(d[1]), "+f"(d[2]), "+f"(d[3])
        : "r"(a[0]), "r"(a[1]), "r"(a[2]), "r"(a[3]), "r"(b0), "r"(b1));
}
__device__ __forceinline__ void bsplit(float v, __nv_bfloat16& h16, __nv_bfloat16& l16) {
    h16 = __float2bfloat16(v);
    l16 = __float2bfloat16(v - __bfloat162float(h16));
}
__device__ __forceinline__ void pack2(__nv_bfloat16* H, __nv_bfloat16* L, size_t idx,
                                      float v0, float v1) {
    __nv_bfloat16 h0, l0, h1, l1;
    bsplit(v0, h0, l0);
    bsplit(v1, h1, l1);
    __nv_bfloat162 hp; hp.x = h0; hp.y = h1;
    __nv_bfloat162 lp; lp.x = l0; lp.y = l1;
    *reinterpret_cast<__nv_bfloat162*>(H + idx) = hp;
    *reinterpret_cast<__nv_bfloat162*>(L + idx) = lp;
}
__device__ __forceinline__ uint32_t swA(uint32_t off) { return off ^ ((off >> 3) & 0x70); }
__device__ __forceinline__ uint32_t swB(uint32_t off) { return off ^ (((off >> 8) & 7) << 4); }

// ---------------- support: A = softmax(relu(E E^T), rows) ----------------
__global__ void build_support_kernel(const float* __restrict__ emb, float* __restrict__ A) {
    __shared__ float se[NN * 8];
    __shared__ float row[NN];
    __shared__ float wred[8];
    __shared__ float red;
    int n = blockIdx.x, tid = threadIdx.x;
    for (int i = tid; i < NN * 8; i += 256) se[i] = emb[i];
    __syncthreads();
    float e[8];
    #pragma unroll
    for (int j = 0; j < 8; j++) e[j] = se[n * 8 + j];
    float mx = 0.f;
    for (int m = tid; m < NN; m += 256) {
        const float* em = &se[m * 8];
        float s = 0.f;
        #pragma unroll
        for (int j = 0; j < 8; j++) s += e[j] * em[j];
        s = fmaxf(s, 0.f);
        row[m] = s;
        mx = fmaxf(mx, s);
    }
    #pragma unroll
    for (int o = 16; o; o >>= 1) mx = fmaxf(mx, __shfl_xor_sync(0xffffffffu, mx, o));
    if ((tid & 31) == 0) wred[tid >> 5] = mx;
    __syncthreads();
    if (tid == 0) { float v = wred[0]; for (int w = 1; w < 8; w++) v = fmaxf(v, wred[w]); red = v; }
    __syncthreads();
    float bmax = red, sum = 0.f;
    for (int m = tid; m < NN; m += 256) { float v = expf(row[m] - bmax); row[m] = v; sum += v; }
    #pragma unroll
    for (int o = 16; o; o >>= 1) sum += __shfl_xor_sync(0xffffffffu, sum, o);
    if ((tid & 31) == 0) wred[tid >> 5] = sum;
    __syncthreads();
    if (tid == 0) { float v = 0.f; for (int w = 0; w < 8; w++) v += wred[w]; red = v; }
    __syncthreads();
    float inv = 1.f / red;
    for (int m = tid; m < NN; m += 256) A[n * NN + m] = row[m] * inv;
}

// ---------------- A2 = A @ A ----------------
__global__ void __launch_bounds__(256, 2) gemmA2(const float* __restrict__ A, float* __restrict__ A2) {
    __shared__ __align__(16) float As[2][8][132];
    __shared__ __align__(16) float Bs[2][8][128];
    int tid = threadIdx.x;
    int row0 = blockIdx.y * 128, col0 = blockIdx.x * 128;
    int arow = tid >> 1, acol4 = (tid & 1) << 2;
    int brow = tid >> 5, bcol4 = (tid & 31) << 2;
    int tx = tid & 15, ty = tid >> 4;
    const float* Ap = A + (size_t)(row0 + arow) * NN + acol4;
    const float* Xp = A + (size_t)brow * NN + col0 + bcol4;
    float acc[8][8];
    #pragma unroll
    for (int i = 0; i < 8; i++)
        #pragma unroll
        for (int j = 0; j < 8; j++) acc[i][j] = 0.f;
    float4 av = *(const float4*)Ap;
    float4 bv = *(const float4*)Xp;
    int buf = 0;
    As[0][acol4 + 0][arow] = av.x; As[0][acol4 + 1][arow] = av.y;
    As[0][acol4 + 2][arow] = av.z; As[0][acol4 + 3][arow] = av.w;
    *(float4*)&Bs[0][brow][bcol4] = bv;
    __syncthreads();
    for (int kt = 1; kt < 128; kt++) {
        av = *(const float4*)(Ap + kt * 8);
        bv = *(const float4*)(Xp + (size_t)(kt * 8) * NN);
        #pragma unroll
        for (int kk = 0; kk < 8; kk++) {
            float4 a0 = *(const float4*)&As[buf][kk][ty * 4];
            float4 a1 = *(const float4*)&As[buf][kk][64 + ty * 4];
            float4 b0 = *(const float4*)&Bs[buf][kk][tx * 4];
            float4 b1 = *(const float4*)&Bs[buf][kk][64 + tx * 4];
            float a[8] = {a0.x,a0.y,a0.z,a0.w,a1.x,a1.y,a1.z,a1.w};
            float b[8] = {b0.x,b0.y,b0.z,b0.w,b1.x,b1.y,b1.z,b1.w};
            #pragma unroll
            for (int i = 0; i < 8; i++)
                #pragma unroll
                for (int j = 0; j < 8; j++) acc[i][j] = fmaf(a[i], b[j], acc[i][j]);
        }
        buf ^= 1;
        As[buf][acol4 + 0][arow] = av.x; As[buf][acol4 + 1][arow] = av.y;
        As[buf][acol4 + 2][arow] = av.z; As[buf][acol4 + 3][arow] = av.w;
        *(float4*)&Bs[buf][brow][bcol4] = bv;
        __syncthreads();
    }
    #pragma unroll
    for (int kk = 0; kk < 8; kk++) {
        float4 a0 = *(const float4*)&As[buf][kk][ty * 4];
        float4 a1 = *(const float4*)&As[buf][kk][64 + ty * 4];
        float4 b0 = *(const float4*)&Bs[buf][kk][tx * 4];
        float4 b1 = *(const float4*)&Bs[buf][kk][64 + tx * 4];
        float a[8] = {a0.x,a0.y,a0.z,a0.w,a1.x,a1.y,a1.z,a1.w};
        float b[8] = {b0.x,b0.y,b0.z,b0.w,b1.x,b1.y,b1.z,b1.w};
        #pragma unroll
        for (int i = 0; i < 8; i++)
            #pragma unroll
            for (int j = 0; j < 8; j++) acc[i][j] = fmaf(a[i], b[j], acc[i][j]);
    }
    #pragma unroll
    for (int i = 0; i < 8; i++) {
        int grow = row0 + ((i < 4) ? (ty * 4 + i) : (64 + ty * 4 + i - 4));
        float* yp = A2 + (size_t)grow * NN;
        *(float4*)(yp + col0 + tx * 4)       = make_float4(acc[i][0], acc[i][1], acc[i][2], acc[i][3]);
        *(float4*)(yp + col0 + 64 + tx * 4)  = make_float4(acc[i][4], acc[i][5], acc[i][6], acc[i][7]);
    }
}

// ---------------- M -> bf16 hi/lo (fold 2x into bottom half) ----------------
__global__ void convert_M(const float* __restrict__ M,
                          __nv_bfloat16* __restrict__ Mh, __nv_bfloat16* __restrict__ Ml) {
    int i = blockIdx.x * 256 + threadIdx.x;
    float v = M[i];
    if (i >= NN * NN) v *= 2.f;
    __nv_bfloat16 h, l;
    bsplit(v, h, l);
    Mh[i] = h;
    Ml[i] = l;
}

// ---------------- W^T image prep: img[h|l][f][216], zero-padded k>=K3 ----------------
__global__ void prep_W(const float* __restrict__ W, int K3, int Fall,
                       __nv_bfloat16* __restrict__ img) {
    int f = blockIdx.x;
    __nv_bfloat16* imgH = img;
    __nv_bfloat16* imgL = img + Fall * 216;
    for (int k = threadIdx.x; k < 216; k += 64) {
        float v = (k < K3) ? W[k * Fall + f] : 0.f;
        __nv_bfloat16 h, l;
        bsplit(v, h, l);
        imgH[f * 216 + k] = h;
        imgL[f * 216 + k] = l;
    }
}

// ---------------- HMMA split-bf16 diffusion GEMM (round-4 structure, bf16 epilogue) ----------------
#define KC 64
#define STG 65536
__global__ void __launch_bounds__(256, 1) hmma_gemm(
    const __nv_bfloat16* __restrict__ Mh, const __nv_bfloat16* __restrict__ Ml,
    const __nv_bfloat16* __restrict__ Xh, const __nv_bfloat16* __restrict__ Xl,
    const float* __restrict__ Xf,
    __nv_bfloat16* __restrict__ Y1h, __nv_bfloat16* __restrict__ Y1l,
    __nv_bfloat16* __restrict__ Y2h, __nv_bfloat16* __restrict__ Y2l)
{
    extern __shared__ __align__(1024) char smem[];
    uint32_t sb = smem_u32(smem);
    int tid = threadIdx.x;
    int lane = tid & 31, wid = tid >> 5;
    int wm = wid >> 1, wn = wid & 1;
    int row0 = blockIdx.y * 128;
    int col0 = blockIdx.x * 128;

    float acc[2][8][4];
    #pragma unroll
    for (int mt = 0; mt < 2; mt++)
        #pragma unroll
        for (int nt = 0; nt < 8; nt++)
            #pragma unroll
            for (int j = 0; j < 4; j++) acc[mt][nt][j] = 0.f;

    auto load_stage = [&](int it) {
        uint32_t base = sb + (it & 1) * STG;
        int k0 = it * KC;
        #pragma unroll
        for (int i = tid; i < 1024; i += 256) {
            int r = i >> 3, c = i & 7;
            uint32_t sw = swA((uint32_t)(r * 128 + c * 16));
            size_t g = (size_t)(row0 + r) * NN + k0 + c * 8;
            cpa16(base + sw, Mh + g);
            cpa16(base + 16384 + sw, Ml + g);
        }
        #pragma unroll
        for (int i = tid; i < 1024; i += 256) {
            int k = i >> 4, c = i & 15;
            uint32_t sw = swB((uint32_t)(k * 256 + c * 16));
            size_t g = (size_t)(k0 + k) * LD + col0 + c * 8;
            cpa16(base + 32768 + sw, Xh + g);
            cpa16(base + 49152 + sw, Xl + g);
        }
        asm volatile("cp.async.commit_group;" ::: "memory");
    };

    load_stage(0);
    load_stage(1);

    int a_r = wm * 32 + (lane & 15);
    int a_ch = (lane >> 4);
    int b_k = (lane & 7) + ((lane >> 3) & 1) * 8;
    int b_n8 = ((lane >> 4) & 1) * 8;

    #pragma unroll 1
    for (int it = 0; it < 16; it++) {
        int buf = it & 1;
        if (it < 15) asm volatile("cp.async.wait_group 1;" ::: "memory");
        else         asm volatile("cp.async.wait_group 0;" ::: "memory");
        __syncthreads();
        uint32_t base = sb + buf * STG;
        #pragma unroll
        for (int kk = 0; kk < 4; kk++) {
            uint32_t aH[2][4], aL[2][4];
            #pragma unroll
            for (int mt = 0; mt < 2; mt++) {
                uint32_t off = swA((uint32_t)((a_r + mt * 16) * 128 + (kk * 2 + a_ch) * 16));
                ldsm4(aH[mt], base + off);
                ldsm4(aL[mt], base + 16384 + off);
            }
            uint32_t bH[4][4], bL[4][4];
            #pragma unroll
            for (int p = 0; p < 4; p++) {
                int nb = wn * 64 + p * 16 + b_n8;
                uint32_t off = swB((uint32_t)((kk * 16 + b_k) * 256 + nb * 2));
                ldsm4t(bH[p], base + 32768 + off);
                ldsm4t(bL[p], base + 49152 + off);
            }
            #pragma unroll
            for (int mt = 0; mt < 2; mt++) {
                #pragma unroll
                for (int p = 0; p < 4; p++) {
                    mma_bf16(acc[mt][2 * p],     aH[mt], bH[p][0], bH[p][1]);
                    mma_bf16(acc[mt][2 * p],     aH[mt], bL[p][0], bL[p][1]);
                    mma_bf16(acc[mt][2 * p],     aL[mt], bH[p][0], bH[p][1]);
                    mma_bf16(acc[mt][2 * p + 1], aH[mt], bH[p][2], bH[p][3]);
                    mma_bf16(acc[mt][2 * p + 1], aH[mt], bL[p][2], bL[p][3]);
                    mma_bf16(acc[mt][2 * p + 1], aL[mt], bH[p][2], bH[p][3]);
                }
            }
        }
        __syncthreads();
        if (it + 2 < 16) load_stage(it + 2);
    }

    // epilogue: write Y as bf16 hi/lo
    int r_lo = lane >> 2;
    int c_lo = (lane & 3) * 2;
    if (row0 < 1024) {
        #pragma unroll
        for (int mt = 0; mt < 2; mt++) {
            int r = row0 + wm * 32 + mt * 16 + r_lo;
            #pragma unroll
            for (int nt = 0; nt < 8; nt++) {
                int c = col0 + wn * 64 + nt * 8 + c_lo;
                pack2(Y1h, Y1l, (size_t)r * LD + c,       acc[mt][nt][0], acc[mt][nt][1]);
                pack2(Y1h, Y1l, (size_t)(r + 8) * LD + c, acc[mt][nt][2], acc[mt][nt][3]);
            }
        }
    } else {
        #pragma unroll
        for (int mt = 0; mt < 2; mt++) {
            int r = row0 - 1024 + wm * 32 + mt * 16 + r_lo;
            #pragma unroll
            for (int nt = 0; nt < 8; nt++) {
                int c = col0 + wn * 64 + nt * 8 + c_lo;
                float2 x0 = *(const float2*)(Xf + (size_t)r * LD + c);
                float2 x1 = *(const float2*)(Xf + (size_t)(r + 8) * LD + c);
                pack2(Y2h, Y2l, (size_t)r * LD + c,       acc[mt][nt][0] - x0.x, acc[mt][nt][1] - x0.y);
                pack2(Y2h, Y2l, (size_t)(r + 8) * LD + c, acc[mt][nt][2] - x1.x, acc[mt][nt][3] - x1.y);
            }
        }
    }
}

// ---------------- HMMA weight matmul + GRU epilogue (one node per CTA) ----------------
// D^T[Fall][64] = W^T[Fall][K3pad=208] @ feats^T[208][64]
// GATE: rows 0..63 = z -> cat2 hidden slot gets z*h ; rows 64..127 = r -> rbuf
// !GATE: rows 0..63 = hc -> h = r*h + (1-r)*tanh(hc)
template <int C, bool GATE>
__global__ void __launch_bounds__(256) cell_mm(
    const __nv_bfloat16* __restrict__ F0h, const __nv_bfloat16* __restrict__ F0l,
    const __nv_bfloat16* __restrict__ F1h, const __nv_bfloat16* __restrict__ F1l,
    const __nv_bfloat16* __restrict__ F2h, const __nv_bfloat16* __restrict__ F2l,
    const __nv_bfloat16* __restrict__ Wimg, const float* __restrict__ bias,
    const float* __restrict__ hin, float* __restrict__ rbuf,
    float* __restrict__ cat2, __nv_bfloat16* __restrict__ c2h, __nv_bfloat16* __restrict__ c2l,
    float* __restrict__ hout)
{
    constexpr int Fall = GATE ? 128 : 64;
    constexpr int NP   = GATE ? 2 : 1;
    constexpr int BIMG = 208 * 128;     // feats image bytes per (h|l)
    constexpr int WIMG = Fall * 432;    // W image bytes per (h|l)
    constexpr int OFF  = C - 64;
    extern __shared__ __align__(16) char sm[];
    char* Bh = sm;
    char* Bl = sm + BIMG;
    char* Wh = sm + 2 * BIMG;
    char* Wl = Wh + WIMG;
    float* bs = (float*)(Wl + WIMG);
    int n = blockIdx.x, tid = threadIdx.x;
    int lane = tid & 31, wid = tid >> 5;
    uint32_t bBh = smem_u32(Bh), bBl = smem_u32(Bl);
    uint32_t bWh = smem_u32(Wh), bWl = smem_u32(Wl);

    const __nv_bfloat16* srcH[3] = {F0h + (size_t)n * LD, F1h + (size_t)n * LD, F2h + (size_t)n * LD};
    const __nv_bfloat16* srcL[3] = {F0l + (size_t)n * LD, F1l + (size_t)n * LD, F2l + (size_t)n * LD};

    // feats: 208 k-rows x 128B, swA swizzled
    for (int i = tid; i < 1664; i += 256) {
        int k = i >> 3, ch = i & 7;
        uint32_t sw = swA((uint32_t)(k * 128 + ch * 16));
        if (k < 3 * C) {
            int kk = k / C, c = k - kk * C;
            cpa16(bBh + sw, srcH[kk] + c * 64 + ch * 8);
            cpa16(bBl + sw, srcL[kk] + c * 64 + ch * 8);
        } else {
            uint4 z = make_uint4(0, 0, 0, 0);
            *(uint4*)(Bh + sw) = z;
            *(uint4*)(Bl + sw) = z;
        }
    }
    // W images: [f][432B] rows (216 bf16)
    for (int i = tid; i < Fall * 27; i += 256) {
        int f = i / 27, ch = i - f * 27;
        cpa16(bWh + f * 432 + ch * 16, Wimg + f * 216 + ch * 8);
        cpa16(bWl + f * 432 + ch * 16, Wimg + Fall * 216 + f * 216 + ch * 8);
    }
    if (tid < Fall) bs[tid] = bias[tid];
    asm volatile("cp.async.commit_group;" ::: "memory");
    asm volatile("cp.async.wait_group 0;" ::: "memory");
    __syncthreads();

    int wm = GATE ? (wid & 3) : (wid & 1);
    int wn = GATE ? (wid >> 2) : (wid >> 1);
    int f0 = wm * 32;
    int nb0 = wn * (GATE ? 32 : 16);
    int bk  = (lane & 7) + ((lane >> 3) & 1) * 8;
    int bn8 = ((lane >> 4) & 1) * 8;

    float acc[2][2 * NP][4];
    #pragma unroll
    for (int mt = 0; mt < 2; mt++)
        #pragma unroll
        for (int nt = 0; nt < 2 * NP; nt++)
            #pragma unroll
            for (int j = 0; j < 4; j++) acc[mt][nt][j] = 0.f;

    #pragma unroll 1
    for (int kt = 0; kt < 13; kt++) {
        uint32_t aH[2][4], aL[2][4];
        #pragma unroll
        for (int mt = 0; mt < 2; mt++) {
            uint32_t ao = (uint32_t)((f0 + mt * 16 + (lane & 15)) * 432 + kt * 32 + (lane >> 4) * 16);
            ldsm4(aH[mt], bWh + ao);
            ldsm4(aL[mt], bWl + ao);
        }
        #pragma unroll
        for (int p = 0; p < NP; p++) {
            uint32_t bo = swA((uint32_t)((kt * 16 + bk) * 128 + (nb0 + p * 16 + bn8) * 2));
            uint32_t bHf[4], bLf[4];
            ldsm4t(bHf, bBh + bo);
            ldsm4t(bLf, bBl + bo);
            #pragma unroll
            for (int mt = 0; mt < 2; mt++) {
                mma_bf16(acc[mt][2 * p],     aH[mt], bHf[0], bHf[1]);
                mma_bf16(acc[mt][2 * p],     aH[mt], bLf[0], bLf[1]);
                mma_bf16(acc[mt][2 * p],     aL[mt], bHf[0], bHf[1]);
                mma_bf16(acc[mt][2 * p + 1], aH[mt], bHf[2], bHf[3]);
                mma_bf16(acc[mt][2 * p + 1], aH[mt], bLf[2], bLf[3]);
                mma_bf16(acc[mt][2 * p + 1], aL[mt], bHf[2], bHf[3]);
            }
        }
    }

    // epilogue
    int r_lo = lane >> 2, c_lo = (lane & 3) * 2;
    size_t nLD = (size_t)n * LD;
    size_t nH  = (size_t)n * 4096;
    #pragma unroll
    for (int mt = 0; mt < 2; mt++) {
        int row = f0 + mt * 16 + r_lo;
        #pragma unroll
        for (int nt = 0; nt < 2 * NP; nt++) {
            int col = nb0 + nt * 8 + c_lo;
            float v0 = acc[mt][nt][0] + bs[row];
            float v1 = acc[mt][nt][1] + bs[row];
            float v2 = acc[mt][nt][2] + bs[row + 8];
            float v3 = acc[mt][nt][3] + bs[row + 8];
            if (GATE) {
                if (row < 64) {
                    // z rows
                    #pragma unroll
                    for (int q = 0; q < 2; q++) {
                        int f = row + q * 8;
                        float z0 = 1.f / (1.f + expf(-(q ? v2 : v0)));
                        float z1 = 1.f / (1.f + expf(-(q ? v3 : v1)));
                        float2 hv = *(const float2*)(hin + nH + (size_t)f * 64 + col);
                        float o0 = z0 * hv.x, o1 = z1 * hv.y;
                        size_t pos = nLD + (size_t)(OFF + f) * 64 + col;
                        *(float2*)(cat2 + pos) = make_float2(o0, o1);
                        pack2(c2h, c2l, pos, o0, o1);
                    }
                } else {
                    // r rows
                    #pragma unroll
                    for (int q = 0; q < 2; q++) {
                        int f = row - 64 + q * 8;
                        float r0 = 1.f / (1.f + expf(-(q ? v2 : v0)));
                        float r1 = 1.f / (1.f + expf(-(q ? v3 : v1)));
                        *(float2*)(rbuf + nH + (size_t)f * 64 + col) = make_float2(r0, r1);
                    }
                }
            } else {
                #pragma unroll
                for (int q = 0; q < 2; q++) {
                    int f = row + q * 8;
                    float hc0 = tanhf(q ? v2 : v0);
                    float hc1 = tanhf(q ? v3 : v1);
                    float2 rv = *(const float2*)(rbuf + nH + (size_t)f * 64 + col);
                    float2 hv = *(const float2*)(hin  + nH + (size_t)f * 64 + col);
                    float hn0 = rv.x * hv.x + (1.f - rv.x) * hc0;
                    float hn1 = rv.y * hv.y + (1.f - rv.y) * hc1;
                    *(float2*)(hout + nH + (size_t)f * 64 + col) = make_float2(hn0, hn1);
                }
            }
        }
    }
}

// ---------------- concat builders (c-major) ----------------
__global__ void build_cat_enc(const float* __restrict__ x, int t,
                              const float* __restrict__ h,
                              float* __restrict__ cat1,
                              __nv_bfloat16* __restrict__ c1h, __nv_bfloat16* __restrict__ c1l,
                              float* __restrict__ cat2,
                              __nv_bfloat16* __restrict__ c2h, __nv_bfloat16* __restrict__ c2l) {
    int n = blockIdx.x;
    size_t base = (size_t)n * LD;
    size_t nH = (size_t)n * 4096;
    for (int idx = threadIdx.x; idx < 65 * 64; idx += 256) {
        int slot = idx >> 6, b = idx & 63;
        float v;
        if (slot == 0) v = x[(size_t)(b * TT + t) * NN + n];
        else           v = h[nH + idx - 64];
        __nv_bfloat16 hh, ll;
        bsplit(v, hh, ll);
        cat1[base + idx] = v;
        c1h[base + idx] = hh;
        c1l[base + idx] = ll;
        if (slot == 0) {
            cat2[base + idx] = v;
            c2h[base + idx] = hh;
            c2l[base + idx] = ll;
        }
    }
}
__global__ void build_cat_dec(const float* __restrict__ yc, int t,
                              const float* __restrict__ go,
                              const float* __restrict__ h,
                              float* __restrict__ cat1,
                              __nv_bfloat16* __restrict__ c1h, __nv_bfloat16* __restrict__ c1l,
                              float* __restrict__ cat2,
                              __nv_bfloat16* __restrict__ c2h, __nv_bfloat16* __restrict__ c2l) {
    int n = blockIdx.x;
    size_t base = (size_t)n * LD;
    size_t nH = (size_t)n * 4096;
    for (int idx = threadIdx.x; idx < 66 * 64; idx += 256) {
        int slot = idx >> 6, b = idx & 63;
        float v;
        if (slot == 0)      v = go[n * 64 + b];
        else if (slot == 1) v = yc[(size_t)(b * TT + t) * NN + n];
        else                v = h[nH + idx - 128];
        __nv_bfloat16 hh, ll;
        bsplit(v, hh, ll);
        cat1[base + idx] = v;
        c1h[base + idx] = hh;
        c1l[base + idx] = ll;
        if (slot < 2) {
            cat2[base + idx] = v;
            c2h[base + idx] = hh;
            c2l[base + idx] = ll;
        }
    }
}

// ---------------- projection ----------------
__global__ void proj_kernel(const float* __restrict__ h, const float* __restrict__ pW,
                            const float* __restrict__ pb, float* __restrict__ go,
                            float* __restrict__ out, int t) {
    __shared__ float w[64];
    int n = blockIdx.x, b = threadIdx.x;
    w[b] = pW[b];
    __syncthreads();
    size_t nH = (size_t)n * 4096;
    float s = 0.f;
    #pragma unroll
    for (int f = 0; f < 64; f++) s = fmaf(h[nH + f * 64 + b], w[f], s);
    float v = s + pb[0];
    go[n * 64 + b] = v;
    out[(size_t)(b * TT + t) * NN + n] = v;
}

// ---------------- orchestration ----------------
extern "C" void kernel_launch(void* const* d_in, const int* in_sizes, int n_in,
                              void* d_out, int out_size) {
    const float* x    = (const float*)d_in[0];
    const float* ycov = (const float*)d_in[1];
    const float* emb  = (const float*)d_in[2];
    const float* egW  = (const float*)d_in[3];
    const float* egb  = (const float*)d_in[4];
    const float* euW  = (const float*)d_in[5];
    const float* eub  = (const float*)d_in[6];
    const float* dgW  = (const float*)d_in[7];
    const float* dgb  = (const float*)d_in[8];
    const float* duW  = (const float*)d_in[9];
    const float* dub  = (const float*)d_in[10];
    const float* pW   = (const float*)d_in[11];
    const float* pb   = (const float*)d_in[12];
    float* out = (float*)d_out;

    float *pM, *pc1, *pc2, *pY1, *pY2, *ph, *pr, *pgo;
    __nv_bfloat16 *pMh, *pMl, *p1h, *p1l, *p2h, *p2l, *pWgE, *pWgD, *pWuE, *pWuD;
    cudaGetSymbolAddress((void**)&pM,   g_M);
    cudaGetSymbolAddress((void**)&pMh,  g_Mh);
    cudaGetSymbolAddress((void**)&pMl,  g_Ml);
    cudaGetSymbolAddress((void**)&pc1,  g_cat1);
    cudaGetSymbolAddress((void**)&pc2,  g_cat2);
    cudaGetSymbolAddress((void**)&p1h,  g_c1h);
    cudaGetSymbolAddress((void**)&p1l,  g_c1l);
    cudaGetSymbolAddress((void**)&p2h,  g_c2h);
    cudaGetSymbolAddress((void**)&p2l,  g_c2l);
    cudaGetSymbolAddress((void**)&pY1,  g_Y1);
    cudaGetSymbolAddress((void**)&pY2,  g_Y2);
    cudaGetSymbolAddress((void**)&ph,   g_h);
    cudaGetSymbolAddress((void**)&pr,   g_r);
    cudaGetSymbolAddress((void**)&pgo,  g_go);
    cudaGetSymbolAddress((void**)&pWgE, g_WgE);
    cudaGetSymbolAddress((void**)&pWgD, g_WgD);
    cudaGetSymbolAddress((void**)&pWuE, g_WuE);
    cudaGetSymbolAddress((void**)&pWuD, g_WuD);

    __nv_bfloat16* pY1h = (__nv_bfloat16*)pY1;
    __nv_bfloat16* pY1l = pY1h + (size_t)NN * LD;
    __nv_bfloat16* pY2h = (__nv_bfloat16*)pY2;
    __nv_bfloat16* pY2l = pY2h + (size_t)NN * LD;

    const int smHM = 2 * STG;                          // 131072
    const int smG  = 2 * (208 * 128) + 2 * (128 * 432) + 512;  // 164352
    const int smU  = 2 * (208 * 128) + 2 * (64 * 432) + 256;   // 108800
    cudaFuncSetAttribute((const void*)hmma_gemm,          cudaFuncAttributeMaxDynamicSharedMemorySize, smHM);
    cudaFuncSetAttribute((const void*)cell_mm<65, true>,  cudaFuncAttributeMaxDynamicSharedMemorySize, smG);
    cudaFuncSetAttribute((const void*)cell_mm<66, true>,  cudaFuncAttributeMaxDynamicSharedMemorySize, smG);
    cudaFuncSetAttribute((const void*)cell_mm<65, false>, cudaFuncAttributeMaxDynamicSharedMemorySize, smU);
    cudaFuncSetAttribute((const void*)cell_mm<66, false>, cudaFuncAttributeMaxDynamicSharedMemorySize, smU);

    cudaMemsetAsync(ph,  0, (size_t)NN * 64 * 64 * sizeof(float));
    cudaMemsetAsync(pgo, 0, (size_t)NN * 64 * sizeof(float));
    cudaMemsetAsync(pc1, 0, (size_t)NN * LD * sizeof(float));
    cudaMemsetAsync(pc2, 0, (size_t)NN * LD * sizeof(float));
    cudaMemsetAsync(p1h, 0, (size_t)NN * LD * sizeof(__nv_bfloat16));
    cudaMemsetAsync(p1l, 0, (size_t)NN * LD * sizeof(__nv_bfloat16));
    cudaMemsetAsync(p2h, 0, (size_t)NN * LD * sizeof(__nv_bfloat16));
    cudaMemsetAsync(p2l, 0, (size_t)NN * LD * sizeof(__nv_bfloat16));

    build_support_kernel<<<NN, 256>>>(emb, pM);
    gemmA2<<<dim3(8, 8), 256>>>(pM, pM + (size_t)NN * NN);
    convert_M<<<2 * NN * NN / 256, 256>>>(pM, pMh, pMl);
    prep_W<<<128, 64>>>(egW, 195, 128, pWgE);
    prep_W<<<128, 64>>>(dgW, 198, 128, pWgD);
    prep_W<<<64, 64>>>(euW, 195, 64, pWuE);
    prep_W<<<64, 64>>>(duW, 198, 64, pWuD);

    dim3 gg(33, 16);
    for (int t = 0; t < TT; t++) {
        build_cat_enc<<<NN, 256>>>(x, t, ph, pc1, p1h, p1l, pc2, p2h, p2l);
        hmma_gemm<<<gg, 256, smHM>>>(pMh, pMl, p1h, p1l, pc1, pY1h, pY1l, pY2h, pY2l);
        cell_mm<65, true><<<NN, 256, smG>>>(p1h, p1l, pY1h, pY1l, pY2h, pY2l,
                                            pWgE, egb, ph, pr, pc2, p2h, p2l, nullptr);
        hmma_gemm<<<gg, 256, smHM>>>(pMh, pMl, p2h, p2l, pc2, pY1h, pY1l, pY2h, pY2l);
        cell_mm<65, false><<<NN, 256, smU>>>(p2h, p2l, pY1h, pY1l, pY2h, pY2l,
                                             pWuE, eub, ph, pr, nullptr, nullptr, nullptr, ph);
    }
    for (int t = 0; t < TT; t++) {
        build_cat_dec<<<NN, 256>>>(ycov, t, pgo, ph, pc1, p1h, p1l, pc2, p2h, p2l);
        hmma_gemm<<<gg, 256, smHM>>>(pMh, pMl, p1h, p1l, pc1, pY1h, pY1l, pY2h, pY2l);
        cell_mm<66, true><<<NN, 256, smG>>>(p1h, p1l, pY1h, pY1l, pY2h, pY2l,
                                            pWgD, dgb, ph, pr, pc2, p2h, p2l, nullptr);
        hmma_gemm<<<gg, 256, smHM>>>(pMh, pMl, p2h, p2l, pc2, pY1h, pY1l, pY2h, pY2l);
        cell_mm<66, false><<<NN, 256, smU>>>(p2h, p2l, pY1h, pY1l, pY2h, pY2l,
                                             pWuD, dub, ph, pr, nullptr, nullptr, nullptr, ph);
        proj_kernel<<<NN, 64>>>(ph, pW, pb, pgo, out, t);
    }
}

// round 11
// speedup vs baseline: 1.5274x; 1.0038x over previous
#include <cuda_runtime.h>
#include <cuda_bf16.h>
#include <math.h>
#include <stdint.h>

#define NN 1024
#define TT 12
#define LD 4352   // padded cols; GEMM covers 33*128 = 4224

// ---------------- scratch ----------------
__device__ float g_M [2 * NN * NN];
__device__ __align__(256) __nv_bfloat16 g_Mh[2 * NN * NN];
__device__ __align__(256) __nv_bfloat16 g_Ml[2 * NN * NN];
__device__ __align__(256) __nv_bfloat16 g_c1h[NN * LD];   // cat1 bf16 hi, c-major [n][c*64+b]
__device__ __align__(256) __nv_bfloat16 g_c1l[NN * LD];
__device__ __align__(256) __nv_bfloat16 g_c2h[NN * LD];
__device__ __align__(256) __nv_bfloat16 g_c2l[NN * LD];
__device__ __align__(256) __nv_bfloat16 g_Y1h[NN * LD];
__device__ __align__(256) __nv_bfloat16 g_Y1l[NN * LD];
__device__ __align__(256) __nv_bfloat16 g_Y2h[NN * LD];
__device__ __align__(256) __nv_bfloat16 g_Y2l[NN * LD];
__device__ float g_h [NN * 64 * 64];              // [n][f*64+b]
__device__ float g_r [NN * 64 * 64];              // [n][f*64+b]
__device__ float g_go[NN * 64];                   // [n*64+b]
// W images: [h|l], each [Fall][216] bf16 (k padded to 216, zero beyond K3)
__device__ __align__(256) __nv_bfloat16 g_WgE[2 * 128 * 216];
__device__ __align__(256) __nv_bfloat16 g_WgD[2 * 128 * 216];
__device__ __align__(256) __nv_bfloat16 g_WuE[2 * 64 * 216];
__device__ __align__(256) __nv_bfloat16 g_WuD[2 * 64 * 216];

// ---------------- helpers ----------------
__device__ __forceinline__ uint32_t smem_u32(const void* p) {
    uint32_t a;
    asm("{ .reg .u64 t; cvta.to.shared.u64 t, %1; cvt.u32.u64 %0, t; }" : "=r"(a) : "l"(p));
    return a;
}
__device__ __forceinline__ void cpa16(uint32_t dst, const void* src) {
    asm volatile("cp.async.cg.shared.global [%0], [%1], 16;" :: "r"(dst), "l"(src));
}
__device__ __forceinline__ void ldsm4(uint32_t* r, uint32_t a) {
    asm volatile("ldmatrix.sync.aligned.m8n8.x4.shared.b16 {%0,%1,%2,%3}, [%4];"
        : "=r"(r[0]), "=r"(r[1]), "=r"(r[2]), "=r"(r[3]) : "r"(a));
}
__device__ __forceinline__ void ldsm4t(uint32_t* r, uint32_t a) {
    asm volatile("ldmatrix.sync.aligned.m8n8.x4.trans.shared.b16 {%0,%1,%2,%3}, [%4];"
        : "=r"(r[0]), "=r"(r[1]), "=r"(r[2]), "=r"(r[3]) : "r"(a));
}
__device__ __forceinline__ void mma_bf16(float* d, const uint32_t* a, uint32_t b0, uint32_t b1) {
    asm volatile("mma.sync.aligned.m16n8k16.row.col.f32.bf16.bf16.f32 "
        "{%0,%1,%2,%3},{%4,%5,%6,%7},{%8,%9},{%0,%1,%2,%3};"
        : "+f"(d[0]), "+f"(d[1]), "+f"(d[2]), "+f"(d[3])
        : "r"(a[0]), "r"(a[1]), "r"(a[2]), "r"(a[3]), "r"(b0), "r"(b1));
}
__device__ __forceinline__ void bsplit(float v, __nv_bfloat16& h16, __nv_bfloat16& l16) {
    h16 = __float2bfloat16(v);
    l16 = __float2bfloat16(v - __bfloat162float(h16));
}
__device__ __forceinline__ void pack2(__nv_bfloat16* H, __nv_bfloat16* L, size_t idx,
                                      float v0, float v1) {
    __nv_bfloat16 h0, l0, h1, l1;
    bsplit(v0, h0, l0);
    bsplit(v1, h1, l1);
    __nv_bfloat162 hp; hp.x = h0; hp.y = h1;
    __nv_bfloat162 lp; lp.x = l0; lp.y = l1;
    *reinterpret_cast<__nv_bfloat162*>(H + idx) = hp;
    *reinterpret_cast<__nv_bfloat162*>(L + idx) = lp;
}
__device__ __forceinline__ float2 rec2(const __nv_bfloat16* H, const __nv_bfloat16* L, size_t idx) {
    __nv_bfloat162 hp = *reinterpret_cast<const __nv_bfloat162*>(H + idx);
    __nv_bfloat162 lp = *reinterpret_cast<const __nv_bfloat162*>(L + idx);
    return make_float2(__bfloat162float(hp.x) + __bfloat162float(lp.x),
                       __bfloat162float(hp.y) + __bfloat162float(lp.y));
}
__device__ __forceinline__ uint32_t swA(uint32_t off) { return off ^ ((off >> 3) & 0x70); }
__device__ __forceinline__ uint32_t swB(uint32_t off) { return off ^ (((off >> 8) & 7) << 4); }

// ---------------- support: A = softmax(relu(E E^T), rows) ----------------
__global__ void build_support_kernel(const float* __restrict__ emb, float* __restrict__ A) {
    __shared__ float se[NN * 8];
    __shared__ float row[NN];
    __shared__ float wred[8];
    __shared__ float red;
    int n = blockIdx.x, tid = threadIdx.x;
    for (int i = tid; i < NN * 8; i += 256) se[i] = emb[i];
    __syncthreads();
    float e[8];
    #pragma unroll
    for (int j = 0; j < 8; j++) e[j] = se[n * 8 + j];
    float mx = 0.f;
    for (int m = tid; m < NN; m += 256) {
        const float* em = &se[m * 8];
        float s = 0.f;
        #pragma unroll
        for (int j = 0; j < 8; j++) s += e[j] * em[j];
        s = fmaxf(s, 0.f);
        row[m] = s;
        mx = fmaxf(mx, s);
    }
    #pragma unroll
    for (int o = 16; o; o >>= 1) mx = fmaxf(mx, __shfl_xor_sync(0xffffffffu, mx, o));
    if ((tid & 31) == 0) wred[tid >> 5] = mx;
    __syncthreads();
    if (tid == 0) { float v = wred[0]; for (int w = 1; w < 8; w++) v = fmaxf(v, wred[w]); red = v; }
    __syncthreads();
    float bmax = red, sum = 0.f;
    for (int m = tid; m < NN; m += 256) { float v = expf(row[m] - bmax); row[m] = v; sum += v; }
    #pragma unroll
    for (int o = 16; o; o >>= 1) sum += __shfl_xor_sync(0xffffffffu, sum, o);
    if ((tid & 31) == 0) wred[tid >> 5] = sum;
    __syncthreads();
    if (tid == 0) { float v = 0.f; for (int w = 0; w < 8; w++) v += wred[w]; red = v; }
    __syncthreads();
    float inv = 1.f / red;
    for (int m = tid; m < NN; m += 256) A[n * NN + m] = row[m] * inv;
}

// ---------------- A2 = A @ A ----------------
__global__ void __launch_bounds__(256, 2) gemmA2(const float* __restrict__ A, float* __restrict__ A2) {
    __shared__ __align__(16) float As[2][8][132];
    __shared__ __align__(16) float Bs[2][8][128];
    int tid = threadIdx.x;
    int row0 = blockIdx.y * 128, col0 = blockIdx.x * 128;
    int arow = tid >> 1, acol4 = (tid & 1) << 2;
    int brow = tid >> 5, bcol4 = (tid & 31) << 2;
    int tx = tid & 15, ty = tid >> 4;
    const float* Ap = A + (size_t)(row0 + arow) * NN + acol4;
    const float* Xp = A + (size_t)brow * NN + col0 + bcol4;
    float acc[8][8];
    #pragma unroll
    for (int i = 0; i < 8; i++)
        #pragma unroll
        for (int j = 0; j < 8; j++) acc[i][j] = 0.f;
    float4 av = *(const float4*)Ap;
    float4 bv = *(const float4*)Xp;
    int buf = 0;
    As[0][acol4 + 0][arow] = av.x; As[0][acol4 + 1][arow] = av.y;
    As[0][acol4 + 2][arow] = av.z; As[0][acol4 + 3][arow] = av.w;
    *(float4*)&Bs[0][brow][bcol4] = bv;
    __syncthreads();
    for (int kt = 1; kt < 128; kt++) {
        av = *(const float4*)(Ap + kt * 8);
        bv = *(const float4*)(Xp + (size_t)(kt * 8) * NN);
        #pragma unroll
        for (int kk = 0; kk < 8; kk++) {
            float4 a0 = *(const float4*)&As[buf][kk][ty * 4];
            float4 a1 = *(const float4*)&As[buf][kk][64 + ty * 4];
            float4 b0 = *(const float4*)&Bs[buf][kk][tx * 4];
            float4 b1 = *(const float4*)&Bs[buf][kk][64 + tx * 4];
            float a[8] = {a0.x,a0.y,a0.z,a0.w,a1.x,a1.y,a1.z,a1.w};
            float b[8] = {b0.x,b0.y,b0.z,b0.w,b1.x,b1.y,b1.z,b1.w};
            #pragma unroll
            for (int i = 0; i < 8; i++)
                #pragma unroll
                for (int j = 0; j < 8; j++) acc[i][j] = fmaf(a[i], b[j], acc[i][j]);
        }
        buf ^= 1;
        As[buf][acol4 + 0][arow] = av.x; As[buf][acol4 + 1][arow] = av.y;
        As[buf][acol4 + 2][arow] = av.z; As[buf][acol4 + 3][arow] = av.w;
        *(float4*)&Bs[buf][brow][bcol4] = bv;
        __syncthreads();
    }
    #pragma unroll
    for (int kk = 0; kk < 8; kk++) {
        float4 a0 = *(const float4*)&As[buf][kk][ty * 4];
        float4 a1 = *(const float4*)&As[buf][kk][64 + ty * 4];
        float4 b0 = *(const float4*)&Bs[buf][kk][tx * 4];
        float4 b1 = *(const float4*)&Bs[buf][kk][64 + tx * 4];
        float a[8] = {a0.x,a0.y,a0.z,a0.w,a1.x,a1.y,a1.z,a1.w};
        float b[8] = {b0.x,b0.y,b0.z,b0.w,b1.x,b1.y,b1.z,b1.w};
        #pragma unroll
        for (int i = 0; i < 8; i++)
            #pragma unroll
            for (int j = 0; j < 8; j++) acc[i][j] = fmaf(a[i], b[j], acc[i][j]);
    }
    #pragma unroll
    for (int i = 0; i < 8; i++) {
        int grow = row0 + ((i < 4) ? (ty * 4 + i) : (64 + ty * 4 + i - 4));
        float* yp = A2 + (size_t)grow * NN;
        *(float4*)(yp + col0 + tx * 4)       = make_float4(acc[i][0], acc[i][1], acc[i][2], acc[i][3]);
        *(float4*)(yp + col0 + 64 + tx * 4)  = make_float4(acc[i][4], acc[i][5], acc[i][6], acc[i][7]);
    }
}

// ---------------- M -> bf16 hi/lo (fold 2x into bottom half) ----------------
__global__ void convert_M(const float* __restrict__ M,
                          __nv_bfloat16* __restrict__ Mh, __nv_bfloat16* __restrict__ Ml) {
    int i = blockIdx.x * 256 + threadIdx.x;
    float v = M[i];
    if (i >= NN * NN) v *= 2.f;
    __nv_bfloat16 h, l;
    bsplit(v, h, l);
    Mh[i] = h;
    Ml[i] = l;
}

// ---------------- W^T image prep ----------------
__global__ void prep_W(const float* __restrict__ W, int K3, int Fall,
                       __nv_bfloat16* __restrict__ img) {
    int f = blockIdx.x;
    __nv_bfloat16* imgH = img;
    __nv_bfloat16* imgL = img + Fall * 216;
    for (int k = threadIdx.x; k < 216; k += 64) {
        float v = (k < K3) ? W[k * Fall + f] : 0.f;
        __nv_bfloat16 h, l;
        bsplit(v, h, l);
        imgH[f * 216 + k] = h;
        imgL[f * 216 + k] = l;
    }
}

// ---------------- HMMA split-bf16 diffusion GEMM ----------------
#define KC 64
#define STG 65536
__global__ void __launch_bounds__(256, 1) hmma_gemm(
    const __nv_bfloat16* __restrict__ Mh, const __nv_bfloat16* __restrict__ Ml,
    const __nv_bfloat16* __restrict__ Xh, const __nv_bfloat16* __restrict__ Xl,
    __nv_bfloat16* __restrict__ Y1h, __nv_bfloat16* __restrict__ Y1l,
    __nv_bfloat16* __restrict__ Y2h, __nv_bfloat16* __restrict__ Y2l)
{
    extern __shared__ __align__(1024) char smem[];
    uint32_t sb = smem_u32(smem);
    int tid = threadIdx.x;
    int lane = tid & 31, wid = tid >> 5;
    int wm = wid >> 1, wn = wid & 1;
    int row0 = blockIdx.y * 128;
    int col0 = blockIdx.x * 128;

    float acc[2][8][4];
    #pragma unroll
    for (int mt = 0; mt < 2; mt++)
        #pragma unroll
        for (int nt = 0; nt < 8; nt++)
            #pragma unroll
            for (int j = 0; j < 4; j++) acc[mt][nt][j] = 0.f;

    auto load_stage = [&](int it) {
        uint32_t base = sb + (it & 1) * STG;
        int k0 = it * KC;
        #pragma unroll
        for (int i = tid; i < 1024; i += 256) {
            int r = i >> 3, c = i & 7;
            uint32_t sw = swA((uint32_t)(r * 128 + c * 16));
            size_t g = (size_t)(row0 + r) * NN + k0 + c * 8;
            cpa16(base + sw, Mh + g);
            cpa16(base + 16384 + sw, Ml + g);
        }
        #pragma unroll
        for (int i = tid; i < 1024; i += 256) {
            int k = i >> 4, c = i & 15;
            uint32_t sw = swB((uint32_t)(k * 256 + c * 16));
            size_t g = (size_t)(k0 + k) * LD + col0 + c * 8;
            cpa16(base + 32768 + sw, Xh + g);
            cpa16(base + 49152 + sw, Xl + g);
        }
        asm volatile("cp.async.commit_group;" ::: "memory");
    };

    load_stage(0);
    load_stage(1);

    int a_r = wm * 32 + (lane & 15);
    int a_ch = (lane >> 4);
    int b_k = (lane & 7) + ((lane >> 3) & 1) * 8;
    int b_n8 = ((lane >> 4) & 1) * 8;

    #pragma unroll 1
    for (int it = 0; it < 16; it++) {
        int buf = it & 1;
        if (it < 15) asm volatile("cp.async.wait_group 1;" ::: "memory");
        else         asm volatile("cp.async.wait_group 0;" ::: "memory");
        __syncthreads();
        uint32_t base = sb + buf * STG;
        #pragma unroll
        for (int kk = 0; kk < 4; kk++) {
            uint32_t aH[2][4], aL[2][4];
            #pragma unroll
            for (int mt = 0; mt < 2; mt++) {
                uint32_t off = swA((uint32_t)((a_r + mt * 16) * 128 + (kk * 2 + a_ch) * 16));
                ldsm4(aH[mt], base + off);
                ldsm4(aL[mt], base + 16384 + off);
            }
            uint32_t bH[4][4], bL[4][4];
            #pragma unroll
            for (int p = 0; p < 4; p++) {
                int nb = wn * 64 + p * 16 + b_n8;
                uint32_t off = swB((uint32_t)((kk * 16 + b_k) * 256 + nb * 2));
                ldsm4t(bH[p], base + 32768 + off);
                ldsm4t(bL[p], base + 49152 + off);
            }
            #pragma unroll
            for (int mt = 0; mt < 2; mt++) {
                #pragma unroll
                for (int p = 0; p < 4; p++) {
                    mma_bf16(acc[mt][2 * p],     aH[mt], bH[p][0], bH[p][1]);
                    mma_bf16(acc[mt][2 * p],     aH[mt], bL[p][0], bL[p][1]);
                    mma_bf16(acc[mt][2 * p],     aL[mt], bH[p][0], bH[p][1]);
                    mma_bf16(acc[mt][2 * p + 1], aH[mt], bH[p][2], bH[p][3]);
                    mma_bf16(acc[mt][2 * p + 1], aH[mt], bL[p][2], bL[p][3]);
                    mma_bf16(acc[mt][2 * p + 1], aL[mt], bH[p][2], bH[p][3]);
                }
            }
        }
        __syncthreads();
        if (it + 2 < 16) load_stage(it + 2);
    }

    // epilogue: write Y as bf16 hi/lo; Y2 subtracts X reconstructed from hi/lo
    int r_lo = lane >> 2;
    int c_lo = (lane & 3) * 2;
    if (row0 < 1024) {
        #pragma unroll
        for (int mt = 0; mt < 2; mt++) {
            int r = row0 + wm * 32 + mt * 16 + r_lo;
            #pragma unroll
            for (int nt = 0; nt < 8; nt++) {
                int c = col0 + wn * 64 + nt * 8 + c_lo;
                pack2(Y1h, Y1l, (size_t)r * LD + c,       acc[mt][nt][0], acc[mt][nt][1]);
                pack2(Y1h, Y1l, (size_t)(r + 8) * LD + c, acc[mt][nt][2], acc[mt][nt][3]);
            }
        }
    } else {
        #pragma unroll
        for (int mt = 0; mt < 2; mt++) {
            int r = row0 - 1024 + wm * 32 + mt * 16 + r_lo;
            #pragma unroll
            for (int nt = 0; nt < 8; nt++) {
                int c = col0 + wn * 64 + nt * 8 + c_lo;
                float2 x0 = rec2(Xh, Xl, (size_t)r * LD + c);
                float2 x1 = rec2(Xh, Xl, (size_t)(r + 8) * LD + c);
                pack2(Y2h, Y2l, (size_t)r * LD + c,       acc[mt][nt][0] - x0.x, acc[mt][nt][1] - x0.y);
                pack2(Y2h, Y2l, (size_t)(r + 8) * LD + c, acc[mt][nt][2] - x1.x, acc[mt][nt][3] - x1.y);
            }
        }
    }
}

// ---------------- HMMA weight matmul + GRU epilogue (one node per CTA) ----------------
// GATE: rows 0..63 = z -> cat2 h-slot gets z*h (bf16 h/l) ; rows 64..127 = r -> rbuf
// !GATE: rows 0..63 = hc -> h = r*h + (1-r)*tanh(hc); writes h fp32 AND next cat1 h-slot bf16
template <int C, bool GATE>
__global__ void __launch_bounds__(256) cell_mm(
    const __nv_bfloat16* __restrict__ F0h, const __nv_bfloat16* __restrict__ F0l,
    const __nv_bfloat16* __restrict__ F1h, const __nv_bfloat16* __restrict__ F1l,
    const __nv_bfloat16* __restrict__ F2h, const __nv_bfloat16* __restrict__ F2l,
    const __nv_bfloat16* __restrict__ Wimg, const float* __restrict__ bias,
    const float* __restrict__ hin, float* __restrict__ rbuf,
    __nv_bfloat16* __restrict__ outH, __nv_bfloat16* __restrict__ outL,
    float* __restrict__ hout, int offn)
{
    constexpr int Fall = GATE ? 128 : 64;
    constexpr int NP   = GATE ? 2 : 1;
    constexpr int BIMG = 208 * 128;
    constexpr int WIMG = Fall * 432;
    constexpr int OFF  = C - 64;
    extern __shared__ __align__(16) char sm[];
    char* Bh = sm;
    char* Bl = sm + BIMG;
    char* Wh = sm + 2 * BIMG;
    char* Wl = Wh + WIMG;
    float* bs = (float*)(Wl + WIMG);
    int n = blockIdx.x, tid = threadIdx.x;
    int lane = tid & 31, wid = tid >> 5;
    uint32_t bBh = smem_u32(Bh), bBl = smem_u32(Bl);
    uint32_t bWh = smem_u32(Wh), bWl = smem_u32(Wl);

    const __nv_bfloat16* srcH[3] = {F0h + (size_t)n * LD, F1h + (size_t)n * LD, F2h + (size_t)n * LD};
    const __nv_bfloat16* srcL[3] = {F0l + (size_t)n * LD, F1l + (size_t)n * LD, F2l + (size_t)n * LD};

    for (int i = tid; i < 1664; i += 256) {
        int k = i >> 3, ch = i & 7;
        uint32_t sw = swA((uint32_t)(k * 128 + ch * 16));
        if (k < 3 * C) {
            int kk = k / C, c = k - kk * C;
            cpa16(bBh + sw, srcH[kk] + c * 64 + ch * 8);
            cpa16(bBl + sw, srcL[kk] + c * 64 + ch * 8);
        } else {
            uint4 z = make_uint4(0, 0, 0, 0);
            *(uint4*)(Bh + sw) = z;
            *(uint4*)(Bl + sw) = z;
        }
    }
    for (int i = tid; i < Fall * 27; i += 256) {
        int f = i / 27, ch = i - f * 27;
        cpa16(bWh + f * 432 + ch * 16, Wimg + f * 216 + ch * 8);
        cpa16(bWl + f * 432 + ch * 16, Wimg + Fall * 216 + f * 216 + ch * 8);
    }
    if (tid < Fall) bs[tid] = bias[tid];
    asm volatile("cp.async.commit_group;" ::: "memory");
    asm volatile("cp.async.wait_group 0;" ::: "memory");
    __syncthreads();

    int wm = GATE ? (wid & 3) : (wid & 1);
    int wn = GATE ? (wid >> 2) : (wid >> 1);
    int f0 = wm * 32;
    int nb0 = wn * (GATE ? 32 : 16);
    int bk  = (lane & 7) + ((lane >> 3) & 1) * 8;
    int bn8 = ((lane >> 4) & 1) * 8;

    float acc[2][2 * NP][4];
    #pragma unroll
    for (int mt = 0; mt < 2; mt++)
        #pragma unroll
        for (int nt = 0; nt < 2 * NP; nt++)
            #pragma unroll
            for (int j = 0; j < 4; j++) acc[mt][nt][j] = 0.f;

    #pragma unroll 1
    for (int kt = 0; kt < 13; kt++) {
        uint32_t aH[2][4], aL[2][4];
        #pragma unroll
        for (int mt = 0; mt < 2; mt++) {
            uint32_t ao = (uint32_t)((f0 + mt * 16 + (lane & 15)) * 432 + kt * 32 + (lane >> 4) * 16);
            ldsm4(aH[mt], bWh + ao);
            ldsm4(aL[mt], bWl + ao);
        }
        #pragma unroll
        for (int p = 0; p < NP; p++) {
            uint32_t bo = swA((uint32_t)((kt * 16 + bk) * 128 + (nb0 + p * 16 + bn8) * 2));
            uint32_t bHf[4], bLf[4];
            ldsm4t(bHf, bBh + bo);
            ldsm4t(bLf, bBl + bo);
            #pragma unroll
            for (int mt = 0; mt < 2; mt++) {
                mma_bf16(acc[mt][2 * p],     aH[mt], bHf[0], bHf[1]);
                mma_bf16(acc[mt][2 * p],     aH[mt], bLf[0], bLf[1]);
                mma_bf16(acc[mt][2 * p],     aL[mt], bHf[0], bHf[1]);
                mma_bf16(acc[mt][2 * p + 1], aH[mt], bHf[2], bHf[3]);
                mma_bf16(acc[mt][2 * p + 1], aH[mt], bLf[2], bLf[3]);
                mma_bf16(acc[mt][2 * p + 1], aL[mt], bHf[2], bHf[3]);
            }
        }
    }

    // epilogue
    int r_lo = lane >> 2, c_lo = (lane & 3) * 2;
    size_t nLD = (size_t)n * LD;
    size_t nH  = (size_t)n * 4096;
    #pragma unroll
    for (int mt = 0; mt < 2; mt++) {
        int row = f0 + mt * 16 + r_lo;
        #pragma unroll
        for (int nt = 0; nt < 2 * NP; nt++) {
            int col = nb0 + nt * 8 + c_lo;
            float v0 = acc[mt][nt][0] + bs[row];
            float v1 = acc[mt][nt][1] + bs[row];
            float v2 = acc[mt][nt][2] + bs[row + 8];
            float v3 = acc[mt][nt][3] + bs[row + 8];
            if (GATE) {
                if (row < 64) {
                    #pragma unroll
                    for (int q = 0; q < 2; q++) {
                        int f = row + q * 8;
                        float z0 = 1.f / (1.f + expf(-(q ? v2 : v0)));
                        float z1 = 1.f / (1.f + expf(-(q ? v3 : v1)));
                        float2 hv = *(const float2*)(hin + nH + (size_t)f * 64 + col);
                        pack2(outH, outL, nLD + (size_t)(OFF + f) * 64 + col, z0 * hv.x, z1 * hv.y);
                    }
                } else {
                    #pragma unroll
                    for (int q = 0; q < 2; q++) {
                        int f = row - 64 + q * 8;
                        float r0 = 1.f / (1.f + expf(-(q ? v2 : v0)));
                        float r1 = 1.f / (1.f + expf(-(q ? v3 : v1)));
                        *(float2*)(rbuf + nH + (size_t)f * 64 + col) = make_float2(r0, r1);
                    }
                }
            } else {
                #pragma unroll
                for (int q = 0; q < 2; q++) {
                    int f = row + q * 8;
                    float hc0 = tanhf(q ? v2 : v0);
                    float hc1 = tanhf(q ? v3 : v1);
                    float2 rv = *(const float2*)(rbuf + nH + (size_t)f * 64 + col);
                    float2 hv = *(const float2*)(hin  + nH + (size_t)f * 64 + col);
                    float hn0 = rv.x * hv.x + (1.f - rv.x) * hc0;
                    float hn1 = rv.y * hv.y + (1.f - rv.y) * hc1;
                    *(float2*)(hout + nH + (size_t)f * 64 + col) = make_float2(hn0, hn1);
                    pack2(outH, outL, nLD + (size_t)(offn + f) * 64 + col, hn0, hn1);
                }
            }
        }
    }
}

// ---------------- per-step column injection (c-major, coalesced bf16 writes) ----------------
__global__ void inject_enc(const float* __restrict__ x, int t,
                           __nv_bfloat16* __restrict__ c1h, __nv_bfloat16* __restrict__ c1l,
                           __nv_bfloat16* __restrict__ c2h, __nv_bfloat16* __restrict__ c2l) {
    int n = blockIdx.x, b = threadIdx.x;
    float v = x[(size_t)(b * TT + t) * NN + n];
    __nv_bfloat16 hh, ll;
    bsplit(v, hh, ll);
    size_t pos = (size_t)n * LD + b;
    c1h[pos] = hh; c1l[pos] = ll;
    c2h[pos] = hh; c2l[pos] = ll;
}
__global__ void inject_dec(const float* __restrict__ yc, int t, const float* __restrict__ go,
                           __nv_bfloat16* __restrict__ c1h, __nv_bfloat16* __restrict__ c1l,
                           __nv_bfloat16* __restrict__ c2h, __nv_bfloat16* __restrict__ c2l) {
    int n = blockIdx.x, b = threadIdx.x;
    float v0 = go[n * 64 + b];
    float v1 = yc[(size_t)(b * TT + t) * NN + n];
    __nv_bfloat16 h0, l0, h1, l1;
    bsplit(v0, h0, l0);
    bsplit(v1, h1, l1);
    size_t pos = (size_t)n * LD + b;
    c1h[pos] = h0; c1l[pos] = l0;
    c2h[pos] = h0; c2l[pos] = l0;
    c1h[pos + 64] = h1; c1l[pos + 64] = l1;
    c2h[pos + 64] = h1; c2l[pos + 64] = l1;
}

// ---------------- projection ----------------
__global__ void proj_kernel(const float* __restrict__ h, const float* __restrict__ pW,
                            const float* __restrict__ pb, float* __restrict__ go,
                            float* __restrict__ out, int t) {
    __shared__ float w[64];
    int n = blockIdx.x, b = threadIdx.x;
    w[b] = pW[b];
    __syncthreads();
    size_t nH = (size_t)n * 4096;
    float s = 0.f;
    #pragma unroll
    for (int f = 0; f < 64; f++) s = fmaf(h[nH + f * 64 + b], w[f], s);
    float v = s + pb[0];
    go[n * 64 + b] = v;
    out[(size_t)(b * TT + t) * NN + n] = v;
}

// ---------------- orchestration ----------------
extern "C" void kernel_launch(void* const* d_in, const int* in_sizes, int n_in,
                              void* d_out, int out_size) {
    const float* x    = (const float*)d_in[0];
    const float* ycov = (const float*)d_in[1];
    const float* emb  = (const float*)d_in[2];
    const float* egW  = (const float*)d_in[3];
    const float* egb  = (const float*)d_in[4];
    const float* euW  = (const float*)d_in[5];
    const float* eub  = (const float*)d_in[6];
    const float* dgW  = (const float*)d_in[7];
    const float* dgb  = (const float*)d_in[8];
    const float* duW  = (const float*)d_in[9];
    const float* dub  = (const float*)d_in[10];
    const float* pW   = (const float*)d_in[11];
    const float* pb   = (const float*)d_in[12];
    float* out = (float*)d_out;

    float *pM, *ph, *pr, *pgo;
    __nv_bfloat16 *pMh, *pMl, *p1h, *p1l, *p2h, *p2l;
    __nv_bfloat16 *pY1h, *pY1l, *pY2h, *pY2l, *pWgE, *pWgD, *pWuE, *pWuD;
    cudaGetSymbolAddress((void**)&pM,   g_M);
    cudaGetSymbolAddress((void**)&pMh,  g_Mh);
    cudaGetSymbolAddress((void**)&pMl,  g_Ml);
    cudaGetSymbolAddress((void**)&p1h,  g_c1h);
    cudaGetSymbolAddress((void**)&p1l,  g_c1l);
    cudaGetSymbolAddress((void**)&p2h,  g_c2h);
    cudaGetSymbolAddress((void**)&p2l,  g_c2l);
    cudaGetSymbolAddress((void**)&pY1h, g_Y1h);
    cudaGetSymbolAddress((void**)&pY1l, g_Y1l);
    cudaGetSymbolAddress((void**)&pY2h, g_Y2h);
    cudaGetSymbolAddress((void**)&pY2l, g_Y2l);
    cudaGetSymbolAddress((void**)&ph,   g_h);
    cudaGetSymbolAddress((void**)&pr,   g_r);
    cudaGetSymbolAddress((void**)&pgo,  g_go);
    cudaGetSymbolAddress((void**)&pWgE, g_WgE);
    cudaGetSymbolAddress((void**)&pWgD, g_WgD);
    cudaGetSymbolAddress((void**)&pWuE, g_WuE);
    cudaGetSymbolAddress((void**)&pWuD, g_WuD);

    const int smHM = 2 * STG;
    const int smG  = 2 * (208 * 128) + 2 * (128 * 432) + 512;
    const int smU  = 2 * (208 * 128) + 2 * (64 * 432) + 256;
    cudaFuncSetAttribute((const void*)hmma_gemm,          cudaFuncAttributeMaxDynamicSharedMemorySize, smHM);
    cudaFuncSetAttribute((const void*)cell_mm<65, true>,  cudaFuncAttributeMaxDynamicSharedMemorySize, smG);
    cudaFuncSetAttribute((const void*)cell_mm<66, true>,  cudaFuncAttributeMaxDynamicSharedMemorySize, smG);
    cudaFuncSetAttribute((const void*)cell_mm<65, false>, cudaFuncAttributeMaxDynamicSharedMemorySize, smU);
    cudaFuncSetAttribute((const void*)cell_mm<66, false>, cudaFuncAttributeMaxDynamicSharedMemorySize, smU);

    cudaMemsetAsync(ph,  0, (size_t)NN * 64 * 64 * sizeof(float));
    cudaMemsetAsync(pgo, 0, (size_t)NN * 64 * sizeof(float));
    cudaMemsetAsync(p1h, 0, (size_t)NN * LD * sizeof(__nv_bfloat16));
    cudaMemsetAsync(p1l, 0, (size_t)NN * LD * sizeof(__nv_bfloat16));
    cudaMemsetAsync(p2h, 0, (size_t)NN * LD * sizeof(__nv_bfloat16));
    cudaMemsetAsync(p2l, 0, (size_t)NN * LD * sizeof(__nv_bfloat16));

    build_support_kernel<<<NN, 256>>>(emb, pM);
    gemmA2<<<dim3(8, 8), 256>>>(pM, pM + (size_t)NN * NN);
    convert_M<<<2 * NN * NN / 256, 256>>>(pM, pMh, pMl);
    prep_W<<<128, 64>>>(egW, 195, 128, pWgE);
    prep_W<<<128, 64>>>(dgW, 198, 128, pWgD);
    prep_W<<<64, 64>>>(euW, 195, 64, pWuE);
    prep_W<<<64, 64>>>(duW, 198, 64, pWuD);

    dim3 gg(33, 16);
    for (int t = 0; t < TT; t++) {
        inject_enc<<<NN, 64>>>(x, t, p1h, p1l, p2h, p2l);
        hmma_gemm<<<gg, 256, smHM>>>(pMh, pMl, p1h, p1l, pY1h, pY1l, pY2h, pY2l);
        cell_mm<65, true><<<NN, 256, smG>>>(p1h, p1l, pY1h, pY1l, pY2h, pY2l,
                                            pWgE, egb, ph, pr, p2h, p2l, nullptr, 0);
        hmma_gemm<<<gg, 256, smHM>>>(pMh, pMl, p2h, p2l, pY1h, pY1l, pY2h, pY2l);
        int offn = (t == TT - 1) ? 2 : 1;
        cell_mm<65, false><<<NN, 256, smU>>>(p2h, p2l, pY1h, pY1l, pY2h, pY2l,
                                             pWuE, eub, ph, pr, p1h, p1l, ph, offn);
    }
    for (int t = 0; t < TT; t++) {
        inject_dec<<<NN, 64>>>(ycov, t, pgo, p1h, p1l, p2h, p2l);
        hmma_gemm<<<gg, 256, smHM>>>(pMh, pMl, p1h, p1l, pY1h, pY1l, pY2h, pY2l);
        cell_mm<66, true><<<NN, 256, smG>>>(p1h, p1l, pY1h, pY1l, pY2h, pY2l,
                                            pWgD, dgb, ph, pr, p2h, p2l, nullptr, 0);
        hmma_gemm<<<gg, 256, smHM>>>(pMh, pMl, p2h, p2l, pY1h, pY1l, pY2h, pY2l);
        cell_mm<66, false><<<NN, 256, smU>>>(p2h, p2l, pY1h, pY1l, pY2h, pY2l,
                                             pWuD, dub, ph, pr, p1h, p1l, ph, 2);
        proj_kernel<<<NN, 64>>>(ph, pW, pb, pgo, out, t);
    }
}

// round 12
// speedup vs baseline: 2.1358x; 1.3983x over previous
#include <cuda_runtime.h>
#include <cuda_fp16.h>
#include <math.h>
#include <stdint.h>

#define NN 1024
#define TT 12
#define LD 4352   // padded cols; GEMM covers 33*128 = 4224

// ---------------- scratch ----------------
__device__ float g_M [2 * NN * NN];
__device__ __align__(256) __half g_Mh[2 * NN * NN];   // fp16 hi of [A ; 2*A2]
__device__ __align__(256) __half g_Ml[2 * NN * NN];   // fp16 lo
__device__ __align__(256) __half g_c1[NN * LD];       // cat1 fp16, c-major [n][c*64+b]
__device__ __align__(256) __half g_c2[NN * LD];
__device__ __align__(256) __half g_Y1[NN * LD];
__device__ __align__(256) __half g_Y2[NN * LD];
__device__ float g_h [NN * 64 * 64];                  // [n][f*64+b]
__device__ float g_r [NN * 64 * 64];
__device__ float g_go[NN * 64];
// W images: [h|l], each [Fall][216] fp16
__device__ __align__(256) __half g_WgE[2 * 128 * 216];
__device__ __align__(256) __half g_WgD[2 * 128 * 216];
__device__ __align__(256) __half g_WuE[2 * 64 * 216];
__device__ __align__(256) __half g_WuD[2 * 64 * 216];

// ---------------- helpers ----------------
__device__ __forceinline__ uint32_t smem_u32(const void* p) {
    uint32_t a;
    asm("{ .reg .u64 t; cvta.to.shared.u64 t, %1; cvt.u32.u64 %0, t; }" : "=r"(a) : "l"(p));
    return a;
}
__device__ __forceinline__ void cpa16(uint32_t dst, const void* src) {
    asm volatile("cp.async.cg.shared.global [%0], [%1], 16;" :: "r"(dst), "l"(src));
}
__device__ __forceinline__ void ldsm4(uint32_t* r, uint32_t a) {
    asm volatile("ldmatrix.sync.aligned.m8n8.x4.shared.b16 {%0,%1,%2,%3}, [%4];"
        : "=r"(r[0]), "=r"(r[1]), "=r"(r[2]), "=r"(r[3]) : "r"(a));
}
__device__ __forceinline__ void ldsm4t(uint32_t* r, uint32_t a) {
    asm volatile("ldmatrix.sync.aligned.m8n8.x4.trans.shared.b16 {%0,%1,%2,%3}, [%4];"
        : "=r"(r[0]), "=r"(r[1]), "=r"(r[2]), "=r"(r[3]) : "r"(a));
}
__device__ __forceinline__ void mma_f16(float* d, const uint32_t* a, uint32_t b0, uint32_t b1) {
    asm volatile("mma.sync.aligned.m16n8k16.row.col.f32.f16.f16.f32 "
        "{%0,%1,%2,%3},{%4,%5,%6,%7},{%8,%9},{%0,%1,%2,%3};"
        : "+f"(d[0]), "+f"(d[1]), "+f"(d[2]), "+f"(d[3])
        : "r"(a[0]), "r"(a[1]), "r"(a[2]), "r"(a[3]), "r"(b0), "r"(b1));
}
__device__ __forceinline__ void hsplit(float v, __half& h16, __half& l16) {
    h16 = __float2half(v);
    l16 = __float2half(v - __half2float(h16));
}
__device__ __forceinline__ void st2h(__half* H, size_t idx, float a, float b) {
    __half2 v;
    v.x = __float2half(a);
    v.y = __float2half(b);
    *reinterpret_cast<__half2*>(H + idx) = v;
}
__device__ __forceinline__ float2 rd2h(const __half* H, size_t idx) {
    __half2 v = *reinterpret_cast<const __half2*>(H + idx);
    return make_float2(__half2float(v.x), __half2float(v.y));
}
__device__ __forceinline__ uint32_t swA(uint32_t off) { return off ^ ((off >> 3) & 0x70); }
__device__ __forceinline__ uint32_t swB(uint32_t off) { return off ^ (((off >> 8) & 7) << 4); }

// ---------------- support: A = softmax(relu(E E^T), rows) ----------------
__global__ void build_support_kernel(const float* __restrict__ emb, float* __restrict__ A) {
    __shared__ float se[NN * 8];
    __shared__ float row[NN];
    __shared__ float wred[8];
    __shared__ float red;
    int n = blockIdx.x, tid = threadIdx.x;
    for (int i = tid; i < NN * 8; i += 256) se[i] = emb[i];
    __syncthreads();
    float e[8];
    #pragma unroll
    for (int j = 0; j < 8; j++) e[j] = se[n * 8 + j];
    float mx = 0.f;
    for (int m = tid; m < NN; m += 256) {
        const float* em = &se[m * 8];
        float s = 0.f;
        #pragma unroll
        for (int j = 0; j < 8; j++) s += e[j] * em[j];
        s = fmaxf(s, 0.f);
        row[m] = s;
        mx = fmaxf(mx, s);
    }
    #pragma unroll
    for (int o = 16; o; o >>= 1) mx = fmaxf(mx, __shfl_xor_sync(0xffffffffu, mx, o));
    if ((tid & 31) == 0) wred[tid >> 5] = mx;
    __syncthreads();
    if (tid == 0) { float v = wred[0]; for (int w = 1; w < 8; w++) v = fmaxf(v, wred[w]); red = v; }
    __syncthreads();
    float bmax = red, sum = 0.f;
    for (int m = tid; m < NN; m += 256) { float v = expf(row[m] - bmax); row[m] = v; sum += v; }
    #pragma unroll
    for (int o = 16; o; o >>= 1) sum += __shfl_xor_sync(0xffffffffu, sum, o);
    if ((tid & 31) == 0) wred[tid >> 5] = sum;
    __syncthreads();
    if (tid == 0) { float v = 0.f; for (int w = 0; w < 8; w++) v += wred[w]; red = v; }
    __syncthreads();
    float inv = 1.f / red;
    for (int m = tid; m < NN; m += 256) A[n * NN + m] = row[m] * inv;
}

// ---------------- A2 = A @ A ----------------
__global__ void __launch_bounds__(256, 2) gemmA2(const float* __restrict__ A, float* __restrict__ A2) {
    __shared__ __align__(16) float As[2][8][132];
    __shared__ __align__(16) float Bs[2][8][128];
    int tid = threadIdx.x;
    int row0 = blockIdx.y * 128, col0 = blockIdx.x * 128;
    int arow = tid >> 1, acol4 = (tid & 1) << 2;
    int brow = tid >> 5, bcol4 = (tid & 31) << 2;
    int tx = tid & 15, ty = tid >> 4;
    const float* Ap = A + (size_t)(row0 + arow) * NN + acol4;
    const float* Xp = A + (size_t)brow * NN + col0 + bcol4;
    float acc[8][8];
    #pragma unroll
    for (int i = 0; i < 8; i++)
        #pragma unroll
        for (int j = 0; j < 8; j++) acc[i][j] = 0.f;
    float4 av = *(const float4*)Ap;
    float4 bv = *(const float4*)Xp;
    int buf = 0;
    As[0][acol4 + 0][arow] = av.x; As[0][acol4 + 1][arow] = av.y;
    As[0][acol4 + 2][arow] = av.z; As[0][acol4 + 3][arow] = av.w;
    *(float4*)&Bs[0][brow][bcol4] = bv;
    __syncthreads();
    for (int kt = 1; kt < 128; kt++) {
        av = *(const float4*)(Ap + kt * 8);
        bv = *(const float4*)(Xp + (size_t)(kt * 8) * NN);
        #pragma unroll
        for (int kk = 0; kk < 8; kk++) {
            float4 a0 = *(const float4*)&As[buf][kk][ty * 4];
            float4 a1 = *(const float4*)&As[buf][kk][64 + ty * 4];
            float4 b0 = *(const float4*)&Bs[buf][kk][tx * 4];
            float4 b1 = *(const float4*)&Bs[buf][kk][64 + tx * 4];
            float a[8] = {a0.x,a0.y,a0.z,a0.w,a1.x,a1.y,a1.z,a1.w};
            float b[8] = {b0.x,b0.y,b0.z,b0.w,b1.x,b1.y,b1.z,b1.w};
            #pragma unroll
            for (int i = 0; i < 8; i++)
                #pragma unroll
                for (int j = 0; j < 8; j++) acc[i][j] = fmaf(a[i], b[j], acc[i][j]);
        }
        buf ^= 1;
        As[buf][acol4 + 0][arow] = av.x; As[buf][acol4 + 1][arow] = av.y;
        As[buf][acol4 + 2][arow] = av.z; As[buf][acol4 + 3][arow] = av.w;
        *(float4*)&Bs[buf][brow][bcol4] = bv;
        __syncthreads();
    }
    #pragma unroll
    for (int kk = 0; kk < 8; kk++) {
        float4 a0 = *(const float4*)&As[buf][kk][ty * 4];
        float4 a1 = *(const float4*)&As[buf][kk][64 + ty * 4];
        float4 b0 = *(const float4*)&Bs[buf][kk][tx * 4];
        float4 b1 = *(const float4*)&Bs[buf][kk][64 + tx * 4];
        float a[8] = {a0.x,a0.y,a0.z,a0.w,a1.x,a1.y,a1.z,a1.w};
        float b[8] = {b0.x,b0.y,b0.z,b0.w,b1.x,b1.y,b1.z,b1.w};
        #pragma unroll
        for (int i = 0; i < 8; i++)
            #pragma unroll
            for (int j = 0; j < 8; j++) acc[i][j] = fmaf(a[i], b[j], acc[i][j]);
    }
    #pragma unroll
    for (int i = 0; i < 8; i++) {
        int grow = row0 + ((i < 4) ? (ty * 4 + i) : (64 + ty * 4 + i - 4));
        float* yp = A2 + (size_t)grow * NN;
        *(float4*)(yp + col0 + tx * 4)       = make_float4(acc[i][0], acc[i][1], acc[i][2], acc[i][3]);
        *(float4*)(yp + col0 + 64 + tx * 4)  = make_float4(acc[i][4], acc[i][5], acc[i][6], acc[i][7]);
    }
}

// ---------------- M -> fp16 hi/lo (fold 2x into bottom half) ----------------
__global__ void convert_M(const float* __restrict__ M,
                          __half* __restrict__ Mh, __half* __restrict__ Ml) {
    int i = blockIdx.x * 256 + threadIdx.x;
    float v = M[i];
    if (i >= NN * NN) v *= 2.f;
    __half h, l;
    hsplit(v, h, l);
    Mh[i] = h;
    Ml[i] = l;
}

// ---------------- W^T image prep: fp16 hi/lo ----------------
__global__ void prep_W(const float* __restrict__ W, int K3, int Fall,
                       __half* __restrict__ img) {
    int f = blockIdx.x;
    __half* imgH = img;
    __half* imgL = img + Fall * 216;
    for (int k = threadIdx.x; k < 216; k += 64) {
        float v = (k < K3) ? W[k * Fall + f] : 0.f;
        __half h, l;
        hsplit(v, h, l);
        imgH[f * 216 + k] = h;
        imgL[f * 216 + k] = l;
    }
}

// ---------------- HMMA split-fp16 diffusion GEMM (2-term: Ah*B + Al*B) ----------------
// stage (48KB): Ah 16K | Al 16K | B 16K ; 2-stage, KC=64
#define KC 64
#define STG 49152
__global__ void __launch_bounds__(256, 1) hmma_gemm(
    const __half* __restrict__ Mh, const __half* __restrict__ Ml,
    const __half* __restrict__ X,
    __half* __restrict__ Y1, __half* __restrict__ Y2)
{
    extern __shared__ __align__(1024) char smem[];
    uint32_t sb = smem_u32(smem);
    int tid = threadIdx.x;
    int lane = tid & 31, wid = tid >> 5;
    int wm = wid >> 1, wn = wid & 1;
    int row0 = blockIdx.y * 128;
    int col0 = blockIdx.x * 128;

    float acc[2][8][4];
    #pragma unroll
    for (int mt = 0; mt < 2; mt++)
        #pragma unroll
        for (int nt = 0; nt < 8; nt++)
            #pragma unroll
            for (int j = 0; j < 4; j++) acc[mt][nt][j] = 0.f;

    auto load_stage = [&](int it) {
        uint32_t base = sb + (it & 1) * STG;
        int k0 = it * KC;
        #pragma unroll
        for (int i = tid; i < 1024; i += 256) {
            int r = i >> 3, c = i & 7;
            uint32_t sw = swA((uint32_t)(r * 128 + c * 16));
            size_t g = (size_t)(row0 + r) * NN + k0 + c * 8;
            cpa16(base + sw, Mh + g);
            cpa16(base + 16384 + sw, Ml + g);
        }
        #pragma unroll
        for (int i = tid; i < 1024; i += 256) {
            int k = i >> 4, c = i & 15;
            uint32_t sw = swB((uint32_t)(k * 256 + c * 16));
            cpa16(base + 32768 + sw, X + (size_t)(k0 + k) * LD + col0 + c * 8);
        }
        asm volatile("cp.async.commit_group;" ::: "memory");
    };

    load_stage(0);
    load_stage(1);

    int a_r = wm * 32 + (lane & 15);
    int a_ch = (lane >> 4);
    int b_k = (lane & 7) + ((lane >> 3) & 1) * 8;
    int b_n8 = ((lane >> 4) & 1) * 8;

    #pragma unroll 1
    for (int it = 0; it < 16; it++) {
        int buf = it & 1;
        if (it < 15) asm volatile("cp.async.wait_group 1;" ::: "memory");
        else         asm volatile("cp.async.wait_group 0;" ::: "memory");
        __syncthreads();
        uint32_t base = sb + buf * STG;
        #pragma unroll
        for (int kk = 0; kk < 4; kk++) {
            uint32_t aH[2][4], aL[2][4];
            #pragma unroll
            for (int mt = 0; mt < 2; mt++) {
                uint32_t off = swA((uint32_t)((a_r + mt * 16) * 128 + (kk * 2 + a_ch) * 16));
                ldsm4(aH[mt], base + off);
                ldsm4(aL[mt], base + 16384 + off);
            }
            uint32_t bF[4][4];
            #pragma unroll
            for (int p = 0; p < 4; p++) {
                int nb = wn * 64 + p * 16 + b_n8;
                uint32_t off = swB((uint32_t)((kk * 16 + b_k) * 256 + nb * 2));
                ldsm4t(bF[p], base + 32768 + off);
            }
            #pragma unroll
            for (int mt = 0; mt < 2; mt++) {
                #pragma unroll
                for (int p = 0; p < 4; p++) {
                    mma_f16(acc[mt][2 * p],     aH[mt], bF[p][0], bF[p][1]);
                    mma_f16(acc[mt][2 * p],     aL[mt], bF[p][0], bF[p][1]);
                    mma_f16(acc[mt][2 * p + 1], aH[mt], bF[p][2], bF[p][3]);
                    mma_f16(acc[mt][2 * p + 1], aL[mt], bF[p][2], bF[p][3]);
                }
            }
        }
        __syncthreads();
        if (it + 2 < 16) load_stage(it + 2);
    }

    // epilogue
    int r_lo = lane >> 2;
    int c_lo = (lane & 3) * 2;
    if (row0 < 1024) {
        #pragma unroll
        for (int mt = 0; mt < 2; mt++) {
            int r = row0 + wm * 32 + mt * 16 + r_lo;
            #pragma unroll
            for (int nt = 0; nt < 8; nt++) {
                int c = col0 + wn * 64 + nt * 8 + c_lo;
                st2h(Y1, (size_t)r * LD + c,       acc[mt][nt][0], acc[mt][nt][1]);
                st2h(Y1, (size_t)(r + 8) * LD + c, acc[mt][nt][2], acc[mt][nt][3]);
            }
        }
    } else {
        #pragma unroll
        for (int mt = 0; mt < 2; mt++) {
            int r = row0 - 1024 + wm * 32 + mt * 16 + r_lo;
            #pragma unroll
            for (int nt = 0; nt < 8; nt++) {
                int c = col0 + wn * 64 + nt * 8 + c_lo;
                float2 x0 = rd2h(X, (size_t)r * LD + c);
                float2 x1 = rd2h(X, (size_t)(r + 8) * LD + c);
                st2h(Y2, (size_t)r * LD + c,       acc[mt][nt][0] - x0.x, acc[mt][nt][1] - x0.y);
                st2h(Y2, (size_t)(r + 8) * LD + c, acc[mt][nt][2] - x1.x, acc[mt][nt][3] - x1.y);
            }
        }
    }
}

// ---------------- HMMA weight matmul + GRU epilogue (one node per CTA, 2-term) ----------------
template <int C, bool GATE>
__global__ void __launch_bounds__(256) cell_mm(
    const __half* __restrict__ F0, const __half* __restrict__ F1, const __half* __restrict__ F2,
    const __half* __restrict__ Wimg, const float* __restrict__ bias,
    const float* __restrict__ hin, float* __restrict__ rbuf,
    __half* __restrict__ outC, float* __restrict__ hout, int offn)
{
    constexpr int Fall = GATE ? 128 : 64;
    constexpr int NP   = GATE ? 2 : 1;
    constexpr int BIMG = 208 * 128;     // feats image bytes (single fp16)
    constexpr int WIMG = Fall * 432;
    constexpr int OFF  = C - 64;
    extern __shared__ __align__(16) char sm[];
    char* Bm = sm;
    char* Wh = sm + BIMG;
    char* Wl = Wh + WIMG;
    float* bs = (float*)(Wl + WIMG);
    int n = blockIdx.x, tid = threadIdx.x;
    int lane = tid & 31, wid = tid >> 5;
    uint32_t bB = smem_u32(Bm);
    uint32_t bWh = smem_u32(Wh), bWl = smem_u32(Wl);

    const __half* src[3] = {F0 + (size_t)n * LD, F1 + (size_t)n * LD, F2 + (size_t)n * LD};

    for (int i = tid; i < 1664; i += 256) {
        int k = i >> 3, ch = i & 7;
        uint32_t sw = swA((uint32_t)(k * 128 + ch * 16));
        if (k < 3 * C) {
            int kk = k / C, c = k - kk * C;
            cpa16(bB + sw, src[kk] + c * 64 + ch * 8);
        } else {
            *(uint4*)(Bm + sw) = make_uint4(0, 0, 0, 0);
        }
    }
    for (int i = tid; i < Fall * 27; i += 256) {
        int f = i / 27, ch = i - f * 27;
        cpa16(bWh + f * 432 + ch * 16, Wimg + f * 216 + ch * 8);
        cpa16(bWl + f * 432 + ch * 16, Wimg + Fall * 216 + f * 216 + ch * 8);
    }
    if (tid < Fall) bs[tid] = bias[tid];
    asm volatile("cp.async.commit_group;" ::: "memory");
    asm volatile("cp.async.wait_group 0;" ::: "memory");
    __syncthreads();

    int wm = GATE ? (wid & 3) : (wid & 1);
    int wn = GATE ? (wid >> 2) : (wid >> 1);
    int f0 = wm * 32;
    int nb0 = wn * (GATE ? 32 : 16);
    int bk  = (lane & 7) + ((lane >> 3) & 1) * 8;
    int bn8 = ((lane >> 4) & 1) * 8;

    float acc[2][2 * NP][4];
    #pragma unroll
    for (int mt = 0; mt < 2; mt++)
        #pragma unroll
        for (int nt = 0; nt < 2 * NP; nt++)
            #pragma unroll
            for (int j = 0; j < 4; j++) acc[mt][nt][j] = 0.f;

    #pragma unroll 1
    for (int kt = 0; kt < 13; kt++) {
        uint32_t aH[2][4], aL[2][4];
        #pragma unroll
        for (int mt = 0; mt < 2; mt++) {
            uint32_t ao = (uint32_t)((f0 + mt * 16 + (lane & 15)) * 432 + kt * 32 + (lane >> 4) * 16);
            ldsm4(aH[mt], bWh + ao);
            ldsm4(aL[mt], bWl + ao);
        }
        #pragma unroll
        for (int p = 0; p < NP; p++) {
            uint32_t bo = swA((uint32_t)((kt * 16 + bk) * 128 + (nb0 + p * 16 + bn8) * 2));
            uint32_t bF[4];
            ldsm4t(bF, bB + bo);
            #pragma unroll
            for (int mt = 0; mt < 2; mt++) {
                mma_f16(acc[mt][2 * p],     aH[mt], bF[0], bF[1]);
                mma_f16(acc[mt][2 * p],     aL[mt], bF[0], bF[1]);
                mma_f16(acc[mt][2 * p + 1], aH[mt], bF[2], bF[3]);
                mma_f16(acc[mt][2 * p + 1], aL[mt], bF[2], bF[3]);
            }
        }
    }

    // epilogue
    int r_lo = lane >> 2, c_lo = (lane & 3) * 2;
    size_t nLD = (size_t)n * LD;
    size_t nH  = (size_t)n * 4096;
    #pragma unroll
    for (int mt = 0; mt < 2; mt++) {
        int row = f0 + mt * 16 + r_lo;
        #pragma unroll
        for (int nt = 0; nt < 2 * NP; nt++) {
            int col = nb0 + nt * 8 + c_lo;
            float v0 = acc[mt][nt][0] + bs[row];
            float v1 = acc[mt][nt][1] + bs[row];
            float v2 = acc[mt][nt][2] + bs[row + 8];
            float v3 = acc[mt][nt][3] + bs[row + 8];
            if (GATE) {
                if (row < 64) {
                    #pragma unroll
                    for (int q = 0; q < 2; q++) {
                        int f = row + q * 8;
                        float z0 = 1.f / (1.f + expf(-(q ? v2 : v0)));
                        float z1 = 1.f / (1.f + expf(-(q ? v3 : v1)));
                        float2 hv = *(const float2*)(hin + nH + (size_t)f * 64 + col);
                        st2h(outC, nLD + (size_t)(OFF + f) * 64 + col, z0 * hv.x, z1 * hv.y);
                    }
                } else {
                    #pragma unroll
                    for (int q = 0; q < 2; q++) {
                        int f = row - 64 + q * 8;
                        float r0 = 1.f / (1.f + expf(-(q ? v2 : v0)));
                        float r1 = 1.f / (1.f + expf(-(q ? v3 : v1)));
                        *(float2*)(rbuf + nH + (size_t)f * 64 + col) = make_float2(r0, r1);
                    }
                }
            } else {
                #pragma unroll
                for (int q = 0; q < 2; q++) {
                    int f = row + q * 8;
                    float hc0 = tanhf(q ? v2 : v0);
                    float hc1 = tanhf(q ? v3 : v1);
                    float2 rv = *(const float2*)(rbuf + nH + (size_t)f * 64 + col);
                    float2 hv = *(const float2*)(hin  + nH + (size_t)f * 64 + col);
                    float hn0 = rv.x * hv.x + (1.f - rv.x) * hc0;
                    float hn1 = rv.y * hv.y + (1.f - rv.y) * hc1;
                    *(float2*)(hout + nH + (size_t)f * 64 + col) = make_float2(hn0, hn1);
                    st2h(outC, nLD + (size_t)(offn + f) * 64 + col, hn0, hn1);
                }
            }
        }
    }
}

// ---------------- per-step column injection ----------------
__global__ void inject_enc(const float* __restrict__ x, int t,
                           __half* __restrict__ c1, __half* __restrict__ c2) {
    int n = blockIdx.x, b = threadIdx.x;
    __half v = __float2half(x[(size_t)(b * TT + t) * NN + n]);
    size_t pos = (size_t)n * LD + b;
    c1[pos] = v;
    c2[pos] = v;
}
__global__ void inject_dec(const float* __restrict__ yc, int t, const float* __restrict__ go,
                           __half* __restrict__ c1, __half* __restrict__ c2) {
    int n = blockIdx.x, b = threadIdx.x;
    __half v0 = __float2half(go[n * 64 + b]);
    __half v1 = __float2half(yc[(size_t)(b * TT + t) * NN + n]);
    size_t pos = (size_t)n * LD + b;
    c1[pos] = v0; c2[pos] = v0;
    c1[pos + 64] = v1; c2[pos + 64] = v1;
}

// ---------------- projection ----------------
__global__ void proj_kernel(const float* __restrict__ h, const float* __restrict__ pW,
                            const float* __restrict__ pb, float* __restrict__ go,
                            float* __restrict__ out, int t) {
    __shared__ float w[64];
    int n = blockIdx.x, b = threadIdx.x;
    w[b] = pW[b];
    __syncthreads();
    size_t nH = (size_t)n * 4096;
    float s = 0.f;
    #pragma unroll
    for (int f = 0; f < 64; f++) s = fmaf(h[nH + f * 64 + b], w[f], s);
    float v = s + pb[0];
    go[n * 64 + b] = v;
    out[(size_t)(b * TT + t) * NN + n] = v;
}

// ---------------- orchestration ----------------
extern "C" void kernel_launch(void* const* d_in, const int* in_sizes, int n_in,
                              void* d_out, int out_size) {
    const float* x    = (const float*)d_in[0];
    const float* ycov = (const float*)d_in[1];
    const float* emb  = (const float*)d_in[2];
    const float* egW  = (const float*)d_in[3];
    const float* egb  = (const float*)d_in[4];
    const float* euW  = (const float*)d_in[5];
    const float* eub  = (const float*)d_in[6];
    const float* dgW  = (const float*)d_in[7];
    const float* dgb  = (const float*)d_in[8];
    const float* duW  = (const float*)d_in[9];
    const float* dub  = (const float*)d_in[10];
    const float* pW   = (const float*)d_in[11];
    const float* pb   = (const float*)d_in[12];
    float* out = (float*)d_out;

    float *pM, *ph, *pr, *pgo;
    __half *pMh, *pMl, *pc1, *pc2, *pY1, *pY2, *pWgE, *pWgD, *pWuE, *pWuD;
    cudaGetSymbolAddress((void**)&pM,   g_M);
    cudaGetSymbolAddress((void**)&pMh,  g_Mh);
    cudaGetSymbolAddress((void**)&pMl,  g_Ml);
    cudaGetSymbolAddress((void**)&pc1,  g_c1);
    cudaGetSymbolAddress((void**)&pc2,  g_c2);
    cudaGetSymbolAddress((void**)&pY1,  g_Y1);
    cudaGetSymbolAddress((void**)&pY2,  g_Y2);
    cudaGetSymbolAddress((void**)&ph,   g_h);
    cudaGetSymbolAddress((void**)&pr,   g_r);
    cudaGetSymbolAddress((void**)&pgo,  g_go);
    cudaGetSymbolAddress((void**)&pWgE, g_WgE);
    cudaGetSymbolAddress((void**)&pWgD, g_WgD);
    cudaGetSymbolAddress((void**)&pWuE, g_WuE);
    cudaGetSymbolAddress((void**)&pWuD, g_WuD);

    const int smHM = 2 * STG;                               // 98304
    const int smG  = 208 * 128 + 2 * (128 * 432) + 512;     // 137728
    const int smU  = 208 * 128 + 2 * (64 * 432) + 256;      // 82176
    cudaFuncSetAttribute((const void*)hmma_gemm,          cudaFuncAttributeMaxDynamicSharedMemorySize, smHM);
    cudaFuncSetAttribute((const void*)cell_mm<65, true>,  cudaFuncAttributeMaxDynamicSharedMemorySize, smG);
    cudaFuncSetAttribute((const void*)cell_mm<66, true>,  cudaFuncAttributeMaxDynamicSharedMemorySize, smG);
    cudaFuncSetAttribute((const void*)cell_mm<65, false>, cudaFuncAttributeMaxDynamicSharedMemorySize, smU);
    cudaFuncSetAttribute((const void*)cell_mm<66, false>, cudaFuncAttributeMaxDynamicSharedMemorySize, smU);

    cudaMemsetAsync(ph,  0, (size_t)NN * 64 * 64 * sizeof(float));
    cudaMemsetAsync(pgo, 0, (size_t)NN * 64 * sizeof(float));
    cudaMemsetAsync(pc1, 0, (size_t)NN * LD * sizeof(__half));
    cudaMemsetAsync(pc2, 0, (size_t)NN * LD * sizeof(__half));

    build_support_kernel<<<NN, 256>>>(emb, pM);
    gemmA2<<<dim3(8, 8), 256>>>(pM, pM + (size_t)NN * NN);
    convert_M<<<2 * NN * NN / 256, 256>>>(pM, pMh, pMl);
    prep_W<<<128, 64>>>(egW, 195, 128, pWgE);
    prep_W<<<128, 64>>>(dgW, 198, 128, pWgD);
    prep_W<<<64, 64>>>(euW, 195, 64, pWuE);
    prep_W<<<64, 64>>>(duW, 198, 64, pWuD);

    dim3 gg(33, 16);
    for (int t = 0; t < TT; t++) {
        inject_enc<<<NN, 64>>>(x, t, pc1, pc2);
        hmma_gemm<<<gg, 256, smHM>>>(pMh, pMl, pc1, pY1, pY2);
        cell_mm<65, true><<<NN, 256, smG>>>(pc1, pY1, pY2, pWgE, egb, ph, pr, pc2, nullptr, 0);
        hmma_gemm<<<gg, 256, smHM>>>(pMh, pMl, pc2, pY1, pY2);
        int offn = (t == TT - 1) ? 2 : 1;
        cell_mm<65, false><<<NN, 256, smU>>>(pc2, pY1, pY2, pWuE, eub, ph, pr, pc1, ph, offn);
    }
    for (int t = 0; t < TT; t++) {
        inject_dec<<<NN, 64>>>(ycov, t, pgo, pc1, pc2);
        hmma_gemm<<<gg, 256, smHM>>>(pMh, pMl, pc1, pY1, pY2);
        cell_mm<66, true><<<NN, 256, smG>>>(pc1, pY1, pY2, pWgD, dgb, ph, pr, pc2, nullptr, 0);
        hmma_gemm<<<gg, 256, smHM>>>(pMh, pMl, pc2, pY1, pY2);
        cell_mm<66, false><<<NN, 256, smU>>>(pc2, pY1, pY2, pWuD, dub, ph, pr, pc1, ph, 2);
        proj_kernel<<<NN, 64>>>(ph, pW, pb, pgo, out, t);
    }
}

// round 13
// speedup vs baseline: 3.2097x; 1.5028x over previous
#include <cuda_runtime.h>
#include <cuda_fp16.h>
#include <math.h>
#include <stdint.h>

#define NN 1024
#define TT 12
#define LD 4352   // padded cols; GEMM covers 33*128 = 4224

// ---------------- scratch ----------------
__device__ float g_M [2 * NN * NN];
__device__ __align__(256) __half g_Mh[2 * NN * NN];   // fp16 of [A ; 2*A2]
__device__ __align__(256) __half g_c1[NN * LD];       // cat1 fp16, c-major [n][c*64+b]
__device__ __align__(256) __half g_c2[NN * LD];
__device__ __align__(256) __half g_Y1[NN * LD];
__device__ __align__(256) __half g_Y2[NN * LD];
__device__ float g_h [NN * 64 * 64];                  // [n][f*64+b]
__device__ float g_r [NN * 64 * 64];
__device__ float g_go[NN * 64];
// W images: [Fall][216] fp16 (k padded to 216, zero beyond K3)
__device__ __align__(256) __half g_WgE[128 * 216];
__device__ __align__(256) __half g_WgD[128 * 216];
__device__ __align__(256) __half g_WuE[64 * 216];
__device__ __align__(256) __half g_WuD[64 * 216];

// ---------------- helpers ----------------
__device__ __forceinline__ uint32_t smem_u32(const void* p) {
    uint32_t a;
    asm("{ .reg .u64 t; cvta.to.shared.u64 t, %1; cvt.u32.u64 %0, t; }" : "=r"(a) : "l"(p));
    return a;
}
__device__ __forceinline__ void cpa16(uint32_t dst, const void* src) {
    asm volatile("cp.async.cg.shared.global [%0], [%1], 16;" :: "r"(dst), "l"(src));
}
__device__ __forceinline__ void ldsm4(uint32_t* r, uint32_t a) {
    asm volatile("ldmatrix.sync.aligned.m8n8.x4.shared.b16 {%0,%1,%2,%3}, [%4];"
        : "=r"(r[0]), "=r"(r[1]), "=r"(r[2]), "=r"(r[3]) : "r"(a));
}
__device__ __forceinline__ void ldsm4t(uint32_t* r, uint32_t a) {
    asm volatile("ldmatrix.sync.aligned.m8n8.x4.trans.shared.b16 {%0,%1,%2,%3}, [%4];"
        : "=r"(r[0]), "=r"(r[1]), "=r"(r[2]), "=r"(r[3]) : "r"(a));
}
__device__ __forceinline__ void mma_f16(float* d, const uint32_t* a, uint32_t b0, uint32_t b1) {
    asm volatile("mma.sync.aligned.m16n8k16.row.col.f32.f16.f16.f32 "
        "{%0,%1,%2,%3},{%4,%5,%6,%7},{%8,%9},{%0,%1,%2,%3};"
        : "+f"(d[0]), "+f"(d[1]), "+f"(d[2]), "+f"(d[3])
        : "r"(a[0]), "r"(a[1]), "r"(a[2]), "r"(a[3]), "r"(b0), "r"(b1));
}
__device__ __forceinline__ void st2h(__half* H, size_t idx, float a, float b) {
    __half2 v;
    v.x = __float2half(a);
    v.y = __float2half(b);
    *reinterpret_cast<__half2*>(H + idx) = v;
}
__device__ __forceinline__ float2 rd2h(const __half* H, size_t idx) {
    __half2 v = *reinterpret_cast<const __half2*>(H + idx);
    return make_float2(__half2float(v.x), __half2float(v.y));
}
__device__ __forceinline__ uint32_t swA(uint32_t off) { return off ^ ((off >> 3) & 0x70); }
__device__ __forceinline__ uint32_t swB(uint32_t off) { return off ^ (((off >> 8) & 7) << 4); }

// ---------------- support: A = softmax(relu(E E^T), rows) ----------------
__global__ void build_support_kernel(const float* __restrict__ emb, float* __restrict__ A) {
    __shared__ float se[NN * 8];
    __shared__ float row[NN];
    __shared__ float wred[8];
    __shared__ float red;
    int n = blockIdx.x, tid = threadIdx.x;
    for (int i = tid; i < NN * 8; i += 256) se[i] = emb[i];
    __syncthreads();
    float e[8];
    #pragma unroll
    for (int j = 0; j < 8; j++) e[j] = se[n * 8 + j];
    float mx = 0.f;
    for (int m = tid; m < NN; m += 256) {
        const float* em = &se[m * 8];
        float s = 0.f;
        #pragma unroll
        for (int j = 0; j < 8; j++) s += e[j] * em[j];
        s = fmaxf(s, 0.f);
        row[m] = s;
        mx = fmaxf(mx, s);
    }
    #pragma unroll
    for (int o = 16; o; o >>= 1) mx = fmaxf(mx, __shfl_xor_sync(0xffffffffu, mx, o));
    if ((tid & 31) == 0) wred[tid >> 5] = mx;
    __syncthreads();
    if (tid == 0) { float v = wred[0]; for (int w = 1; w < 8; w++) v = fmaxf(v, wred[w]); red = v; }
    __syncthreads();
    float bmax = red, sum = 0.f;
    for (int m = tid; m < NN; m += 256) { float v = expf(row[m] - bmax); row[m] = v; sum += v; }
    #pragma unroll
    for (int o = 16; o; o >>= 1) sum += __shfl_xor_sync(0xffffffffu, sum, o);
    if ((tid & 31) == 0) wred[tid >> 5] = sum;
    __syncthreads();
    if (tid == 0) { float v = 0.f; for (int w = 0; w < 8; w++) v += wred[w]; red = v; }
    __syncthreads();
    float inv = 1.f / red;
    for (int m = tid; m < NN; m += 256) A[n * NN + m] = row[m] * inv;
}

// ---------------- A2 = A @ A ----------------
__global__ void __launch_bounds__(256, 2) gemmA2(const float* __restrict__ A, float* __restrict__ A2) {
    __shared__ __align__(16) float As[2][8][132];
    __shared__ __align__(16) float Bs[2][8][128];
    int tid = threadIdx.x;
    int row0 = blockIdx.y * 128, col0 = blockIdx.x * 128;
    int arow = tid >> 1, acol4 = (tid & 1) << 2;
    int brow = tid >> 5, bcol4 = (tid & 31) << 2;
    int tx = tid & 15, ty = tid >> 4;
    const float* Ap = A + (size_t)(row0 + arow) * NN + acol4;
    const float* Xp = A + (size_t)brow * NN + col0 + bcol4;
    float acc[8][8];
    #pragma unroll
    for (int i = 0; i < 8; i++)
        #pragma unroll
        for (int j = 0; j < 8; j++) acc[i][j] = 0.f;
    float4 av = *(const float4*)Ap;
    float4 bv = *(const float4*)Xp;
    int buf = 0;
    As[0][acol4 + 0][arow] = av.x; As[0][acol4 + 1][arow] = av.y;
    As[0][acol4 + 2][arow] = av.z; As[0][acol4 + 3][arow] = av.w;
    *(float4*)&Bs[0][brow][bcol4] = bv;
    __syncthreads();
    for (int kt = 1; kt < 128; kt++) {
        av = *(const float4*)(Ap + kt * 8);
        bv = *(const float4*)(Xp + (size_t)(kt * 8) * NN);
        #pragma unroll
        for (int kk = 0; kk < 8; kk++) {
            float4 a0 = *(const float4*)&As[buf][kk][ty * 4];
            float4 a1 = *(const float4*)&As[buf][kk][64 + ty * 4];
            float4 b0 = *(const float4*)&Bs[buf][kk][tx * 4];
            float4 b1 = *(const float4*)&Bs[buf][kk][64 + tx * 4];
            float a[8] = {a0.x,a0.y,a0.z,a0.w,a1.x,a1.y,a1.z,a1.w};
            float b[8] = {b0.x,b0.y,b0.z,b0.w,b1.x,b1.y,b1.z,b1.w};
            #pragma unroll
            for (int i = 0; i < 8; i++)
                #pragma unroll
                for (int j = 0; j < 8; j++) acc[i][j] = fmaf(a[i], b[j], acc[i][j]);
        }
        buf ^= 1;
        As[buf][acol4 + 0][arow] = av.x; As[buf][acol4 + 1][arow] = av.y;
        As[buf][acol4 + 2][arow] = av.z; As[buf][acol4 + 3][arow] = av.w;
        *(float4*)&Bs[buf][brow][bcol4] = bv;
        __syncthreads();
    }
    #pragma unroll
    for (int kk = 0; kk < 8; kk++) {
        float4 a0 = *(const float4*)&As[buf][kk][ty * 4];
        float4 a1 = *(const float4*)&As[buf][kk][64 + ty * 4];
        float4 b0 = *(const float4*)&Bs[buf][kk][tx * 4];
        float4 b1 = *(const float4*)&Bs[buf][kk][64 + tx * 4];
        float a[8] = {a0.x,a0.y,a0.z,a0.w,a1.x,a1.y,a1.z,a1.w};
        float b[8] = {b0.x,b0.y,b0.z,b0.w,b1.x,b1.y,b1.z,b1.w};
        #pragma unroll
        for (int i = 0; i < 8; i++)
            #pragma unroll
            for (int j = 0; j < 8; j++) acc[i][j] = fmaf(a[i], b[j], acc[i][j]);
    }
    #pragma unroll
    for (int i = 0; i < 8; i++) {
        int grow = row0 + ((i < 4) ? (ty * 4 + i) : (64 + ty * 4 + i - 4));
        float* yp = A2 + (size_t)grow * NN;
        *(float4*)(yp + col0 + tx * 4)       = make_float4(acc[i][0], acc[i][1], acc[i][2], acc[i][3]);
        *(float4*)(yp + col0 + 64 + tx * 4)  = make_float4(acc[i][4], acc[i][5], acc[i][6], acc[i][7]);
    }
}

// ---------------- M -> fp16 (fold 2x into bottom half) ----------------
__global__ void convert_M(const float* __restrict__ M, __half* __restrict__ Mh) {
    int i = blockIdx.x * 256 + threadIdx.x;
    float v = M[i];
    if (i >= NN * NN) v *= 2.f;
    Mh[i] = __float2half(v);
}

// ---------------- W^T image prep: fp16 [Fall][216] ----------------
__global__ void prep_W(const float* __restrict__ W, int K3, int Fall,
                       __half* __restrict__ img) {
    int f = blockIdx.x;
    for (int k = threadIdx.x; k < 216; k += 64) {
        float v = (k < K3) ? W[k * Fall + f] : 0.f;
        img[f * 216 + k] = __float2half(v);
    }
}

// ---------------- fp16 HMMA diffusion GEMM ----------------
// stage (32KB): A 16K | B 16K ; 2-stage, KC=64
#define KC 64
#define STG 32768
__global__ void __launch_bounds__(256, 1) hmma_gemm(
    const __half* __restrict__ Mh, const __half* __restrict__ X,
    __half* __restrict__ Y1, __half* __restrict__ Y2)
{
    extern __shared__ __align__(1024) char smem[];
    uint32_t sb = smem_u32(smem);
    int tid = threadIdx.x;
    int lane = tid & 31, wid = tid >> 5;
    int wm = wid >> 1, wn = wid & 1;
    int row0 = blockIdx.y * 128;
    int col0 = blockIdx.x * 128;

    float acc[2][8][4];
    #pragma unroll
    for (int mt = 0; mt < 2; mt++)
        #pragma unroll
        for (int nt = 0; nt < 8; nt++)
            #pragma unroll
            for (int j = 0; j < 4; j++) acc[mt][nt][j] = 0.f;

    auto load_stage = [&](int it) {
        uint32_t base = sb + (it & 1) * STG;
        int k0 = it * KC;
        #pragma unroll
        for (int i = tid; i < 1024; i += 256) {
            int r = i >> 3, c = i & 7;
            uint32_t sw = swA((uint32_t)(r * 128 + c * 16));
            cpa16(base + sw, Mh + (size_t)(row0 + r) * NN + k0 + c * 8);
        }
        #pragma unroll
        for (int i = tid; i < 1024; i += 256) {
            int k = i >> 4, c = i & 15;
            uint32_t sw = swB((uint32_t)(k * 256 + c * 16));
            cpa16(base + 16384 + sw, X + (size_t)(k0 + k) * LD + col0 + c * 8);
        }
        asm volatile("cp.async.commit_group;" ::: "memory");
    };

    load_stage(0);
    load_stage(1);

    int a_r = wm * 32 + (lane & 15);
    int a_ch = (lane >> 4);
    int b_k = (lane & 7) + ((lane >> 3) & 1) * 8;
    int b_n8 = ((lane >> 4) & 1) * 8;

    #pragma unroll 1
    for (int it = 0; it < 16; it++) {
        int buf = it & 1;
        if (it < 15) asm volatile("cp.async.wait_group 1;" ::: "memory");
        else         asm volatile("cp.async.wait_group 0;" ::: "memory");
        __syncthreads();
        uint32_t base = sb + buf * STG;
        #pragma unroll
        for (int kk = 0; kk < 4; kk++) {
            uint32_t aF[2][4];
            #pragma unroll
            for (int mt = 0; mt < 2; mt++) {
                uint32_t off = swA((uint32_t)((a_r + mt * 16) * 128 + (kk * 2 + a_ch) * 16));
                ldsm4(aF[mt], base + off);
            }
            uint32_t bF[4][4];
            #pragma unroll
            for (int p = 0; p < 4; p++) {
                int nb = wn * 64 + p * 16 + b_n8;
                uint32_t off = swB((uint32_t)((kk * 16 + b_k) * 256 + nb * 2));
                ldsm4t(bF[p], base + 16384 + off);
            }
            #pragma unroll
            for (int mt = 0; mt < 2; mt++) {
                #pragma unroll
                for (int p = 0; p < 4; p++) {
                    mma_f16(acc[mt][2 * p],     aF[mt], bF[p][0], bF[p][1]);
                    mma_f16(acc[mt][2 * p + 1], aF[mt], bF[p][2], bF[p][3]);
                }
            }
        }
        __syncthreads();
        if (it + 2 < 16) load_stage(it + 2);
    }

    // epilogue
    int r_lo = lane >> 2;
    int c_lo = (lane & 3) * 2;
    if (row0 < 1024) {
        #pragma unroll
        for (int mt = 0; mt < 2; mt++) {
            int r = row0 + wm * 32 + mt * 16 + r_lo;
            #pragma unroll
            for (int nt = 0; nt < 8; nt++) {
                int c = col0 + wn * 64 + nt * 8 + c_lo;
                st2h(Y1, (size_t)r * LD + c,       acc[mt][nt][0], acc[mt][nt][1]);
                st2h(Y1, (size_t)(r + 8) * LD + c, acc[mt][nt][2], acc[mt][nt][3]);
            }
        }
    } else {
        #pragma unroll
        for (int mt = 0; mt < 2; mt++) {
            int r = row0 - 1024 + wm * 32 + mt * 16 + r_lo;
            #pragma unroll
            for (int nt = 0; nt < 8; nt++) {
                int c = col0 + wn * 64 + nt * 8 + c_lo;
                float2 x0 = rd2h(X, (size_t)r * LD + c);
                float2 x1 = rd2h(X, (size_t)(r + 8) * LD + c);
                st2h(Y2, (size_t)r * LD + c,       acc[mt][nt][0] - x0.x, acc[mt][nt][1] - x0.y);
                st2h(Y2, (size_t)(r + 8) * LD + c, acc[mt][nt][2] - x1.x, acc[mt][nt][3] - x1.y);
            }
        }
    }
}

// ---------------- fp16 HMMA weight matmul + GRU epilogue (one node per CTA) ----------------
template <int C, bool GATE>
__global__ void __launch_bounds__(256) cell_mm(
    const __half* __restrict__ F0, const __half* __restrict__ F1, const __half* __restrict__ F2,
    const __half* __restrict__ Wimg, const float* __restrict__ bias,
    const float* __restrict__ hin, float* __restrict__ rbuf,
    __half* __restrict__ outC, float* __restrict__ hout, int offn)
{
    constexpr int Fall = GATE ? 128 : 64;
    constexpr int NP   = GATE ? 2 : 1;
    constexpr int BIMG = 208 * 128;
    constexpr int WIMG = Fall * 432;
    constexpr int OFF  = C - 64;
    extern __shared__ __align__(16) char sm[];
    char* Bm = sm;
    char* Wm = sm + BIMG;
    float* bs = (float*)(Wm + WIMG);
    int n = blockIdx.x, tid = threadIdx.x;
    int lane = tid & 31, wid = tid >> 5;
    uint32_t bB = smem_u32(Bm);
    uint32_t bW = smem_u32(Wm);

    const __half* src[3] = {F0 + (size_t)n * LD, F1 + (size_t)n * LD, F2 + (size_t)n * LD};

    for (int i = tid; i < 1664; i += 256) {
        int k = i >> 3, ch = i & 7;
        uint32_t sw = swA((uint32_t)(k * 128 + ch * 16));
        if (k < 3 * C) {
            int kk = k / C, c = k - kk * C;
            cpa16(bB + sw, src[kk] + c * 64 + ch * 8);
        } else {
            *(uint4*)(Bm + sw) = make_uint4(0, 0, 0, 0);
        }
    }
    for (int i = tid; i < Fall * 27; i += 256) {
        int f = i / 27, ch = i - f * 27;
        cpa16(bW + f * 432 + ch * 16, Wimg + f * 216 + ch * 8);
    }
    if (tid < Fall) bs[tid] = bias[tid];
    asm volatile("cp.async.commit_group;" ::: "memory");
    asm volatile("cp.async.wait_group 0;" ::: "memory");
    __syncthreads();

    int wm = GATE ? (wid & 3) : (wid & 1);
    int wn = GATE ? (wid >> 2) : (wid >> 1);
    int f0 = wm * 32;
    int nb0 = wn * (GATE ? 32 : 16);
    int bk  = (lane & 7) + ((lane >> 3) & 1) * 8;
    int bn8 = ((lane >> 4) & 1) * 8;

    float acc[2][2 * NP][4];
    #pragma unroll
    for (int mt = 0; mt < 2; mt++)
        #pragma unroll
        for (int nt = 0; nt < 2 * NP; nt++)
            #pragma unroll
            for (int j = 0; j < 4; j++) acc[mt][nt][j] = 0.f;

    #pragma unroll 1
    for (int kt = 0; kt < 13; kt++) {
        uint32_t aF[2][4];
        #pragma unroll
        for (int mt = 0; mt < 2; mt++) {
            uint32_t ao = (uint32_t)((f0 + mt * 16 + (lane & 15)) * 432 + kt * 32 + (lane >> 4) * 16);
            ldsm4(aF[mt], bW + ao);
        }
        #pragma unroll
        for (int p = 0; p < NP; p++) {
            uint32_t bo = swA((uint32_t)((kt * 16 + bk) * 128 + (nb0 + p * 16 + bn8) * 2));
            uint32_t bF[4];
            ldsm4t(bF, bB + bo);
            #pragma unroll
            for (int mt = 0; mt < 2; mt++) {
                mma_f16(acc[mt][2 * p],     aF[mt], bF[0], bF[1]);
                mma_f16(acc[mt][2 * p + 1], aF[mt], bF[2], bF[3]);
            }
        }
    }

    // epilogue
    int r_lo = lane >> 2, c_lo = (lane & 3) * 2;
    size_t nLD = (size_t)n * LD;
    size_t nH  = (size_t)n * 4096;
    #pragma unroll
    for (int mt = 0; mt < 2; mt++) {
        int row = f0 + mt * 16 + r_lo;
        #pragma unroll
        for (int nt = 0; nt < 2 * NP; nt++) {
            int col = nb0 + nt * 8 + c_lo;
            float v0 = acc[mt][nt][0] + bs[row];
            float v1 = acc[mt][nt][1] + bs[row];
            float v2 = acc[mt][nt][2] + bs[row + 8];
            float v3 = acc[mt][nt][3] + bs[row + 8];
            if (GATE) {
                if (row < 64) {
                    #pragma unroll
                    for (int q = 0; q < 2; q++) {
                        int f = row + q * 8;
                        float z0 = 1.f / (1.f + expf(-(q ? v2 : v0)));
                        float z1 = 1.f / (1.f + expf(-(q ? v3 : v1)));
                        float2 hv = *(const float2*)(hin + nH + (size_t)f * 64 + col);
                        st2h(outC, nLD + (size_t)(OFF + f) * 64 + col, z0 * hv.x, z1 * hv.y);
                    }
                } else {
                    #pragma unroll
                    for (int q = 0; q < 2; q++) {
                        int f = row - 64 + q * 8;
                        float r0 = 1.f / (1.f + expf(-(q ? v2 : v0)));
                        float r1 = 1.f / (1.f + expf(-(q ? v3 : v1)));
                        *(float2*)(rbuf + nH + (size_t)f * 64 + col) = make_float2(r0, r1);
                    }
                }
            } else {
                #pragma unroll
                for (int q = 0; q < 2; q++) {
                    int f = row + q * 8;
                    float hc0 = tanhf(q ? v2 : v0);
                    float hc1 = tanhf(q ? v3 : v1);
                    float2 rv = *(const float2*)(rbuf + nH + (size_t)f * 64 + col);
                    float2 hv = *(const float2*)(hin  + nH + (size_t)f * 64 + col);
                    float hn0 = rv.x * hv.x + (1.f - rv.x) * hc0;
                    float hn1 = rv.y * hv.y + (1.f - rv.y) * hc1;
                    *(float2*)(hout + nH + (size_t)f * 64 + col) = make_float2(hn0, hn1);
                    st2h(outC, nLD + (size_t)(offn + f) * 64 + col, hn0, hn1);
                }
            }
        }
    }
}

// ---------------- per-step column injection ----------------
__global__ void inject_enc(const float* __restrict__ x, int t,
                           __half* __restrict__ c1, __half* __restrict__ c2) {
    int n = blockIdx.x, b = threadIdx.x;
    __half v = __float2half(x[(size_t)(b * TT + t) * NN + n]);
    size_t pos = (size_t)n * LD + b;
    c1[pos] = v;
    c2[pos] = v;
}
__global__ void inject_dec(const float* __restrict__ yc, int t, const float* __restrict__ go,
                           __half* __restrict__ c1, __half* __restrict__ c2) {
    int n = blockIdx.x, b = threadIdx.x;
    __half v0 = __float2half(go[n * 64 + b]);
    __half v1 = __float2half(yc[(size_t)(b * TT + t) * NN + n]);
    size_t pos = (size_t)n * LD + b;
    c1[pos] = v0; c2[pos] = v0;
    c1[pos + 64] = v1; c2[pos + 64] = v1;
}

// ---------------- projection ----------------
__global__ void proj_kernel(const float* __restrict__ h, const float* __restrict__ pW,
                            const float* __restrict__ pb, float* __restrict__ go,
                            float* __restrict__ out, int t) {
    __shared__ float w[64];
    int n = blockIdx.x, b = threadIdx.x;
    w[b] = pW[b];
    __syncthreads();
    size_t nH = (size_t)n * 4096;
    float s = 0.f;
    #pragma unroll
    for (int f = 0; f < 64; f++) s = fmaf(h[nH + f * 64 + b], w[f], s);
    float v = s + pb[0];
    go[n * 64 + b] = v;
    out[(size_t)(b * TT + t) * NN + n] = v;
}

// ---------------- orchestration ----------------
extern "C" void kernel_launch(void* const* d_in, const int* in_sizes, int n_in,
                              void* d_out, int out_size) {
    const float* x    = (const float*)d_in[0];
    const float* ycov = (const float*)d_in[1];
    const float* emb  = (const float*)d_in[2];
    const float* egW  = (const float*)d_in[3];
    const float* egb  = (const float*)d_in[4];
    const float* euW  = (const float*)d_in[5];
    const float* eub  = (const float*)d_in[6];
    const float* dgW  = (const float*)d_in[7];
    const float* dgb  = (const float*)d_in[8];
    const float* duW  = (const float*)d_in[9];
    const float* dub  = (const float*)d_in[10];
    const float* pW   = (const float*)d_in[11];
    const float* pb   = (const float*)d_in[12];
    float* out = (float*)d_out;

    float *pM, *ph, *pr, *pgo;
    __half *pMh, *pc1, *pc2, *pY1, *pY2, *pWgE, *pWgD, *pWuE, *pWuD;
    cudaGetSymbolAddress((void**)&pM,   g_M);
    cudaGetSymbolAddress((void**)&pMh,  g_Mh);
    cudaGetSymbolAddress((void**)&pc1,  g_c1);
    cudaGetSymbolAddress((void**)&pc2,  g_c2);
    cudaGetSymbolAddress((void**)&pY1,  g_Y1);
    cudaGetSymbolAddress((void**)&pY2,  g_Y2);
    cudaGetSymbolAddress((void**)&ph,   g_h);
    cudaGetSymbolAddress((void**)&pr,   g_r);
    cudaGetSymbolAddress((void**)&pgo,  g_go);
    cudaGetSymbolAddress((void**)&pWgE, g_WgE);
    cudaGetSymbolAddress((void**)&pWgD, g_WgD);
    cudaGetSymbolAddress((void**)&pWuE, g_WuE);
    cudaGetSymbolAddress((void**)&pWuD, g_WuD);

    const int smHM = 2 * STG;                           // 65536
    const int smG  = 208 * 128 + 128 * 432 + 512;       // 82432
    const int smU  = 208 * 128 + 64 * 432 + 256;        // 54528
    cudaFuncSetAttribute((const void*)hmma_gemm,          cudaFuncAttributeMaxDynamicSharedMemorySize, smHM);
    cudaFuncSetAttribute((const void*)cell_mm<65, true>,  cudaFuncAttributeMaxDynamicSharedMemorySize, smG);
    cudaFuncSetAttribute((const void*)cell_mm<66, true>,  cudaFuncAttributeMaxDynamicSharedMemorySize, smG);
    cudaFuncSetAttribute((const void*)cell_mm<65, false>, cudaFuncAttributeMaxDynamicSharedMemorySize, smU);
    cudaFuncSetAttribute((const void*)cell_mm<66, false>, cudaFuncAttributeMaxDynamicSharedMemorySize, smU);

    cudaMemsetAsync(ph,  0, (size_t)NN * 64 * 64 * sizeof(float));
    cudaMemsetAsync(pgo, 0, (size_t)NN * 64 * sizeof(float));
    cudaMemsetAsync(pc1, 0, (size_t)NN * LD * sizeof(__half));
    cudaMemsetAsync(pc2, 0, (size_t)NN * LD * sizeof(__half));

    build_support_kernel<<<NN, 256>>>(emb, pM);
    gemmA2<<<dim3(8, 8), 256>>>(pM, pM + (size_t)NN * NN);
    convert_M<<<2 * NN * NN / 256, 256>>>(pM, pMh);
    prep_W<<<128, 64>>>(egW, 195, 128, pWgE);
    prep_W<<<128, 64>>>(dgW, 198, 128, pWgD);
    prep_W<<<64, 64>>>(euW, 195, 64, pWuE);
    prep_W<<<64, 64>>>(duW, 198, 64, pWuD);

    dim3 gg(33, 16);
    for (int t = 0; t < TT; t++) {
        inject_enc<<<NN, 64>>>(x, t, pc1, pc2);
        hmma_gemm<<<gg, 256, smHM>>>(pMh, pc1, pY1, pY2);
        cell_mm<65, true><<<NN, 256, smG>>>(pc1, pY1, pY2, pWgE, egb, ph, pr, pc2, nullptr, 0);
        hmma_gemm<<<gg, 256, smHM>>>(pMh, pc2, pY1, pY2);
        int offn = (t == TT - 1) ? 2 : 1;
        cell_mm<65, false><<<NN, 256, smU>>>(pc2, pY1, pY2, pWuE, eub, ph, pr, pc1, ph, offn);
    }
    for (int t = 0; t < TT; t++) {
        inject_dec<<<NN, 64>>>(ycov, t, pgo, pc1, pc2);
        hmma_gemm<<<gg, 256, smHM>>>(pMh, pc1, pY1, pY2);
        cell_mm<66, true><<<NN, 256, smG>>>(pc1, pY1, pY2, pWgD, dgb, ph, pr, pc2, nullptr, 0);
        hmma_gemm<<<gg, 256, smHM>>>(pMh, pc2, pY1, pY2);
        cell_mm<66, false><<<NN, 256, smU>>>(pc2, pY1, pY2, pWuD, dub, ph, pr, pc1, ph, 2);
        proj_kernel<<<NN, 64>>>(ph, pW, pb, pgo, out, t);
    }
}

// round 14
// speedup vs baseline: 3.8622x; 1.2033x over previous
#include <cuda_runtime.h>
#include <cuda_fp16.h>
#include <math.h>
#include <stdint.h>

#define NN 1024
#define TT 12
#define LD 4352   // padded cols; GEMM covers 33*128 = 4224

// ---------------- scratch ----------------
__device__ float g_M [2 * NN * NN];
__device__ __align__(256) __half g_Mh[2 * NN * NN];   // fp16 of [A ; 2*A2]
__device__ __align__(256) __half g_c1[NN * LD];       // cat1 fp16, c-major [n][c*64+b]
__device__ __align__(256) __half g_c2[NN * LD];
__device__ __align__(256) __half g_Y1[NN * LD];
__device__ __align__(256) __half g_Y2[NN * LD];       // holds 2*A2@X (W-folded -X)
__device__ float g_h [NN * 64 * 64];                  // [n][f*64+b]
__device__ float g_r [NN * 64 * 64];
__device__ float g_go[NN * 64];
// W images: [Fall][216] fp16 (k padded to 216; rows k<C hold W1-W3 fold)
__device__ __align__(256) __half g_WgE[128 * 216];
__device__ __align__(256) __half g_WgD[128 * 216];
__device__ __align__(256) __half g_WuE[64 * 216];
__device__ __align__(256) __half g_WuD[64 * 216];

// ---------------- helpers ----------------
__device__ __forceinline__ uint32_t smem_u32(const void* p) {
    uint32_t a;
    asm("{ .reg .u64 t; cvta.to.shared.u64 t, %1; cvt.u32.u64 %0, t; }" : "=r"(a) : "l"(p));
    return a;
}
__device__ __forceinline__ void cpa16(uint32_t dst, const void* src) {
    asm volatile("cp.async.cg.shared.global [%0], [%1], 16;" :: "r"(dst), "l"(src));
}
__device__ __forceinline__ void ldsm4(uint32_t* r, uint32_t a) {
    asm volatile("ldmatrix.sync.aligned.m8n8.x4.shared.b16 {%0,%1,%2,%3}, [%4];"
        : "=r"(r[0]), "=r"(r[1]), "=r"(r[2]), "=r"(r[3]) : "r"(a));
}
__device__ __forceinline__ void ldsm4t(uint32_t* r, uint32_t a) {
    asm volatile("ldmatrix.sync.aligned.m8n8.x4.trans.shared.b16 {%0,%1,%2,%3}, [%4];"
        : "=r"(r[0]), "=r"(r[1]), "=r"(r[2]), "=r"(r[3]) : "r"(a));
}
__device__ __forceinline__ void mma_f16(float* d, const uint32_t* a, uint32_t b0, uint32_t b1) {
    asm volatile("mma.sync.aligned.m16n8k16.row.col.f32.f16.f16.f32 "
        "{%0,%1,%2,%3},{%4,%5,%6,%7},{%8,%9},{%0,%1,%2,%3};"
        : "+f"(d[0]), "+f"(d[1]), "+f"(d[2]), "+f"(d[3])
        : "r"(a[0]), "r"(a[1]), "r"(a[2]), "r"(a[3]), "r"(b0), "r"(b1));
}
__device__ __forceinline__ void st2h(__half* H, size_t idx, float a, float b) {
    __half2 v;
    v.x = __float2half(a);
    v.y = __float2half(b);
    *reinterpret_cast<__half2*>(H + idx) = v;
}
__device__ __forceinline__ uint32_t swA(uint32_t off) { return off ^ ((off >> 3) & 0x70); }
__device__ __forceinline__ uint32_t swB(uint32_t off) { return off ^ (((off >> 8) & 7) << 4); }

// ---------------- support: A = softmax(relu(E E^T), rows) ----------------
__global__ void build_support_kernel(const float* __restrict__ emb, float* __restrict__ A) {
    __shared__ float se[NN * 8];
    __shared__ float row[NN];
    __shared__ float wred[8];
    __shared__ float red;
    int n = blockIdx.x, tid = threadIdx.x;
    for (int i = tid; i < NN * 8; i += 256) se[i] = emb[i];
    __syncthreads();
    float e[8];
    #pragma unroll
    for (int j = 0; j < 8; j++) e[j] = se[n * 8 + j];
    float mx = 0.f;
    for (int m = tid; m < NN; m += 256) {
        const float* em = &se[m * 8];
        float s = 0.f;
        #pragma unroll
        for (int j = 0; j < 8; j++) s += e[j] * em[j];
        s = fmaxf(s, 0.f);
        row[m] = s;
        mx = fmaxf(mx, s);
    }
    #pragma unroll
    for (int o = 16; o; o >>= 1) mx = fmaxf(mx, __shfl_xor_sync(0xffffffffu, mx, o));
    if ((tid & 31) == 0) wred[tid >> 5] = mx;
    __syncthreads();
    if (tid == 0) { float v = wred[0]; for (int w = 1; w < 8; w++) v = fmaxf(v, wred[w]); red = v; }
    __syncthreads();
    float bmax = red, sum = 0.f;
    for (int m = tid; m < NN; m += 256) { float v = expf(row[m] - bmax); row[m] = v; sum += v; }
    #pragma unroll
    for (int o = 16; o; o >>= 1) sum += __shfl_xor_sync(0xffffffffu, sum, o);
    if ((tid & 31) == 0) wred[tid >> 5] = sum;
    __syncthreads();
    if (tid == 0) { float v = 0.f; for (int w = 0; w < 8; w++) v += wred[w]; red = v; }
    __syncthreads();
    float inv = 1.f / red;
    for (int m = tid; m < NN; m += 256) A[n * NN + m] = row[m] * inv;
}

// ---------------- A2 = A @ A ----------------
__global__ void __launch_bounds__(256, 2) gemmA2(const float* __restrict__ A, float* __restrict__ A2) {
    __shared__ __align__(16) float As[2][8][132];
    __shared__ __align__(16) float Bs[2][8][128];
    int tid = threadIdx.x;
    int row0 = blockIdx.y * 128, col0 = blockIdx.x * 128;
    int arow = tid >> 1, acol4 = (tid & 1) << 2;
    int brow = tid >> 5, bcol4 = (tid & 31) << 2;
    int tx = tid & 15, ty = tid >> 4;
    const float* Ap = A + (size_t)(row0 + arow) * NN + acol4;
    const float* Xp = A + (size_t)brow * NN + col0 + bcol4;
    float acc[8][8];
    #pragma unroll
    for (int i = 0; i < 8; i++)
        #pragma unroll
        for (int j = 0; j < 8; j++) acc[i][j] = 0.f;
    float4 av = *(const float4*)Ap;
    float4 bv = *(const float4*)Xp;
    int buf = 0;
    As[0][acol4 + 0][arow] = av.x; As[0][acol4 + 1][arow] = av.y;
    As[0][acol4 + 2][arow] = av.z; As[0][acol4 + 3][arow] = av.w;
    *(float4*)&Bs[0][brow][bcol4] = bv;
    __syncthreads();
    for (int kt = 1; kt < 128; kt++) {
        av = *(const float4*)(Ap + kt * 8);
        bv = *(const float4*)(Xp + (size_t)(kt * 8) * NN);
        #pragma unroll
        for (int kk = 0; kk < 8; kk++) {
            float4 a0 = *(const float4*)&As[buf][kk][ty * 4];
            float4 a1 = *(const float4*)&As[buf][kk][64 + ty * 4];
            float4 b0 = *(const float4*)&Bs[buf][kk][tx * 4];
            float4 b1 = *(const float4*)&Bs[buf][kk][64 + tx * 4];
            float a[8] = {a0.x,a0.y,a0.z,a0.w,a1.x,a1.y,a1.z,a1.w};
            float b[8] = {b0.x,b0.y,b0.z,b0.w,b1.x,b1.y,b1.z,b1.w};
            #pragma unroll
            for (int i = 0; i < 8; i++)
                #pragma unroll
                for (int j = 0; j < 8; j++) acc[i][j] = fmaf(a[i], b[j], acc[i][j]);
        }
        buf ^= 1;
        As[buf][acol4 + 0][arow] = av.x; As[buf][acol4 + 1][arow] = av.y;
        As[buf][acol4 + 2][arow] = av.z; As[buf][acol4 + 3][arow] = av.w;
        *(float4*)&Bs[buf][brow][bcol4] = bv;
        __syncthreads();
    }
    #pragma unroll
    for (int kk = 0; kk < 8; kk++) {
        float4 a0 = *(const float4*)&As[buf][kk][ty * 4];
        float4 a1 = *(const float4*)&As[buf][kk][64 + ty * 4];
        float4 b0 = *(const float4*)&Bs[buf][kk][tx * 4];
        float4 b1 = *(const float4*)&Bs[buf][kk][64 + tx * 4];
        float a[8] = {a0.x,a0.y,a0.z,a0.w,a1.x,a1.y,a1.z,a1.w};
        float b[8] = {b0.x,b0.y,b0.z,b0.w,b1.x,b1.y,b1.z,b1.w};
        #pragma unroll
        for (int i = 0; i < 8; i++)
            #pragma unroll
            for (int j = 0; j < 8; j++) acc[i][j] = fmaf(a[i], b[j], acc[i][j]);
    }
    #pragma unroll
    for (int i = 0; i < 8; i++) {
        int grow = row0 + ((i < 4) ? (ty * 4 + i) : (64 + ty * 4 + i - 4));
        float* yp = A2 + (size_t)grow * NN;
        *(float4*)(yp + col0 + tx * 4)       = make_float4(acc[i][0], acc[i][1], acc[i][2], acc[i][3]);
        *(float4*)(yp + col0 + 64 + tx * 4)  = make_float4(acc[i][4], acc[i][5], acc[i][6], acc[i][7]);
    }
}

// ---------------- M -> fp16 (fold 2x into bottom half) ----------------
__global__ void convert_M(const float* __restrict__ M, __half* __restrict__ Mh) {
    int i = blockIdx.x * 256 + threadIdx.x;
    float v = M[i];
    if (i >= NN * NN) v *= 2.f;
    Mh[i] = __float2half(v);
}

// ---------------- W^T image prep: fp16 [Fall][216], rows k<C folded W1-W3 ----------------
__global__ void prep_W(const float* __restrict__ W, int C, int Fall,
                       __half* __restrict__ img) {
    int f = blockIdx.x;
    int K3 = 3 * C;
    for (int k = threadIdx.x; k < 216; k += 64) {
        float v = 0.f;
        if (k < K3) {
            v = W[k * Fall + f];
            if (k < C) v -= W[(2 * C + k) * Fall + f];   // fold the -X of T2
        }
        img[f * 216 + k] = __float2half(v);
    }
}

// ---------------- fp16 HMMA diffusion GEMM (pure: Y = M @ X, no epilogue math) ----------------
// stage (32KB): A 16K | B 16K ; 2-stage, KC=64, 2 CTAs/SM
#define KC 64
#define STG 32768
__global__ void __launch_bounds__(256, 2) hmma_gemm(
    const __half* __restrict__ Mh, const __half* __restrict__ X,
    __half* __restrict__ Y1, __half* __restrict__ Y2)
{
    extern __shared__ __align__(1024) char smem[];
    uint32_t sb = smem_u32(smem);
    int tid = threadIdx.x;
    int lane = tid & 31, wid = tid >> 5;
    int wm = wid >> 1, wn = wid & 1;
    int row0 = blockIdx.y * 128;
    int col0 = blockIdx.x * 128;

    float acc[2][8][4];
    #pragma unroll
    for (int mt = 0; mt < 2; mt++)
        #pragma unroll
        for (int nt = 0; nt < 8; nt++)
            #pragma unroll
            for (int j = 0; j < 4; j++) acc[mt][nt][j] = 0.f;

    auto load_stage = [&](int it) {
        uint32_t base = sb + (it & 1) * STG;
        int k0 = it * KC;
        #pragma unroll
        for (int i = tid; i < 1024; i += 256) {
            int r = i >> 3, c = i & 7;
            uint32_t sw = swA((uint32_t)(r * 128 + c * 16));
            cpa16(base + sw, Mh + (size_t)(row0 + r) * NN + k0 + c * 8);
        }
        #pragma unroll
        for (int i = tid; i < 1024; i += 256) {
            int k = i >> 4, c = i & 15;
            uint32_t sw = swB((uint32_t)(k * 256 + c * 16));
            cpa16(base + 16384 + sw, X + (size_t)(k0 + k) * LD + col0 + c * 8);
        }
        asm volatile("cp.async.commit_group;" ::: "memory");
    };

    load_stage(0);
    load_stage(1);

    int a_r = wm * 32 + (lane & 15);
    int a_ch = (lane >> 4);
    int b_k = (lane & 7) + ((lane >> 3) & 1) * 8;
    int b_n8 = ((lane >> 4) & 1) * 8;

    #pragma unroll 1
    for (int it = 0; it < 16; it++) {
        int buf = it & 1;
        if (it < 15) asm volatile("cp.async.wait_group 1;" ::: "memory");
        else         asm volatile("cp.async.wait_group 0;" ::: "memory");
        __syncthreads();
        uint32_t base = sb + buf * STG;
        #pragma unroll
        for (int kk = 0; kk < 4; kk++) {
            uint32_t aF[2][4];
            #pragma unroll
            for (int mt = 0; mt < 2; mt++) {
                uint32_t off = swA((uint32_t)((a_r + mt * 16) * 128 + (kk * 2 + a_ch) * 16));
                ldsm4(aF[mt], base + off);
            }
            uint32_t bF[4][4];
            #pragma unroll
            for (int p = 0; p < 4; p++) {
                int nb = wn * 64 + p * 16 + b_n8;
                uint32_t off = swB((uint32_t)((kk * 16 + b_k) * 256 + nb * 2));
                ldsm4t(bF[p], base + 16384 + off);
            }
            #pragma unroll
            for (int mt = 0; mt < 2; mt++) {
                #pragma unroll
                for (int p = 0; p < 4; p++) {
                    mma_f16(acc[mt][2 * p],     aF[mt], bF[p][0], bF[p][1]);
                    mma_f16(acc[mt][2 * p + 1], aF[mt], bF[p][2], bF[p][3]);
                }
            }
        }
        __syncthreads();
        if (it + 2 < 16) load_stage(it + 2);
    }

    // epilogue: plain fp16 store (W-fold removed the -X term)
    int r_lo = lane >> 2;
    int c_lo = (lane & 3) * 2;
    __half* Y = (row0 < 1024) ? Y1 : Y2;
    int rbase = (row0 < 1024) ? row0 : (row0 - 1024);
    #pragma unroll
    for (int mt = 0; mt < 2; mt++) {
        int r = rbase + wm * 32 + mt * 16 + r_lo;
        #pragma unroll
        for (int nt = 0; nt < 8; nt++) {
            int c = col0 + wn * 64 + nt * 8 + c_lo;
            st2h(Y, (size_t)r * LD + c,       acc[mt][nt][0], acc[mt][nt][1]);
            st2h(Y, (size_t)(r + 8) * LD + c, acc[mt][nt][2], acc[mt][nt][3]);
        }
    }
}

// ---------------- fp16 HMMA weight matmul + GRU epilogue (one node per CTA) ----------------
template <int C, bool GATE>
__global__ void __launch_bounds__(256) cell_mm(
    const __half* __restrict__ F0, const __half* __restrict__ F1, const __half* __restrict__ F2,
    const __half* __restrict__ Wimg, const float* __restrict__ bias,
    const float* __restrict__ hin, float* __restrict__ rbuf,
    __half* __restrict__ outC, float* __restrict__ hout, int offn)
{
    constexpr int Fall = GATE ? 128 : 64;
    constexpr int NP   = GATE ? 2 : 1;
    constexpr int BIMG = 208 * 128;
    constexpr int WIMG = Fall * 432;
    constexpr int OFF  = C - 64;
    extern __shared__ __align__(16) char sm[];
    char* Bm = sm;
    char* Wm = sm + BIMG;
    float* bs = (float*)(Wm + WIMG);
    int n = blockIdx.x, tid = threadIdx.x;
    int lane = tid & 31, wid = tid >> 5;
    uint32_t bB = smem_u32(Bm);
    uint32_t bW = smem_u32(Wm);

    const __half* src[3] = {F0 + (size_t)n * LD, F1 + (size_t)n * LD, F2 + (size_t)n * LD};

    for (int i = tid; i < 1664; i += 256) {
        int k = i >> 3, ch = i & 7;
        uint32_t sw = swA((uint32_t)(k * 128 + ch * 16));
        if (k < 3 * C) {
            int kk = k / C, c = k - kk * C;
            cpa16(bB + sw, src[kk] + c * 64 + ch * 8);
        } else {
            *(uint4*)(Bm + sw) = make_uint4(0, 0, 0, 0);
        }
    }
    for (int i = tid; i < Fall * 27; i += 256) {
        int f = i / 27, ch = i - f * 27;
        cpa16(bW + f * 432 + ch * 16, Wimg + f * 216 + ch * 8);
    }
    if (tid < Fall) bs[tid] = bias[tid];
    asm volatile("cp.async.commit_group;" ::: "memory");
    asm volatile("cp.async.wait_group 0;" ::: "memory");
    __syncthreads();

    int wm = GATE ? (wid & 3) : (wid & 1);
    int wn = GATE ? (wid >> 2) : (wid >> 1);
    int f0 = wm * 32;
    int nb0 = wn * (GATE ? 32 : 16);
    int bk  = (lane & 7) + ((lane >> 3) & 1) * 8;
    int bn8 = ((lane >> 4) & 1) * 8;

    float acc[2][2 * NP][4];
    #pragma unroll
    for (int mt = 0; mt < 2; mt++)
        #pragma unroll
        for (int nt = 0; nt < 2 * NP; nt++)
            #pragma unroll
            for (int j = 0; j < 4; j++) acc[mt][nt][j] = 0.f;

    #pragma unroll 1
    for (int kt = 0; kt < 13; kt++) {
        uint32_t aF[2][4];
        #pragma unroll
        for (int mt = 0; mt < 2; mt++) {
            uint32_t ao = (uint32_t)((f0 + mt * 16 + (lane & 15)) * 432 + kt * 32 + (lane >> 4) * 16);
            ldsm4(aF[mt], bW + ao);
        }
        #pragma unroll
        for (int p = 0; p < NP; p++) {
            uint32_t bo = swA((uint32_t)((kt * 16 + bk) * 128 + (nb0 + p * 16 + bn8) * 2));
            uint32_t bF[4];
            ldsm4t(bF, bB + bo);
            #pragma unroll
            for (int mt = 0; mt < 2; mt++) {
                mma_f16(acc[mt][2 * p],     aF[mt], bF[0], bF[1]);
                mma_f16(acc[mt][2 * p + 1], aF[mt], bF[2], bF[3]);
            }
        }
    }

    // epilogue
    int r_lo = lane >> 2, c_lo = (lane & 3) * 2;
    size_t nLD = (size_t)n * LD;
    size_t nH  = (size_t)n * 4096;
    #pragma unroll
    for (int mt = 0; mt < 2; mt++) {
        int row = f0 + mt * 16 + r_lo;
        #pragma unroll
        for (int nt = 0; nt < 2 * NP; nt++) {
            int col = nb0 + nt * 8 + c_lo;
            float v0 = acc[mt][nt][0] + bs[row];
            float v1 = acc[mt][nt][1] + bs[row];
            float v2 = acc[mt][nt][2] + bs[row + 8];
            float v3 = acc[mt][nt][3] + bs[row + 8];
            if (GATE) {
                if (row < 64) {
                    #pragma unroll
                    for (int q = 0; q < 2; q++) {
                        int f = row + q * 8;
                        float z0 = 1.f / (1.f + expf(-(q ? v2 : v0)));
                        float z1 = 1.f / (1.f + expf(-(q ? v3 : v1)));
                        float2 hv = *(const float2*)(hin + nH + (size_t)f * 64 + col);
                        st2h(outC, nLD + (size_t)(OFF + f) * 64 + col, z0 * hv.x, z1 * hv.y);
                    }
                } else {
                    #pragma unroll
                    for (int q = 0; q < 2; q++) {
                        int f = row - 64 + q * 8;
                        float r0 = 1.f / (1.f + expf(-(q ? v2 : v0)));
                        float r1 = 1.f / (1.f + expf(-(q ? v3 : v1)));
                        *(float2*)(rbuf + nH + (size_t)f * 64 + col) = make_float2(r0, r1);
                    }
                }
            } else {
                #pragma unroll
                for (int q = 0; q < 2; q++) {
                    int f = row + q * 8;
                    float hc0 = tanhf(q ? v2 : v0);
                    float hc1 = tanhf(q ? v3 : v1);
                    float2 rv = *(const float2*)(rbuf + nH + (size_t)f * 64 + col);
                    float2 hv = *(const float2*)(hin  + nH + (size_t)f * 64 + col);
                    float hn0 = rv.x * hv.x + (1.f - rv.x) * hc0;
                    float hn1 = rv.y * hv.y + (1.f - rv.y) * hc1;
                    *(float2*)(hout + nH + (size_t)f * 64 + col) = make_float2(hn0, hn1);
                    st2h(outC, nLD + (size_t)(offn + f) * 64 + col, hn0, hn1);
                }
            }
        }
    }
}

// ---------------- per-step column injection ----------------
__global__ void inject_enc(const float* __restrict__ x, int t,
                           __half* __restrict__ c1, __half* __restrict__ c2) {
    int n = blockIdx.x, b = threadIdx.x;
    __half v = __float2half(x[(size_t)(b * TT + t) * NN + n]);
    size_t pos = (size_t)n * LD + b;
    c1[pos] = v;
    c2[pos] = v;
}
__global__ void inject_dec(const float* __restrict__ yc, int t, const float* __restrict__ go,
                           __half* __restrict__ c1, __half* __restrict__ c2) {
    int n = blockIdx.x, b = threadIdx.x;
    __half v0 = __float2half(go[n * 64 + b]);
    __half v1 = __float2half(yc[(size_t)(b * TT + t) * NN + n]);
    size_t pos = (size_t)n * LD + b;
    c1[pos] = v0; c2[pos] = v0;
    c1[pos + 64] = v1; c2[pos + 64] = v1;
}

// ---------------- projection ----------------
__global__ void proj_kernel(const float* __restrict__ h, const float* __restrict__ pW,
                            const float* __restrict__ pb, float* __restrict__ go,
                            float* __restrict__ out, int t) {
    __shared__ float w[64];
    int n = blockIdx.x, b = threadIdx.x;
    w[b] = pW[b];
    __syncthreads();
    size_t nH = (size_t)n * 4096;
    float s = 0.f;
    #pragma unroll
    for (int f = 0; f < 64; f++) s = fmaf(h[nH + f * 64 + b], w[f], s);
    float v = s + pb[0];
    go[n * 64 + b] = v;
    out[(size_t)(b * TT + t) * NN + n] = v;
}

// ---------------- orchestration ----------------
extern "C" void kernel_launch(void* const* d_in, const int* in_sizes, int n_in,
                              void* d_out, int out_size) {
    const float* x    = (const float*)d_in[0];
    const float* ycov = (const float*)d_in[1];
    const float* emb  = (const float*)d_in[2];
    const float* egW  = (const float*)d_in[3];
    const float* egb  = (const float*)d_in[4];
    const float* euW  = (const float*)d_in[5];
    const float* eub  = (const float*)d_in[6];
    const float* dgW  = (const float*)d_in[7];
    const float* dgb  = (const float*)d_in[8];
    const float* duW  = (const float*)d_in[9];
    const float* dub  = (const float*)d_in[10];
    const float* pW   = (const float*)d_in[11];
    const float* pb   = (const float*)d_in[12];
    float* out = (float*)d_out;

    float *pM, *ph, *pr, *pgo;
    __half *pMh, *pc1, *pc2, *pY1, *pY2, *pWgE, *pWgD, *pWuE, *pWuD;
    cudaGetSymbolAddress((void**)&pM,   g_M);
    cudaGetSymbolAddress((void**)&pMh,  g_Mh);
    cudaGetSymbolAddress((void**)&pc1,  g_c1);
    cudaGetSymbolAddress((void**)&pc2,  g_c2);
    cudaGetSymbolAddress((void**)&pY1,  g_Y1);
    cudaGetSymbolAddress((void**)&pY2,  g_Y2);
    cudaGetSymbolAddress((void**)&ph,   g_h);
    cudaGetSymbolAddress((void**)&pr,   g_r);
    cudaGetSymbolAddress((void**)&pgo,  g_go);
    cudaGetSymbolAddress((void**)&pWgE, g_WgE);
    cudaGetSymbolAddress((void**)&pWgD, g_WgD);
    cudaGetSymbolAddress((void**)&pWuE, g_WuE);
    cudaGetSymbolAddress((void**)&pWuD, g_WuD);

    const int smHM = 2 * STG;                           // 65536
    const int smG  = 208 * 128 + 128 * 432 + 512;       // 82432
    const int smU  = 208 * 128 + 64 * 432 + 256;        // 54528
    cudaFuncSetAttribute((const void*)hmma_gemm,          cudaFuncAttributeMaxDynamicSharedMemorySize, smHM);
    cudaFuncSetAttribute((const void*)cell_mm<65, true>,  cudaFuncAttributeMaxDynamicSharedMemorySize, smG);
    cudaFuncSetAttribute((const void*)cell_mm<66, true>,  cudaFuncAttributeMaxDynamicSharedMemorySize, smG);
    cudaFuncSetAttribute((const void*)cell_mm<65, false>, cudaFuncAttributeMaxDynamicSharedMemorySize, smU);
    cudaFuncSetAttribute((const void*)cell_mm<66, false>, cudaFuncAttributeMaxDynamicSharedMemorySize, smU);

    cudaMemsetAsync(ph,  0, (size_t)NN * 64 * 64 * sizeof(float));
    cudaMemsetAsync(pgo, 0, (size_t)NN * 64 * sizeof(float));
    cudaMemsetAsync(pc1, 0, (size_t)NN * LD * sizeof(__half));
    cudaMemsetAsync(pc2, 0, (size_t)NN * LD * sizeof(__half));

    build_support_kernel<<<NN, 256>>>(emb, pM);
    gemmA2<<<dim3(8, 8), 256>>>(pM, pM + (size_t)NN * NN);
    convert_M<<<2 * NN * NN / 256, 256>>>(pM, pMh);
    prep_W<<<128, 64>>>(egW, 65, 128, pWgE);
    prep_W<<<128, 64>>>(dgW, 66, 128, pWgD);
    prep_W<<<64, 64>>>(euW, 65, 64, pWuE);
    prep_W<<<64, 64>>>(duW, 66, 64, pWuD);

    dim3 gg(33, 16);
    for (int t = 0; t < TT; t++) {
        inject_enc<<<NN, 64>>>(x, t, pc1, pc2);
        hmma_gemm<<<gg, 256, smHM>>>(pMh, pc1, pY1, pY2);
        cell_mm<65, true><<<NN, 256, smG>>>(pc1, pY1, pY2, pWgE, egb, ph, pr, pc2, nullptr, 0);
        hmma_gemm<<<gg, 256, smHM>>>(pMh, pc2, pY1, pY2);
        int offn = (t == TT - 1) ? 2 : 1;
        cell_mm<65, false><<<NN, 256, smU>>>(pc2, pY1, pY2, pWuE, eub, ph, pr, pc1, ph, offn);
    }
    for (int t = 0; t < TT; t++) {
        inject_dec<<<NN, 64>>>(ycov, t, pgo, pc1, pc2);
        hmma_gemm<<<gg, 256, smHM>>>(pMh, pc1, pY1, pY2);
        cell_mm<66, true><<<NN, 256, smG>>>(pc1, pY1, pY2, pWgD, dgb, ph, pr, pc2, nullptr, 0);
        hmma_gemm<<<gg, 256, smHM>>>(pMh, pc2, pY1, pY2);
        cell_mm<66, false><<<NN, 256, smU>>>(pc2, pY1, pY2, pWuD, dub, ph, pr, pc1, ph, 2);
        proj_kernel<<<NN, 64>>>(ph, pW, pb, pgo, out, t);
    }
}

// round 15
// speedup vs baseline: 3.9060x; 1.0113x over previous
#include <cuda_runtime.h>
#include <cuda_fp16.h>
#include <math.h>
#include <stdint.h>

#define NN 1024
#define TT 12
#define LD 4352   // padded cols; GEMM covers 33*128 = 4224

// ---------------- scratch ----------------
__device__ float g_M [2 * NN * NN];
__device__ __align__(256) __half g_Mh[2 * NN * NN];   // fp16 of [A ; 2*A2]
__device__ __align__(256) __half g_c1[NN * LD];       // cat1 fp16, c-major [n][c*64+b]
__device__ __align__(256) __half g_c2[NN * LD];
__device__ __align__(256) __half g_Y1[NN * LD];
__device__ __align__(256) __half g_Y2[NN * LD];       // holds 2*A2@X (W-folded -X)
__device__ float g_h [NN * 64 * 64];                  // [n][f*64+b]
__device__ float g_r [NN * 64 * 64];
__device__ float g_go[NN * 64];
// W images: [Fall][216] fp16 (k padded to 216; rows k<C hold W1-W3 fold)
__device__ __align__(256) __half g_WgE[128 * 216];
__device__ __align__(256) __half g_WgD[128 * 216];
__device__ __align__(256) __half g_WuE[64 * 216];
__device__ __align__(256) __half g_WuD[64 * 216];

// ---------------- helpers ----------------
__device__ __forceinline__ uint32_t smem_u32(const void* p) {
    uint32_t a;
    asm("{ .reg .u64 t; cvta.to.shared.u64 t, %1; cvt.u32.u64 %0, t; }" : "=r"(a) : "l"(p));
    return a;
}
__device__ __forceinline__ void cpa16(uint32_t dst, const void* src) {
    asm volatile("cp.async.cg.shared.global [%0], [%1], 16;" :: "r"(dst), "l"(src));
}
__device__ __forceinline__ void ldsm4(uint32_t* r, uint32_t a) {
    asm volatile("ldmatrix.sync.aligned.m8n8.x4.shared.b16 {%0,%1,%2,%3}, [%4];"
        : "=r"(r[0]), "=r"(r[1]), "=r"(r[2]), "=r"(r[3]) : "r"(a));
}
__device__ __forceinline__ void ldsm4t(uint32_t* r, uint32_t a) {
    asm volatile("ldmatrix.sync.aligned.m8n8.x4.trans.shared.b16 {%0,%1,%2,%3}, [%4];"
        : "=r"(r[0]), "=r"(r[1]), "=r"(r[2]), "=r"(r[3]) : "r"(a));
}
__device__ __forceinline__ void mma_f16(float* d, const uint32_t* a, uint32_t b0, uint32_t b1) {
    asm volatile("mma.sync.aligned.m16n8k16.row.col.f32.f16.f16.f32 "
        "{%0,%1,%2,%3},{%4,%5,%6,%7},{%8,%9},{%0,%1,%2,%3};"
        : "+f"(d[0]), "+f"(d[1]), "+f"(d[2]), "+f"(d[3])
        : "r"(a[0]), "r"(a[1]), "r"(a[2]), "r"(a[3]), "r"(b0), "r"(b1));
}
__device__ __forceinline__ void st2h(__half* H, size_t idx, float a, float b) {
    __half2 v;
    v.x = __float2half(a);
    v.y = __float2half(b);
    *reinterpret_cast<__half2*>(H + idx) = v;
}
__device__ __forceinline__ uint32_t swA(uint32_t off) { return off ^ ((off >> 3) & 0x70); }
__device__ __forceinline__ uint32_t swB(uint32_t off) { return off ^ (((off >> 8) & 7) << 4); }

// ---------------- support: A = softmax(relu(E E^T), rows) ----------------
__global__ void build_support_kernel(const float* __restrict__ emb, float* __restrict__ A) {
    __shared__ float se[NN * 8];
    __shared__ float row[NN];
    __shared__ float wred[8];
    __shared__ float red;
    int n = blockIdx.x, tid = threadIdx.x;
    for (int i = tid; i < NN * 8; i += 256) se[i] = emb[i];
    __syncthreads();
    float e[8];
    #pragma unroll
    for (int j = 0; j < 8; j++) e[j] = se[n * 8 + j];
    float mx = 0.f;
    for (int m = tid; m < NN; m += 256) {
        const float* em = &se[m * 8];
        float s = 0.f;
        #pragma unroll
        for (int j = 0; j < 8; j++) s += e[j] * em[j];
        s = fmaxf(s, 0.f);
        row[m] = s;
        mx = fmaxf(mx, s);
    }
    #pragma unroll
    for (int o = 16; o; o >>= 1) mx = fmaxf(mx, __shfl_xor_sync(0xffffffffu, mx, o));
    if ((tid & 31) == 0) wred[tid >> 5] = mx;
    __syncthreads();
    if (tid == 0) { float v = wred[0]; for (int w = 1; w < 8; w++) v = fmaxf(v, wred[w]); red = v; }
    __syncthreads();
    float bmax = red, sum = 0.f;
    for (int m = tid; m < NN; m += 256) { float v = expf(row[m] - bmax); row[m] = v; sum += v; }
    #pragma unroll
    for (int o = 16; o; o >>= 1) sum += __shfl_xor_sync(0xffffffffu, sum, o);
    if ((tid & 31) == 0) wred[tid >> 5] = sum;
    __syncthreads();
    if (tid == 0) { float v = 0.f; for (int w = 0; w < 8; w++) v += wred[w]; red = v; }
    __syncthreads();
    float inv = 1.f / red;
    for (int m = tid; m < NN; m += 256) A[n * NN + m] = row[m] * inv;
}

// ---------------- A2 = A @ A ----------------
__global__ void __launch_bounds__(256, 2) gemmA2(const float* __restrict__ A, float* __restrict__ A2) {
    __shared__ __align__(16) float As[2][8][132];
    __shared__ __align__(16) float Bs[2][8][128];
    int tid = threadIdx.x;
    int row0 = blockIdx.y * 128, col0 = blockIdx.x * 128;
    int arow = tid >> 1, acol4 = (tid & 1) << 2;
    int brow = tid >> 5, bcol4 = (tid & 31) << 2;
    int tx = tid & 15, ty = tid >> 4;
    const float* Ap = A + (size_t)(row0 + arow) * NN + acol4;
    const float* Xp = A + (size_t)brow * NN + col0 + bcol4;
    float acc[8][8];
    #pragma unroll
    for (int i = 0; i < 8; i++)
        #pragma unroll
        for (int j = 0; j < 8; j++) acc[i][j] = 0.f;
    float4 av = *(const float4*)Ap;
    float4 bv = *(const float4*)Xp;
    int buf = 0;
    As[0][acol4 + 0][arow] = av.x; As[0][acol4 + 1][arow] = av.y;
    As[0][acol4 + 2][arow] = av.z; As[0][acol4 + 3][arow] = av.w;
    *(float4*)&Bs[0][brow][bcol4] = bv;
    __syncthreads();
    for (int kt = 1; kt < 128; kt++) {
        av = *(const float4*)(Ap + kt * 8);
        bv = *(const float4*)(Xp + (size_t)(kt * 8) * NN);
        #pragma unroll
        for (int kk = 0; kk < 8; kk++) {
            float4 a0 = *(const float4*)&As[buf][kk][ty * 4];
            float4 a1 = *(const float4*)&As[buf][kk][64 + ty * 4];
            float4 b0 = *(const float4*)&Bs[buf][kk][tx * 4];
            float4 b1 = *(const float4*)&Bs[buf][kk][64 + tx * 4];
            float a[8] = {a0.x,a0.y,a0.z,a0.w,a1.x,a1.y,a1.z,a1.w};
            float b[8] = {b0.x,b0.y,b0.z,b0.w,b1.x,b1.y,b1.z,b1.w};
            #pragma unroll
            for (int i = 0; i < 8; i++)
                #pragma unroll
                for (int j = 0; j < 8; j++) acc[i][j] = fmaf(a[i], b[j], acc[i][j]);
        }
        buf ^= 1;
        As[buf][acol4 + 0][arow] = av.x; As[buf][acol4 + 1][arow] = av.y;
        As[buf][acol4 + 2][arow] = av.z; As[buf][acol4 + 3][arow] = av.w;
        *(float4*)&Bs[buf][brow][bcol4] = bv;
        __syncthreads();
    }
    #pragma unroll
    for (int kk = 0; kk < 8; kk++) {
        float4 a0 = *(const float4*)&As[buf][kk][ty * 4];
        float4 a1 = *(const float4*)&As[buf][kk][64 + ty * 4];
        float4 b0 = *(const float4*)&Bs[buf][kk][tx * 4];
        float4 b1 = *(const float4*)&Bs[buf][kk][64 + tx * 4];
        float a[8] = {a0.x,a0.y,a0.z,a0.w,a1.x,a1.y,a1.z,a1.w};
        float b[8] = {b0.x,b0.y,b0.z,b0.w,b1.x,b1.y,b1.z,b1.w};
        #pragma unroll
        for (int i = 0; i < 8; i++)
            #pragma unroll
            for (int j = 0; j < 8; j++) acc[i][j] = fmaf(a[i], b[j], acc[i][j]);
    }
    #pragma unroll
    for (int i = 0; i < 8; i++) {
        int grow = row0 + ((i < 4) ? (ty * 4 + i) : (64 + ty * 4 + i - 4));
        float* yp = A2 + (size_t)grow * NN;
        *(float4*)(yp + col0 + tx * 4)       = make_float4(acc[i][0], acc[i][1], acc[i][2], acc[i][3]);
        *(float4*)(yp + col0 + 64 + tx * 4)  = make_float4(acc[i][4], acc[i][5], acc[i][6], acc[i][7]);
    }
}

// ---------------- M -> fp16 (fold 2x into bottom half) ----------------
__global__ void convert_M(const float* __restrict__ M, __half* __restrict__ Mh) {
    int i = blockIdx.x * 256 + threadIdx.x;
    float v = M[i];
    if (i >= NN * NN) v *= 2.f;
    Mh[i] = __float2half(v);
}

// ---------------- W^T image prep: fp16 [Fall][216], rows k<C folded W1-W3 ----------------
__global__ void prep_W(const float* __restrict__ W, int C, int Fall,
                       __half* __restrict__ img) {
    int f = blockIdx.x;
    int K3 = 3 * C;
    for (int k = threadIdx.x; k < 216; k += 64) {
        float v = 0.f;
        if (k < K3) {
            v = W[k * Fall + f];
            if (k < C) v -= W[(2 * C + k) * Fall + f];
        }
        img[f * 216 + k] = __float2half(v);
    }
}

// ---------------- fp16 HMMA diffusion GEMM ----------------
#define KC 64
#define STG 32768
__global__ void __launch_bounds__(256, 2) hmma_gemm(
    const __half* __restrict__ Mh, const __half* __restrict__ X,
    __half* __restrict__ Y1, __half* __restrict__ Y2)
{
    extern __shared__ __align__(1024) char smem[];
    uint32_t sb = smem_u32(smem);
    int tid = threadIdx.x;
    int lane = tid & 31, wid = tid >> 5;
    int wm = wid >> 1, wn = wid & 1;
    int row0 = blockIdx.y * 128;
    int col0 = blockIdx.x * 128;

    float acc[2][8][4];
    #pragma unroll
    for (int mt = 0; mt < 2; mt++)
        #pragma unroll
        for (int nt = 0; nt < 8; nt++)
            #pragma unroll
            for (int j = 0; j < 4; j++) acc[mt][nt][j] = 0.f;

    auto load_stage = [&](int it) {
        uint32_t base = sb + (it & 1) * STG;
        int k0 = it * KC;
        #pragma unroll
        for (int i = tid; i < 1024; i += 256) {
            int r = i >> 3, c = i & 7;
            uint32_t sw = swA((uint32_t)(r * 128 + c * 16));
            cpa16(base + sw, Mh + (size_t)(row0 + r) * NN + k0 + c * 8);
        }
        #pragma unroll
        for (int i = tid; i < 1024; i += 256) {
            int k = i >> 4, c = i & 15;
            uint32_t sw = swB((uint32_t)(k * 256 + c * 16));
            cpa16(base + 16384 + sw, X + (size_t)(k0 + k) * LD + col0 + c * 8);
        }
        asm volatile("cp.async.commit_group;" ::: "memory");
    };

    load_stage(0);
    load_stage(1);

    int a_r = wm * 32 + (lane & 15);
    int a_ch = (lane >> 4);
    int b_k = (lane & 7) + ((lane >> 3) & 1) * 8;
    int b_n8 = ((lane >> 4) & 1) * 8;

    #pragma unroll 1
    for (int it = 0; it < 16; it++) {
        int buf = it & 1;
        if (it < 15) asm volatile("cp.async.wait_group 1;" ::: "memory");
        else         asm volatile("cp.async.wait_group 0;" ::: "memory");
        __syncthreads();
        uint32_t base = sb + buf * STG;
        #pragma unroll
        for (int kk = 0; kk < 4; kk++) {
            uint32_t aF[2][4];
            #pragma unroll
            for (int mt = 0; mt < 2; mt++) {
                uint32_t off = swA((uint32_t)((a_r + mt * 16) * 128 + (kk * 2 + a_ch) * 16));
                ldsm4(aF[mt], base + off);
            }
            uint32_t bF[4][4];
            #pragma unroll
            for (int p = 0; p < 4; p++) {
                int nb = wn * 64 + p * 16 + b_n8;
                uint32_t off = swB((uint32_t)((kk * 16 + b_k) * 256 + nb * 2));
                ldsm4t(bF[p], base + 16384 + off);
            }
            #pragma unroll
            for (int mt = 0; mt < 2; mt++) {
                #pragma unroll
                for (int p = 0; p < 4; p++) {
                    mma_f16(acc[mt][2 * p],     aF[mt], bF[p][0], bF[p][1]);
                    mma_f16(acc[mt][2 * p + 1], aF[mt], bF[p][2], bF[p][3]);
                }
            }
        }
        __syncthreads();
        if (it + 2 < 16) load_stage(it + 2);
    }

    int r_lo = lane >> 2;
    int c_lo = (lane & 3) * 2;
    __half* Y = (row0 < 1024) ? Y1 : Y2;
    int rbase = (row0 < 1024) ? row0 : (row0 - 1024);
    #pragma unroll
    for (int mt = 0; mt < 2; mt++) {
        int r = rbase + wm * 32 + mt * 16 + r_lo;
        #pragma unroll
        for (int nt = 0; nt < 8; nt++) {
            int c = col0 + wn * 64 + nt * 8 + c_lo;
            st2h(Y, (size_t)r * LD + c,       acc[mt][nt][0], acc[mt][nt][1]);
            st2h(Y, (size_t)(r + 8) * LD + c, acc[mt][nt][2], acc[mt][nt][3]);
        }
    }
}

// ---------------- fp16 HMMA weight matmul + GRU epilogue (+ optional fused proj) ----------------
template <int C, bool GATE, bool PROJ>
__global__ void __launch_bounds__(256, 2) cell_mm(
    const __half* __restrict__ F0, const __half* __restrict__ F1, const __half* __restrict__ F2,
    const __half* __restrict__ Wimg, const float* __restrict__ bias,
    const float* __restrict__ hin, float* __restrict__ rbuf,
    __half* __restrict__ outC, float* __restrict__ hout, int offn,
    const float* __restrict__ pW, const float* __restrict__ pb,
    float* __restrict__ go, float* __restrict__ out, int t)
{
    constexpr int Fall = GATE ? 128 : 64;
    constexpr int NP   = GATE ? 2 : 1;
    constexpr int BIMG = 208 * 128;
    constexpr int WIMG = Fall * 432;
    constexpr int OFF  = C - 64;
    extern __shared__ __align__(16) char sm[];
    char* Bm = sm;
    char* Wm = sm + BIMG;
    float* bs    = (float*)(Wm + WIMG);
    float* wproj = bs + Fall;        // [64]
    float* sred  = wproj + 64;       // [2][64]
    int n = blockIdx.x, tid = threadIdx.x;
    int lane = tid & 31, wid = tid >> 5;
    uint32_t bB = smem_u32(Bm);
    uint32_t bW = smem_u32(Wm);

    const __half* src[3] = {F0 + (size_t)n * LD, F1 + (size_t)n * LD, F2 + (size_t)n * LD};

    for (int i = tid; i < 1664; i += 256) {
        int k = i >> 3, ch = i & 7;
        uint32_t sw = swA((uint32_t)(k * 128 + ch * 16));
        if (k < 3 * C) {
            int kk = k / C, c = k - kk * C;
            cpa16(bB + sw, src[kk] + c * 64 + ch * 8);
        } else {
            *(uint4*)(Bm + sw) = make_uint4(0, 0, 0, 0);
        }
    }
    for (int i = tid; i < Fall * 27; i += 256) {
        int f = i / 27, ch = i - f * 27;
        cpa16(bW + f * 432 + ch * 16, Wimg + f * 216 + ch * 8);
    }
    if (tid < Fall) {
        bs[tid] = bias[tid];
        if (PROJ && tid < 64) wproj[tid] = pW[tid];
    }
    asm volatile("cp.async.commit_group;" ::: "memory");
    asm volatile("cp.async.wait_group 0;" ::: "memory");
    __syncthreads();

    int wm = GATE ? (wid & 3) : (wid & 1);
    int wn = GATE ? (wid >> 2) : (wid >> 1);
    int f0 = wm * 32;
    int nb0 = wn * (GATE ? 32 : 16);
    int bk  = (lane & 7) + ((lane >> 3) & 1) * 8;
    int bn8 = ((lane >> 4) & 1) * 8;

    float acc[2][2 * NP][4];
    #pragma unroll
    for (int mt = 0; mt < 2; mt++)
        #pragma unroll
        for (int nt = 0; nt < 2 * NP; nt++)
            #pragma unroll
            for (int j = 0; j < 4; j++) acc[mt][nt][j] = 0.f;

    #pragma unroll 1
    for (int kt = 0; kt < 13; kt++) {
        uint32_t aF[2][4];
        #pragma unroll
        for (int mt = 0; mt < 2; mt++) {
            uint32_t ao = (uint32_t)((f0 + mt * 16 + (lane & 15)) * 432 + kt * 32 + (lane >> 4) * 16);
            ldsm4(aF[mt], bW + ao);
        }
        #pragma unroll
        for (int p = 0; p < NP; p++) {
            uint32_t bo = swA((uint32_t)((kt * 16 + bk) * 128 + (nb0 + p * 16 + bn8) * 2));
            uint32_t bF[4];
            ldsm4t(bF, bB + bo);
            #pragma unroll
            for (int mt = 0; mt < 2; mt++) {
                mma_f16(acc[mt][2 * p],     aF[mt], bF[0], bF[1]);
                mma_f16(acc[mt][2 * p + 1], aF[mt], bF[2], bF[3]);
            }
        }
    }

    // epilogue
    int r_lo = lane >> 2, c_lo = (lane & 3) * 2;
    size_t nLD = (size_t)n * LD;
    size_t nH  = (size_t)n * 4096;
    float ps[4] = {0.f, 0.f, 0.f, 0.f};   // proj partials: [nt*2 + {0,1}]
    #pragma unroll
    for (int mt = 0; mt < 2; mt++) {
        int row = f0 + mt * 16 + r_lo;
        #pragma unroll
        for (int nt = 0; nt < 2 * NP; nt++) {
            int col = nb0 + nt * 8 + c_lo;
            float v0 = acc[mt][nt][0] + bs[row];
            float v1 = acc[mt][nt][1] + bs[row];
            float v2 = acc[mt][nt][2] + bs[row + 8];
            float v3 = acc[mt][nt][3] + bs[row + 8];
            if (GATE) {
                if (row < 64) {
                    #pragma unroll
                    for (int q = 0; q < 2; q++) {
                        int f = row + q * 8;
                        float z0 = 1.f / (1.f + expf(-(q ? v2 : v0)));
                        float z1 = 1.f / (1.f + expf(-(q ? v3 : v1)));
                        float2 hv = *(const float2*)(hin + nH + (size_t)f * 64 + col);
                        st2h(outC, nLD + (size_t)(OFF + f) * 64 + col, z0 * hv.x, z1 * hv.y);
                    }
                } else {
                    #pragma unroll
                    for (int q = 0; q < 2; q++) {
                        int f = row - 64 + q * 8;
                        float r0 = 1.f / (1.f + expf(-(q ? v2 : v0)));
                        float r1 = 1.f / (1.f + expf(-(q ? v3 : v1)));
                        *(float2*)(rbuf + nH + (size_t)f * 64 + col) = make_float2(r0, r1);
                    }
                }
            } else {
                #pragma unroll
                for (int q = 0; q < 2; q++) {
                    int f = row + q * 8;
                    float hc0 = tanhf(q ? v2 : v0);
                    float hc1 = tanhf(q ? v3 : v1);
                    float2 rv = *(const float2*)(rbuf + nH + (size_t)f * 64 + col);
                    float2 hv = *(const float2*)(hin  + nH + (size_t)f * 64 + col);
                    float hn0 = rv.x * hv.x + (1.f - rv.x) * hc0;
                    float hn1 = rv.y * hv.y + (1.f - rv.y) * hc1;
                    *(float2*)(hout + nH + (size_t)f * 64 + col) = make_float2(hn0, hn1);
                    st2h(outC, nLD + (size_t)(offn + f) * 64 + col, hn0, hn1);
                    if (PROJ) {
                        float w = wproj[f];
                        ps[nt * 2 + 0] = fmaf(hn0, w, ps[nt * 2 + 0]);
                        ps[nt * 2 + 1] = fmaf(hn1, w, ps[nt * 2 + 1]);
                    }
                }
            }
        }
    }
    if (PROJ) {
        // reduce over r_lo lanes (stride 4, 8, 16 within warp)
        #pragma unroll
        for (int j = 0; j < 4; j++) {
            #pragma unroll
            for (int o = 4; o <= 16; o <<= 1)
                ps[j] += __shfl_xor_sync(0xffffffffu, ps[j], o);
        }
        if (lane < 4) {
            #pragma unroll
            for (int nt = 0; nt < 2; nt++) {
                int col = nb0 + nt * 8 + (lane & 3) * 2;
                sred[wm * 64 + col]     = ps[nt * 2 + 0];
                sred[wm * 64 + col + 1] = ps[nt * 2 + 1];
            }
        }
        __syncthreads();
        if (tid < 64) {
            float v = sred[tid] + sred[64 + tid] + pb[0];
            go[n * 64 + tid] = v;
            out[(size_t)(tid * TT + t) * NN + n] = v;
        }
    }
}

// ---------------- per-step column injection ----------------
__global__ void inject_enc(const float* __restrict__ x, int t,
                           __half* __restrict__ c1, __half* __restrict__ c2) {
    int n = blockIdx.x, b = threadIdx.x;
    __half v = __float2half(x[(size_t)(b * TT + t) * NN + n]);
    size_t pos = (size_t)n * LD + b;
    c1[pos] = v;
    c2[pos] = v;
}
__global__ void inject_dec(const float* __restrict__ yc, int t, const float* __restrict__ go,
                           __half* __restrict__ c1, __half* __restrict__ c2) {
    int n = blockIdx.x, b = threadIdx.x;
    __half v0 = __float2half(go[n * 64 + b]);
    __half v1 = __float2half(yc[(size_t)(b * TT + t) * NN + n]);
    size_t pos = (size_t)n * LD + b;
    c1[pos] = v0; c2[pos] = v0;
    c1[pos + 64] = v1; c2[pos + 64] = v1;
}

// ---------------- orchestration ----------------
extern "C" void kernel_launch(void* const* d_in, const int* in_sizes, int n_in,
                              void* d_out, int out_size) {
    const float* x    = (const float*)d_in[0];
    const float* ycov = (const float*)d_in[1];
    const float* emb  = (const float*)d_in[2];
    const float* egW  = (const float*)d_in[3];
    const float* egb  = (const float*)d_in[4];
    const float* euW  = (const float*)d_in[5];
    const float* eub  = (const float*)d_in[6];
    const float* dgW  = (const float*)d_in[7];
    const float* dgb  = (const float*)d_in[8];
    const float* duW  = (const float*)d_in[9];
    const float* dub  = (const float*)d_in[10];
    const float* pW   = (const float*)d_in[11];
    const float* pb   = (const float*)d_in[12];
    float* out = (float*)d_out;

    float *pM, *ph, *pr, *pgo;
    __half *pMh, *pc1, *pc2, *pY1, *pY2, *pWgE, *pWgD, *pWuE, *pWuD;
    cudaGetSymbolAddress((void**)&pM,   g_M);
    cudaGetSymbolAddress((void**)&pMh,  g_Mh);
    cudaGetSymbolAddress((void**)&pc1,  g_c1);
    cudaGetSymbolAddress((void**)&pc2,  g_c2);
    cudaGetSymbolAddress((void**)&pY1,  g_Y1);
    cudaGetSymbolAddress((void**)&pY2,  g_Y2);
    cudaGetSymbolAddress((void**)&ph,   g_h);
    cudaGetSymbolAddress((void**)&pr,   g_r);
    cudaGetSymbolAddress((void**)&pgo,  g_go);
    cudaGetSymbolAddress((void**)&pWgE, g_WgE);
    cudaGetSymbolAddress((void**)&pWgD, g_WgD);
    cudaGetSymbolAddress((void**)&pWuE, g_WuE);
    cudaGetSymbolAddress((void**)&pWuD, g_WuD);

    const int smHM = 2 * STG;                                   // 65536
    const int smG  = 208 * 128 + 128 * 432 + (128 + 64 + 128) * 4;  // 83,200
    const int smU  = 208 * 128 + 64 * 432 + (64 + 64 + 128) * 4;    // 55,296
    cudaFuncSetAttribute((const void*)hmma_gemm,                  cudaFuncAttributeMaxDynamicSharedMemorySize, smHM);
    cudaFuncSetAttribute((const void*)cell_mm<65, true,  false>,  cudaFuncAttributeMaxDynamicSharedMemorySize, smG);
    cudaFuncSetAttribute((const void*)cell_mm<66, true,  false>,  cudaFuncAttributeMaxDynamicSharedMemorySize, smG);
    cudaFuncSetAttribute((const void*)cell_mm<65, false, false>,  cudaFuncAttributeMaxDynamicSharedMemorySize, smU);
    cudaFuncSetAttribute((const void*)cell_mm<66, false, true>,   cudaFuncAttributeMaxDynamicSharedMemorySize, smU);

    cudaMemsetAsync(ph,  0, (size_t)NN * 64 * 64 * sizeof(float));
    cudaMemsetAsync(pgo, 0, (size_t)NN * 64 * sizeof(float));
    cudaMemsetAsync(pc1, 0, (size_t)NN * LD * sizeof(__half));
    cudaMemsetAsync(pc2, 0, (size_t)NN * LD * sizeof(__half));

    build_support_kernel<<<NN, 256>>>(emb, pM);
    gemmA2<<<dim3(8, 8), 256>>>(pM, pM + (size_t)NN * NN);
    convert_M<<<2 * NN * NN / 256, 256>>>(pM, pMh);
    prep_W<<<128, 64>>>(egW, 65, 128, pWgE);
    prep_W<<<128, 64>>>(dgW, 66, 128, pWgD);
    prep_W<<<64, 64>>>(euW, 65, 64, pWuE);
    prep_W<<<64, 64>>>(duW, 66, 64, pWuD);

    dim3 gg(33, 16);
    for (int t = 0; t < TT; t++) {
        inject_enc<<<NN, 64>>>(x, t, pc1, pc2);
        hmma_gemm<<<gg, 256, smHM>>>(pMh, pc1, pY1, pY2);
        cell_mm<65, true, false><<<NN, 256, smG>>>(pc1, pY1, pY2, pWgE, egb, ph, pr, pc2, nullptr, 0,
                                                   nullptr, nullptr, nullptr, nullptr, 0);
        hmma_gemm<<<gg, 256, smHM>>>(pMh, pc2, pY1, pY2);
        int offn = (t == TT - 1) ? 2 : 1;
        cell_mm<65, false, false><<<NN, 256, smU>>>(pc2, pY1, pY2, pWuE, eub, ph, pr, pc1, ph, offn,
                                                    nullptr, nullptr, nullptr, nullptr, 0);
    }
    for (int t = 0; t < TT; t++) {
        inject_dec<<<NN, 64>>>(ycov, t, pgo, pc1, pc2);
        hmma_gemm<<<gg, 256, smHM>>>(pMh, pc1, pY1, pY2);
        cell_mm<66, true, false><<<NN, 256, smG>>>(pc1, pY1, pY2, pWgD, dgb, ph, pr, pc2, nullptr, 0,
                                                   nullptr, nullptr, nullptr, nullptr, 0);
        hmma_gemm<<<gg, 256, smHM>>>(pMh, pc2, pY1, pY2);
        cell_mm<66, false, true><<<NN, 256, smU>>>(pc2, pY1, pY2, pWuD, dub, ph, pr, pc1, ph, 2,
                                                   pW, pb, pgo, out, t);
    }
}

// round 16
// speedup vs baseline: 4.0439x; 1.0353x over previous
#include <cuda_runtime.h>
#include <cuda_fp16.h>
#include <math.h>
#include <stdint.h>

#define NN 1024
#define TT 12
#define LD 4352   // padded cols; GEMM covers 33*128 = 4224
#define GRID_CELL 296

// ---------------- scratch ----------------
__device__ float g_M [2 * NN * NN];
__device__ __align__(256) __half g_Mh[2 * NN * NN];   // fp16 of [A ; 2*A2]
__device__ __align__(256) __half g_c1[NN * LD];       // cat1 fp16, c-major [n][c*64+b]
__device__ __align__(256) __half g_c2[NN * LD];
__device__ __align__(256) __half g_Y1[NN * LD];
__device__ __align__(256) __half g_Y2[NN * LD];       // holds 2*A2@X (W-folded -X)
__device__ float g_h [NN * 64 * 64];                  // [n][f*64+b]
__device__ float g_r [NN * 64 * 64];
__device__ float g_go[NN * 64];
// W images: [Fall][216] fp16 (k padded to 216; rows k<C hold W1-W3 fold)
__device__ __align__(256) __half g_WgE[128 * 216];
__device__ __align__(256) __half g_WgD[128 * 216];
__device__ __align__(256) __half g_WuE[64 * 216];
__device__ __align__(256) __half g_WuD[64 * 216];

// ---------------- helpers ----------------
__device__ __forceinline__ uint32_t smem_u32(const void* p) {
    uint32_t a;
    asm("{ .reg .u64 t; cvta.to.shared.u64 t, %1; cvt.u32.u64 %0, t; }" : "=r"(a) : "l"(p));
    return a;
}
__device__ __forceinline__ void cpa16(uint32_t dst, const void* src) {
    asm volatile("cp.async.cg.shared.global [%0], [%1], 16;" :: "r"(dst), "l"(src));
}
__device__ __forceinline__ void ldsm4(uint32_t* r, uint32_t a) {
    asm volatile("ldmatrix.sync.aligned.m8n8.x4.shared.b16 {%0,%1,%2,%3}, [%4];"
        : "=r"(r[0]), "=r"(r[1]), "=r"(r[2]), "=r"(r[3]) : "r"(a));
}
__device__ __forceinline__ void ldsm4t(uint32_t* r, uint32_t a) {
    asm volatile("ldmatrix.sync.aligned.m8n8.x4.trans.shared.b16 {%0,%1,%2,%3}, [%4];"
        : "=r"(r[0]), "=r"(r[1]), "=r"(r[2]), "=r"(r[3]) : "r"(a));
}
__device__ __forceinline__ void mma_f16(float* d, const uint32_t* a, uint32_t b0, uint32_t b1) {
    asm volatile("mma.sync.aligned.m16n8k16.row.col.f32.f16.f16.f32 "
        "{%0,%1,%2,%3},{%4,%5,%6,%7},{%8,%9},{%0,%1,%2,%3};"
        : "+f"(d[0]), "+f"(d[1]), "+f"(d[2]), "+f"(d[3])
        : "r"(a[0]), "r"(a[1]), "r"(a[2]), "r"(a[3]), "r"(b0), "r"(b1));
}
__device__ __forceinline__ void st2h(__half* H, size_t idx, float a, float b) {
    __half2 v;
    v.x = __float2half(a);
    v.y = __float2half(b);
    *reinterpret_cast<__half2*>(H + idx) = v;
}
__device__ __forceinline__ uint32_t swA(uint32_t off) { return off ^ ((off >> 3) & 0x70); }
__device__ __forceinline__ uint32_t swB(uint32_t off) { return off ^ (((off >> 8) & 7) << 4); }

// ---------------- support: A = softmax(relu(E E^T), rows) ----------------
__global__ void build_support_kernel(const float* __restrict__ emb, float* __restrict__ A) {
    __shared__ float se[NN * 8];
    __shared__ float row[NN];
    __shared__ float wred[8];
    __shared__ float red;
    int n = blockIdx.x, tid = threadIdx.x;
    for (int i = tid; i < NN * 8; i += 256) se[i] = emb[i];
    __syncthreads();
    float e[8];
    #pragma unroll
    for (int j = 0; j < 8; j++) e[j] = se[n * 8 + j];
    float mx = 0.f;
    for (int m = tid; m < NN; m += 256) {
        const float* em = &se[m * 8];
        float s = 0.f;
        #pragma unroll
        for (int j = 0; j < 8; j++) s += e[j] * em[j];
        s = fmaxf(s, 0.f);
        row[m] = s;
        mx = fmaxf(mx, s);
    }
    #pragma unroll
    for (int o = 16; o; o >>= 1) mx = fmaxf(mx, __shfl_xor_sync(0xffffffffu, mx, o));
    if ((tid & 31) == 0) wred[tid >> 5] = mx;
    __syncthreads();
    if (tid == 0) { float v = wred[0]; for (int w = 1; w < 8; w++) v = fmaxf(v, wred[w]); red = v; }
    __syncthreads();
    float bmax = red, sum = 0.f;
    for (int m = tid; m < NN; m += 256) { float v = expf(row[m] - bmax); row[m] = v; sum += v; }
    #pragma unroll
    for (int o = 16; o; o >>= 1) sum += __shfl_xor_sync(0xffffffffu, sum, o);
    if ((tid & 31) == 0) wred[tid >> 5] = sum;
    __syncthreads();
    if (tid == 0) { float v = 0.f; for (int w = 0; w < 8; w++) v += wred[w]; red = v; }
    __syncthreads();
    float inv = 1.f / red;
    for (int m = tid; m < NN; m += 256) A[n * NN + m] = row[m] * inv;
}

// ---------------- A2 = A @ A ----------------
__global__ void __launch_bounds__(256, 2) gemmA2(const float* __restrict__ A, float* __restrict__ A2) {
    __shared__ __align__(16) float As[2][8][132];
    __shared__ __align__(16) float Bs[2][8][128];
    int tid = threadIdx.x;
    int row0 = blockIdx.y * 128, col0 = blockIdx.x * 128;
    int arow = tid >> 1, acol4 = (tid & 1) << 2;
    int brow = tid >> 5, bcol4 = (tid & 31) << 2;
    int tx = tid & 15, ty = tid >> 4;
    const float* Ap = A + (size_t)(row0 + arow) * NN + acol4;
    const float* Xp = A + (size_t)brow * NN + col0 + bcol4;
    float acc[8][8];
    #pragma unroll
    for (int i = 0; i < 8; i++)
        #pragma unroll
        for (int j = 0; j < 8; j++) acc[i][j] = 0.f;
    float4 av = *(const float4*)Ap;
    float4 bv = *(const float4*)Xp;
    int buf = 0;
    As[0][acol4 + 0][arow] = av.x; As[0][acol4 + 1][arow] = av.y;
    As[0][acol4 + 2][arow] = av.z; As[0][acol4 + 3][arow] = av.w;
    *(float4*)&Bs[0][brow][bcol4] = bv;
    __syncthreads();
    for (int kt = 1; kt < 128; kt++) {
        av = *(const float4*)(Ap + kt * 8);
        bv = *(const float4*)(Xp + (size_t)(kt * 8) * NN);
        #pragma unroll
        for (int kk = 0; kk < 8; kk++) {
            float4 a0 = *(const float4*)&As[buf][kk][ty * 4];
            float4 a1 = *(const float4*)&As[buf][kk][64 + ty * 4];
            float4 b0 = *(const float4*)&Bs[buf][kk][tx * 4];
            float4 b1 = *(const float4*)&Bs[buf][kk][64 + tx * 4];
            float a[8] = {a0.x,a0.y,a0.z,a0.w,a1.x,a1.y,a1.z,a1.w};
            float b[8] = {b0.x,b0.y,b0.z,b0.w,b1.x,b1.y,b1.z,b1.w};
            #pragma unroll
            for (int i = 0; i < 8; i++)
                #pragma unroll
                for (int j = 0; j < 8; j++) acc[i][j] = fmaf(a[i], b[j], acc[i][j]);
        }
        buf ^= 1;
        As[buf][acol4 + 0][arow] = av.x; As[buf][acol4 + 1][arow] = av.y;
        As[buf][acol4 + 2][arow] = av.z; As[buf][acol4 + 3][arow] = av.w;
        *(float4*)&Bs[buf][brow][bcol4] = bv;
        __syncthreads();
    }
    #pragma unroll
    for (int kk = 0; kk < 8; kk++) {
        float4 a0 = *(const float4*)&As[buf][kk][ty * 4];
        float4 a1 = *(const float4*)&As[buf][kk][64 + ty * 4];
        float4 b0 = *(const float4*)&Bs[buf][kk][tx * 4];
        float4 b1 = *(const float4*)&Bs[buf][kk][64 + tx * 4];
        float a[8] = {a0.x,a0.y,a0.z,a0.w,a1.x,a1.y,a1.z,a1.w};
        float b[8] = {b0.x,b0.y,b0.z,b0.w,b1.x,b1.y,b1.z,b1.w};
        #pragma unroll
        for (int i = 0; i < 8; i++)
            #pragma unroll
            for (int j = 0; j < 8; j++) acc[i][j] = fmaf(a[i], b[j], acc[i][j]);
    }
    #pragma unroll
    for (int i = 0; i < 8; i++) {
        int grow = row0 + ((i < 4) ? (ty * 4 + i) : (64 + ty * 4 + i - 4));
        float* yp = A2 + (size_t)grow * NN;
        *(float4*)(yp + col0 + tx * 4)       = make_float4(acc[i][0], acc[i][1], acc[i][2], acc[i][3]);
        *(float4*)(yp + col0 + 64 + tx * 4)  = make_float4(acc[i][4], acc[i][5], acc[i][6], acc[i][7]);
    }
}

// ---------------- M -> fp16 (fold 2x into bottom half) ----------------
__global__ void convert_M(const float* __restrict__ M, __half* __restrict__ Mh) {
    int i = blockIdx.x * 256 + threadIdx.x;
    float v = M[i];
    if (i >= NN * NN) v *= 2.f;
    Mh[i] = __float2half(v);
}

// ---------------- W^T image prep: fp16 [Fall][216], rows k<C folded W1-W3 ----------------
__global__ void prep_W(const float* __restrict__ W, int C, int Fall,
                       __half* __restrict__ img) {
    int f = blockIdx.x;
    int K3 = 3 * C;
    for (int k = threadIdx.x; k < 216; k += 64) {
        float v = 0.f;
        if (k < K3) {
            v = W[k * Fall + f];
            if (k < C) v -= W[(2 * C + k) * Fall + f];
        }
        img[f * 216 + k] = __float2half(v);
    }
}

// ---------------- fp16 HMMA diffusion GEMM ----------------
#define KC 64
#define STG 32768
__global__ void __launch_bounds__(256, 2) hmma_gemm(
    const __half* __restrict__ Mh, const __half* __restrict__ X,
    __half* __restrict__ Y1, __half* __restrict__ Y2)
{
    extern __shared__ __align__(1024) char smem[];
    uint32_t sb = smem_u32(smem);
    int tid = threadIdx.x;
    int lane = tid & 31, wid = tid >> 5;
    int wm = wid >> 1, wn = wid & 1;
    int row0 = blockIdx.y * 128;
    int col0 = blockIdx.x * 128;

    float acc[2][8][4];
    #pragma unroll
    for (int mt = 0; mt < 2; mt++)
        #pragma unroll
        for (int nt = 0; nt < 8; nt++)
            #pragma unroll
            for (int j = 0; j < 4; j++) acc[mt][nt][j] = 0.f;

    auto load_stage = [&](int it) {
        uint32_t base = sb + (it & 1) * STG;
        int k0 = it * KC;
        #pragma unroll
        for (int i = tid; i < 1024; i += 256) {
            int r = i >> 3, c = i & 7;
            uint32_t sw = swA((uint32_t)(r * 128 + c * 16));
            cpa16(base + sw, Mh + (size_t)(row0 + r) * NN + k0 + c * 8);
        }
        #pragma unroll
        for (int i = tid; i < 1024; i += 256) {
            int k = i >> 4, c = i & 15;
            uint32_t sw = swB((uint32_t)(k * 256 + c * 16));
            cpa16(base + 16384 + sw, X + (size_t)(k0 + k) * LD + col0 + c * 8);
        }
        asm volatile("cp.async.commit_group;" ::: "memory");
    };

    load_stage(0);
    load_stage(1);

    int a_r = wm * 32 + (lane & 15);
    int a_ch = (lane >> 4);
    int b_k = (lane & 7) + ((lane >> 3) & 1) * 8;
    int b_n8 = ((lane >> 4) & 1) * 8;

    #pragma unroll 1
    for (int it = 0; it < 16; it++) {
        int buf = it & 1;
        if (it < 15) asm volatile("cp.async.wait_group 1;" ::: "memory");
        else         asm volatile("cp.async.wait_group 0;" ::: "memory");
        __syncthreads();
        uint32_t base = sb + buf * STG;
        #pragma unroll
        for (int kk = 0; kk < 4; kk++) {
            uint32_t aF[2][4];
            #pragma unroll
            for (int mt = 0; mt < 2; mt++) {
                uint32_t off = swA((uint32_t)((a_r + mt * 16) * 128 + (kk * 2 + a_ch) * 16));
                ldsm4(aF[mt], base + off);
            }
            uint32_t bF[4][4];
            #pragma unroll
            for (int p = 0; p < 4; p++) {
                int nb = wn * 64 + p * 16 + b_n8;
                uint32_t off = swB((uint32_t)((kk * 16 + b_k) * 256 + nb * 2));
                ldsm4t(bF[p], base + 16384 + off);
            }
            #pragma unroll
            for (int mt = 0; mt < 2; mt++) {
                #pragma unroll
                for (int p = 0; p < 4; p++) {
                    mma_f16(acc[mt][2 * p],     aF[mt], bF[p][0], bF[p][1]);
                    mma_f16(acc[mt][2 * p + 1], aF[mt], bF[p][2], bF[p][3]);
                }
            }
        }
        __syncthreads();
        if (it + 2 < 16) load_stage(it + 2);
    }

    int r_lo = lane >> 2;
    int c_lo = (lane & 3) * 2;
    __half* Y = (row0 < 1024) ? Y1 : Y2;
    int rbase = (row0 < 1024) ? row0 : (row0 - 1024);
    #pragma unroll
    for (int mt = 0; mt < 2; mt++) {
        int r = rbase + wm * 32 + mt * 16 + r_lo;
        #pragma unroll
        for (int nt = 0; nt < 8; nt++) {
            int c = col0 + wn * 64 + nt * 8 + c_lo;
            st2h(Y, (size_t)r * LD + c,       acc[mt][nt][0], acc[mt][nt][1]);
            st2h(Y, (size_t)(r + 8) * LD + c, acc[mt][nt][2], acc[mt][nt][3]);
        }
    }
}

// ---------------- multi-node pipelined cell_mm: W loaded once, feats double-buffered ----------------
template <int C, bool GATE, bool PROJ>
__global__ void __launch_bounds__(256, 2) cell_mm(
    const __half* __restrict__ F0, const __half* __restrict__ F1, const __half* __restrict__ F2,
    const __half* __restrict__ Wimg, const float* __restrict__ bias,
    const float* __restrict__ hin, float* __restrict__ rbuf,
    __half* __restrict__ outC, float* __restrict__ hout, int offn,
    const float* __restrict__ pW, const float* __restrict__ pb,
    float* __restrict__ go, float* __restrict__ out, int t)
{
    constexpr int Fall = GATE ? 128 : 64;
    constexpr int NP   = GATE ? 2 : 1;
    constexpr int BIMG = 208 * 128;
    constexpr int WIMG = Fall * 432;
    constexpr int OFF  = C - 64;
    constexpr int K3   = 3 * C;
    extern __shared__ __align__(16) char sm[];
    char* Bm0 = sm;                       // two feats buffers
    char* Wm  = sm + 2 * BIMG;
    float* bs    = (float*)(Wm + WIMG);
    float* wproj = bs + Fall;
    float* sred  = wproj + 64;
    int tid = threadIdx.x;
    int lane = tid & 31, wid = tid >> 5;
    uint32_t bB0 = smem_u32(Bm0);
    uint32_t bW  = smem_u32(Wm);

    // zero padding rows (node-invariant) in both buffers
    #pragma unroll 1
    for (int buf = 0; buf < 2; buf++)
        for (int i = tid; i < (208 - K3) * 8; i += 256) {
            int k = K3 + (i >> 3), ch = i & 7;
            *(uint4*)(Bm0 + buf * BIMG + swA((uint32_t)(k * 128 + ch * 16))) = make_uint4(0, 0, 0, 0);
        }
    // W image + bias (once per CTA)
    for (int i = tid; i < Fall * 27; i += 256) {
        int f = i / 27, ch = i - f * 27;
        cpa16(bW + f * 432 + ch * 16, Wimg + f * 216 + ch * 8);
    }
    if (tid < Fall) {
        bs[tid] = bias[tid];
        if (PROJ && tid < 64) wproj[tid] = pW[tid];
    }

    auto load_feats = [&](int buf, int n) {
        const __half* s0 = F0 + (size_t)n * LD;
        const __half* s1 = F1 + (size_t)n * LD;
        const __half* s2 = F2 + (size_t)n * LD;
        uint32_t base = bB0 + buf * BIMG;
        for (int i = tid; i < K3 * 8; i += 256) {
            int k = i >> 3, ch = i & 7;
            int kk = k / C, c = k - kk * C;
            const __half* s = (kk == 0) ? s0 : ((kk == 1) ? s1 : s2);
            cpa16(base + swA((uint32_t)(k * 128 + ch * 16)), s + c * 64 + ch * 8);
        }
        asm volatile("cp.async.commit_group;" ::: "memory");
    };

    int nth = gridDim.x;
    int count = (NN - blockIdx.x + nth - 1) / nth;
    load_feats(0, blockIdx.x);   // group 0 (includes the W cp.asyncs above)

    int wm = GATE ? (wid & 3) : (wid & 1);
    int wn = GATE ? (wid >> 2) : (wid >> 1);
    int f0 = wm * 32;
    int nb0 = wn * (GATE ? 32 : 16);
    int bk  = (lane & 7) + ((lane >> 3) & 1) * 8;
    int bn8 = ((lane >> 4) & 1) * 8;
    int r_lo = lane >> 2, c_lo = (lane & 3) * 2;

    #pragma unroll 1
    for (int i = 0; i < count; i++) {
        int n = blockIdx.x + i * nth;
        int buf = i & 1;
        if (i + 1 < count) {
            load_feats(buf ^ 1, n + nth);
            asm volatile("cp.async.wait_group 1;" ::: "memory");
        } else {
            asm volatile("cp.async.wait_group 0;" ::: "memory");
        }
        __syncthreads();
        uint32_t bB = bB0 + buf * BIMG;

        float acc[2][2 * NP][4];
        #pragma unroll
        for (int mt = 0; mt < 2; mt++)
            #pragma unroll
            for (int nt = 0; nt < 2 * NP; nt++)
                #pragma unroll
                for (int j = 0; j < 4; j++) acc[mt][nt][j] = 0.f;

        #pragma unroll 1
        for (int kt = 0; kt < 13; kt++) {
            uint32_t aF[2][4];
            #pragma unroll
            for (int mt = 0; mt < 2; mt++) {
                uint32_t ao = (uint32_t)((f0 + mt * 16 + (lane & 15)) * 432 + kt * 32 + (lane >> 4) * 16);
                ldsm4(aF[mt], bW + ao);
            }
            #pragma unroll
            for (int p = 0; p < NP; p++) {
                uint32_t bo = swA((uint32_t)((kt * 16 + bk) * 128 + (nb0 + p * 16 + bn8) * 2));
                uint32_t bF[4];
                ldsm4t(bF, bB + bo);
                #pragma unroll
                for (int mt = 0; mt < 2; mt++) {
                    mma_f16(acc[mt][2 * p],     aF[mt], bF[0], bF[1]);
                    mma_f16(acc[mt][2 * p + 1], aF[mt], bF[2], bF[3]);
                }
            }
        }

        // epilogue for node n
        size_t nLD = (size_t)n * LD;
        size_t nH  = (size_t)n * 4096;
        float ps[4] = {0.f, 0.f, 0.f, 0.f};
        #pragma unroll
        for (int mt = 0; mt < 2; mt++) {
            int row = f0 + mt * 16 + r_lo;
            #pragma unroll
            for (int nt = 0; nt < 2 * NP; nt++) {
                int col = nb0 + nt * 8 + c_lo;
                float v0 = acc[mt][nt][0] + bs[row];
                float v1 = acc[mt][nt][1] + bs[row];
                float v2 = acc[mt][nt][2] + bs[row + 8];
                float v3 = acc[mt][nt][3] + bs[row + 8];
                if (GATE) {
                    if (row < 64) {
                        #pragma unroll
                        for (int q = 0; q < 2; q++) {
                            int f = row + q * 8;
                            float z0 = 1.f / (1.f + expf(-(q ? v2 : v0)));
                            float z1 = 1.f / (1.f + expf(-(q ? v3 : v1)));
                            float2 hv = *(const float2*)(hin + nH + (size_t)f * 64 + col);
                            st2h(outC, nLD + (size_t)(OFF + f) * 64 + col, z0 * hv.x, z1 * hv.y);
                        }
                    } else {
                        #pragma unroll
                        for (int q = 0; q < 2; q++) {
                            int f = row - 64 + q * 8;
                            float r0 = 1.f / (1.f + expf(-(q ? v2 : v0)));
                            float r1 = 1.f / (1.f + expf(-(q ? v3 : v1)));
                            *(float2*)(rbuf + nH + (size_t)f * 64 + col) = make_float2(r0, r1);
                        }
                    }
                } else {
                    #pragma unroll
                    for (int q = 0; q < 2; q++) {
                        int f = row + q * 8;
                        float hc0 = tanhf(q ? v2 : v0);
                        float hc1 = tanhf(q ? v3 : v1);
                        float2 rv = *(const float2*)(rbuf + nH + (size_t)f * 64 + col);
                        float2 hv = *(const float2*)(hin  + nH + (size_t)f * 64 + col);
                        float hn0 = rv.x * hv.x + (1.f - rv.x) * hc0;
                        float hn1 = rv.y * hv.y + (1.f - rv.y) * hc1;
                        *(float2*)(hout + nH + (size_t)f * 64 + col) = make_float2(hn0, hn1);
                        st2h(outC, nLD + (size_t)(offn + f) * 64 + col, hn0, hn1);
                        if (PROJ) {
                            float w = wproj[f];
                            ps[nt * 2 + 0] = fmaf(hn0, w, ps[nt * 2 + 0]);
                            ps[nt * 2 + 1] = fmaf(hn1, w, ps[nt * 2 + 1]);
                        }
                    }
                }
            }
        }
        if (PROJ) {
            #pragma unroll
            for (int j = 0; j < 4; j++) {
                #pragma unroll
                for (int o = 4; o <= 16; o <<= 1)
                    ps[j] += __shfl_xor_sync(0xffffffffu, ps[j], o);
            }
            if (lane < 4) {
                #pragma unroll
                for (int nt = 0; nt < 2; nt++) {
                    int col = nb0 + nt * 8 + (lane & 3) * 2;
                    sred[wm * 64 + col]     = ps[nt * 2 + 0];
                    sred[wm * 64 + col + 1] = ps[nt * 2 + 1];
                }
            }
            __syncthreads();
            if (tid < 64) {
                float v = sred[tid] + sred[64 + tid] + pb[0];
                go[n * 64 + tid] = v;
                out[(size_t)(tid * TT + t) * NN + n] = v;
            }
        }
        __syncthreads();
    }
}

// ---------------- per-step column injection ----------------
__global__ void inject_enc(const float* __restrict__ x, int t,
                           __half* __restrict__ c1, __half* __restrict__ c2) {
    int n = blockIdx.x, b = threadIdx.x;
    __half v = __float2half(x[(size_t)(b * TT + t) * NN + n]);
    size_t pos = (size_t)n * LD + b;
    c1[pos] = v;
    c2[pos] = v;
}
__global__ void inject_dec(const float* __restrict__ yc, int t, const float* __restrict__ go,
                           __half* __restrict__ c1, __half* __restrict__ c2) {
    int n = blockIdx.x, b = threadIdx.x;
    __half v0 = __float2half(go[n * 64 + b]);
    __half v1 = __float2half(yc[(size_t)(b * TT + t) * NN + n]);
    size_t pos = (size_t)n * LD + b;
    c1[pos] = v0; c2[pos] = v0;
    c1[pos + 64] = v1; c2[pos + 64] = v1;
}

// ---------------- orchestration ----------------
extern "C" void kernel_launch(void* const* d_in, const int* in_sizes, int n_in,
                              void* d_out, int out_size) {
    const float* x    = (const float*)d_in[0];
    const float* ycov = (const float*)d_in[1];
    const float* emb  = (const float*)d_in[2];
    const float* egW  = (const float*)d_in[3];
    const float* egb  = (const float*)d_in[4];
    const float* euW  = (const float*)d_in[5];
    const float* eub  = (const float*)d_in[6];
    const float* dgW  = (const float*)d_in[7];
    const float* dgb  = (const float*)d_in[8];
    const float* duW  = (const float*)d_in[9];
    const float* dub  = (const float*)d_in[10];
    const float* pW   = (const float*)d_in[11];
    const float* pb   = (const float*)d_in[12];
    float* out = (float*)d_out;

    float *pM, *ph, *pr, *pgo;
    __half *pMh, *pc1, *pc2, *pY1, *pY2, *pWgE, *pWgD, *pWuE, *pWuD;
    cudaGetSymbolAddress((void**)&pM,   g_M);
    cudaGetSymbolAddress((void**)&pMh,  g_Mh);
    cudaGetSymbolAddress((void**)&pc1,  g_c1);
    cudaGetSymbolAddress((void**)&pc2,  g_c2);
    cudaGetSymbolAddress((void**)&pY1,  g_Y1);
    cudaGetSymbolAddress((void**)&pY2,  g_Y2);
    cudaGetSymbolAddress((void**)&ph,   g_h);
    cudaGetSymbolAddress((void**)&pr,   g_r);
    cudaGetSymbolAddress((void**)&pgo,  g_go);
    cudaGetSymbolAddress((void**)&pWgE, g_WgE);
    cudaGetSymbolAddress((void**)&pWgD, g_WgD);
    cudaGetSymbolAddress((void**)&pWuE, g_WuE);
    cudaGetSymbolAddress((void**)&pWuD, g_WuD);

    const int smHM = 2 * STG;                                        // 65536
    const int smG  = 2 * (208 * 128) + 128 * 432 + (128 + 64 + 128) * 4;  // 109,824
    const int smU  = 2 * (208 * 128) + 64 * 432 + (64 + 64 + 128) * 4;    // 81,920
    cudaFuncSetAttribute((const void*)hmma_gemm,                  cudaFuncAttributeMaxDynamicSharedMemorySize, smHM);
    cudaFuncSetAttribute((const void*)cell_mm<65, true,  false>,  cudaFuncAttributeMaxDynamicSharedMemorySize, smG);
    cudaFuncSetAttribute((const void*)cell_mm<66, true,  false>,  cudaFuncAttributeMaxDynamicSharedMemorySize, smG);
    cudaFuncSetAttribute((const void*)cell_mm<65, false, false>,  cudaFuncAttributeMaxDynamicSharedMemorySize, smU);
    cudaFuncSetAttribute((const void*)cell_mm<66, false, true>,   cudaFuncAttributeMaxDynamicSharedMemorySize, smU);

    cudaMemsetAsync(ph,  0, (size_t)NN * 64 * 64 * sizeof(float));
    cudaMemsetAsync(pgo, 0, (size_t)NN * 64 * sizeof(float));
    cudaMemsetAsync(pc1, 0, (size_t)NN * LD * sizeof(__half));
    cudaMemsetAsync(pc2, 0, (size_t)NN * LD * sizeof(__half));

    build_support_kernel<<<NN, 256>>>(emb, pM);
    gemmA2<<<dim3(8, 8), 256>>>(pM, pM + (size_t)NN * NN);
    convert_M<<<2 * NN * NN / 256, 256>>>(pM, pMh);
    prep_W<<<128, 64>>>(egW, 65, 128, pWgE);
    prep_W<<<128, 64>>>(dgW, 66, 128, pWgD);
    prep_W<<<64, 64>>>(euW, 65, 64, pWuE);
    prep_W<<<64, 64>>>(duW, 66, 64, pWuD);

    dim3 gg(33, 16);
    for (int t = 0; t < TT; t++) {
        inject_enc<<<NN, 64>>>(x, t, pc1, pc2);
        hmma_gemm<<<gg, 256, smHM>>>(pMh, pc1, pY1, pY2);
        cell_mm<65, true, false><<<GRID_CELL, 256, smG>>>(pc1, pY1, pY2, pWgE, egb, ph, pr, pc2, nullptr, 0,
                                                          nullptr, nullptr, nullptr, nullptr, 0);
        hmma_gemm<<<gg, 256, smHM>>>(pMh, pc2, pY1, pY2);
        int offn = (t == TT - 1) ? 2 : 1;
        cell_mm<65, false, false><<<GRID_CELL, 256, smU>>>(pc2, pY1, pY2, pWuE, eub, ph, pr, pc1, ph, offn,
                                                           nullptr, nullptr, nullptr, nullptr, 0);
    }
    for (int t = 0; t < TT; t++) {
        inject_dec<<<NN, 64>>>(ycov, t, pgo, pc1, pc2);
        hmma_gemm<<<gg, 256, smHM>>>(pMh, pc1, pY1, pY2);
        cell_mm<66, true, false><<<GRID_CELL, 256, smG>>>(pc1, pY1, pY2, pWgD, dgb, ph, pr, pc2, nullptr, 0,
                                                          nullptr, nullptr, nullptr, nullptr, 0);
        hmma_gemm<<<gg, 256, smHM>>>(pMh, pc2, pY1, pY2);
        cell_mm<66, false, true><<<GRID_CELL, 256, smU>>>(pc2, pY1, pY2, pWuD, dub, ph, pr, pc1, ph, 2,
                                                          pW, pb, pgo, out, t);
    }
}

// round 17
// speedup vs baseline: 4.0646x; 1.0051x over previous
#include <cuda_runtime.h>
#include <cuda_fp16.h>
#include <math.h>
#include <stdint.h>

#define NN 1024
#define TT 12
#define LD 4352   // padded cols; GEMM covers 33*128 = 4224
#define GRID_CELL 296

// ---------------- scratch ----------------
__device__ float g_M [2 * NN * NN];
__device__ __align__(256) __half g_Mh[2 * NN * NN];   // fp16 of [A ; 2*A2]
__device__ __align__(256) __half g_c1[NN * LD];       // cat1 fp16, c-major [n][c*64+b]
__device__ __align__(256) __half g_c2[NN * LD];
__device__ __align__(256) __half g_Y1[NN * LD];
__device__ __align__(256) __half g_Y2[NN * LD];       // holds 2*A2@X (W-folded -X)
__device__ float g_h [NN * 64 * 64];                  // [n][f*64+b]
__device__ float g_r [NN * 64 * 64];
// W images: [Fall][216] fp16 (k padded to 216; rows k<C hold W1-W3 fold)
__device__ __align__(256) __half g_WgE[128 * 216];
__device__ __align__(256) __half g_WgD[128 * 216];
__device__ __align__(256) __half g_WuE[64 * 216];
__device__ __align__(256) __half g_WuD[64 * 216];

// ---------------- helpers ----------------
__device__ __forceinline__ uint32_t smem_u32(const void* p) {
    uint32_t a;
    asm("{ .reg .u64 t; cvta.to.shared.u64 t, %1; cvt.u32.u64 %0, t; }" : "=r"(a) : "l"(p));
    return a;
}
__device__ __forceinline__ void cpa16(uint32_t dst, const void* src) {
    asm volatile("cp.async.cg.shared.global [%0], [%1], 16;" :: "r"(dst), "l"(src));
}
__device__ __forceinline__ void ldsm4(uint32_t* r, uint32_t a) {
    asm volatile("ldmatrix.sync.aligned.m8n8.x4.shared.b16 {%0,%1,%2,%3}, [%4];"
        : "=r"(r[0]), "=r"(r[1]), "=r"(r[2]), "=r"(r[3]) : "r"(a));
}
__device__ __forceinline__ void ldsm4t(uint32_t* r, uint32_t a) {
    asm volatile("ldmatrix.sync.aligned.m8n8.x4.trans.shared.b16 {%0,%1,%2,%3}, [%4];"
        : "=r"(r[0]), "=r"(r[1]), "=r"(r[2]), "=r"(r[3]) : "r"(a));
}
__device__ __forceinline__ void mma_f16(float* d, const uint32_t* a, uint32_t b0, uint32_t b1) {
    asm volatile("mma.sync.aligned.m16n8k16.row.col.f32.f16.f16.f32 "
        "{%0,%1,%2,%3},{%4,%5,%6,%7},{%8,%9},{%0,%1,%2,%3};"
        : "+f"(d[0]), "+f"(d[1]), "+f"(d[2]), "+f"(d[3])
        : "r"(a[0]), "r"(a[1]), "r"(a[2]), "r"(a[3]), "r"(b0), "r"(b1));
}
__device__ __forceinline__ void st2h(__half* H, size_t idx, float a, float b) {
    __half2 v;
    v.x = __float2half(a);
    v.y = __float2half(b);
    *reinterpret_cast<__half2*>(H + idx) = v;
}
__device__ __forceinline__ uint32_t swA(uint32_t off) { return off ^ ((off >> 3) & 0x70); }
__device__ __forceinline__ uint32_t swB(uint32_t off) { return off ^ (((off >> 8) & 7) << 4); }

// ---------------- support: A = softmax(relu(E E^T), rows) ----------------
__global__ void build_support_kernel(const float* __restrict__ emb, float* __restrict__ A) {
    __shared__ float se[NN * 8];
    __shared__ float row[NN];
    __shared__ float wred[8];
    __shared__ float red;
    int n = blockIdx.x, tid = threadIdx.x;
    for (int i = tid; i < NN * 8; i += 256) se[i] = emb[i];
    __syncthreads();
    float e[8];
    #pragma unroll
    for (int j = 0; j < 8; j++) e[j] = se[n * 8 + j];
    float mx = 0.f;
    for (int m = tid; m < NN; m += 256) {
        const float* em = &se[m * 8];
        float s = 0.f;
        #pragma unroll
        for (int j = 0; j < 8; j++) s += e[j] * em[j];
        s = fmaxf(s, 0.f);
        row[m] = s;
        mx = fmaxf(mx, s);
    }
    #pragma unroll
    for (int o = 16; o; o >>= 1) mx = fmaxf(mx, __shfl_xor_sync(0xffffffffu, mx, o));
    if ((tid & 31) == 0) wred[tid >> 5] = mx;
    __syncthreads();
    if (tid == 0) { float v = wred[0]; for (int w = 1; w < 8; w++) v = fmaxf(v, wred[w]); red = v; }
    __syncthreads();
    float bmax = red, sum = 0.f;
    for (int m = tid; m < NN; m += 256) { float v = expf(row[m] - bmax); row[m] = v; sum += v; }
    #pragma unroll
    for (int o = 16; o; o >>= 1) sum += __shfl_xor_sync(0xffffffffu, sum, o);
    if ((tid & 31) == 0) wred[tid >> 5] = sum;
    __syncthreads();
    if (tid == 0) { float v = 0.f; for (int w = 0; w < 8; w++) v += wred[w]; red = v; }
    __syncthreads();
    float inv = 1.f / red;
    for (int m = tid; m < NN; m += 256) A[n * NN + m] = row[m] * inv;
}

// ---------------- A2 = A @ A ----------------
__global__ void __launch_bounds__(256, 2) gemmA2(const float* __restrict__ A, float* __restrict__ A2) {
    __shared__ __align__(16) float As[2][8][132];
    __shared__ __align__(16) float Bs[2][8][128];
    int tid = threadIdx.x;
    int row0 = blockIdx.y * 128, col0 = blockIdx.x * 128;
    int arow = tid >> 1, acol4 = (tid & 1) << 2;
    int brow = tid >> 5, bcol4 = (tid & 31) << 2;
    int tx = tid & 15, ty = tid >> 4;
    const float* Ap = A + (size_t)(row0 + arow) * NN + acol4;
    const float* Xp = A + (size_t)brow * NN + col0 + bcol4;
    float acc[8][8];
    #pragma unroll
    for (int i = 0; i < 8; i++)
        #pragma unroll
        for (int j = 0; j < 8; j++) acc[i][j] = 0.f;
    float4 av = *(const float4*)Ap;
    float4 bv = *(const float4*)Xp;
    int buf = 0;
    As[0][acol4 + 0][arow] = av.x; As[0][acol4 + 1][arow] = av.y;
    As[0][acol4 + 2][arow] = av.z; As[0][acol4 + 3][arow] = av.w;
    *(float4*)&Bs[0][brow][bcol4] = bv;
    __syncthreads();
    for (int kt = 1; kt < 128; kt++) {
        av = *(const float4*)(Ap + kt * 8);
        bv = *(const float4*)(Xp + (size_t)(kt * 8) * NN);
        #pragma unroll
        for (int kk = 0; kk < 8; kk++) {
            float4 a0 = *(const float4*)&As[buf][kk][ty * 4];
            float4 a1 = *(const float4*)&As[buf][kk][64 + ty * 4];
            float4 b0 = *(const float4*)&Bs[buf][kk][tx * 4];
            float4 b1 = *(const float4*)&Bs[buf][kk][64 + tx * 4];
            float a[8] = {a0.x,a0.y,a0.z,a0.w,a1.x,a1.y,a1.z,a1.w};
            float b[8] = {b0.x,b0.y,b0.z,b0.w,b1.x,b1.y,b1.z,b1.w};
            #pragma unroll
            for (int i = 0; i < 8; i++)
                #pragma unroll
                for (int j = 0; j < 8; j++) acc[i][j] = fmaf(a[i], b[j], acc[i][j]);
        }
        buf ^= 1;
        As[buf][acol4 + 0][arow] = av.x; As[buf][acol4 + 1][arow] = av.y;
        As[buf][acol4 + 2][arow] = av.z; As[buf][acol4 + 3][arow] = av.w;
        *(float4*)&Bs[buf][brow][bcol4] = bv;
        __syncthreads();
    }
    #pragma unroll
    for (int kk = 0; kk < 8; kk++) {
        float4 a0 = *(const float4*)&As[buf][kk][ty * 4];
        float4 a1 = *(const float4*)&As[buf][kk][64 + ty * 4];
        float4 b0 = *(const float4*)&Bs[buf][kk][tx * 4];
        float4 b1 = *(const float4*)&Bs[buf][kk][64 + tx * 4];
        float a[8] = {a0.x,a0.y,a0.z,a0.w,a1.x,a1.y,a1.z,a1.w};
        float b[8] = {b0.x,b0.y,b0.z,b0.w,b1.x,b1.y,b1.z,b1.w};
        #pragma unroll
        for (int i = 0; i < 8; i++)
            #pragma unroll
            for (int j = 0; j < 8; j++) acc[i][j] = fmaf(a[i], b[j], acc[i][j]);
    }
    #pragma unroll
    for (int i = 0; i < 8; i++) {
        int grow = row0 + ((i < 4) ? (ty * 4 + i) : (64 + ty * 4 + i - 4));
        float* yp = A2 + (size_t)grow * NN;
        *(float4*)(yp + col0 + tx * 4)       = make_float4(acc[i][0], acc[i][1], acc[i][2], acc[i][3]);
        *(float4*)(yp + col0 + 64 + tx * 4)  = make_float4(acc[i][4], acc[i][5], acc[i][6], acc[i][7]);
    }
}

// ---------------- M -> fp16 (fold 2x into bottom half) ----------------
__global__ void convert_M(const float* __restrict__ M, __half* __restrict__ Mh) {
    int i = blockIdx.x * 256 + threadIdx.x;
    float v = M[i];
    if (i >= NN * NN) v *= 2.f;
    Mh[i] = __float2half(v);
}

// ---------------- W^T image prep: fp16 [Fall][216], rows k<C folded W1-W3 ----------------
__global__ void prep_W(const float* __restrict__ W, int C, int Fall,
                       __half* __restrict__ img) {
    int f = blockIdx.x;
    int K3 = 3 * C;
    for (int k = threadIdx.x; k < 216; k += 64) {
        float v = 0.f;
        if (k < K3) {
            v = W[k * Fall + f];
            if (k < C) v -= W[(2 * C + k) * Fall + f];
        }
        img[f * 216 + k] = __float2half(v);
    }
}

// ---------------- fp16 HMMA diffusion GEMM ----------------
#define KC 64
#define STG 32768
__global__ void __launch_bounds__(256, 2) hmma_gemm(
    const __half* __restrict__ Mh, const __half* __restrict__ X,
    __half* __restrict__ Y1, __half* __restrict__ Y2)
{
    extern __shared__ __align__(1024) char smem[];
    uint32_t sb = smem_u32(smem);
    int tid = threadIdx.x;
    int lane = tid & 31, wid = tid >> 5;
    int wm = wid >> 1, wn = wid & 1;
    int row0 = blockIdx.y * 128;
    int col0 = blockIdx.x * 128;

    float acc[2][8][4];
    #pragma unroll
    for (int mt = 0; mt < 2; mt++)
        #pragma unroll
        for (int nt = 0; nt < 8; nt++)
            #pragma unroll
            for (int j = 0; j < 4; j++) acc[mt][nt][j] = 0.f;

    auto load_stage = [&](int it) {
        uint32_t base = sb + (it & 1) * STG;
        int k0 = it * KC;
        #pragma unroll
        for (int i = tid; i < 1024; i += 256) {
            int r = i >> 3, c = i & 7;
            uint32_t sw = swA((uint32_t)(r * 128 + c * 16));
            cpa16(base + sw, Mh + (size_t)(row0 + r) * NN + k0 + c * 8);
        }
        #pragma unroll
        for (int i = tid; i < 1024; i += 256) {
            int k = i >> 4, c = i & 15;
            uint32_t sw = swB((uint32_t)(k * 256 + c * 16));
            cpa16(base + 16384 + sw, X + (size_t)(k0 + k) * LD + col0 + c * 8);
        }
        asm volatile("cp.async.commit_group;" ::: "memory");
    };

    load_stage(0);
    load_stage(1);

    int a_r = wm * 32 + (lane & 15);
    int a_ch = (lane >> 4);
    int b_k = (lane & 7) + ((lane >> 3) & 1) * 8;
    int b_n8 = ((lane >> 4) & 1) * 8;

    #pragma unroll 1
    for (int it = 0; it < 16; it++) {
        int buf = it & 1;
        if (it < 15) asm volatile("cp.async.wait_group 1;" ::: "memory");
        else         asm volatile("cp.async.wait_group 0;" ::: "memory");
        __syncthreads();
        uint32_t base = sb + buf * STG;
        #pragma unroll
        for (int kk = 0; kk < 4; kk++) {
            uint32_t aF[2][4];
            #pragma unroll
            for (int mt = 0; mt < 2; mt++) {
                uint32_t off = swA((uint32_t)((a_r + mt * 16) * 128 + (kk * 2 + a_ch) * 16));
                ldsm4(aF[mt], base + off);
            }
            uint32_t bF[4][4];
            #pragma unroll
            for (int p = 0; p < 4; p++) {
                int nb = wn * 64 + p * 16 + b_n8;
                uint32_t off = swB((uint32_t)((kk * 16 + b_k) * 256 + nb * 2));
                ldsm4t(bF[p], base + 16384 + off);
            }
            #pragma unroll
            for (int mt = 0; mt < 2; mt++) {
                #pragma unroll
                for (int p = 0; p < 4; p++) {
                    mma_f16(acc[mt][2 * p],     aF[mt], bF[p][0], bF[p][1]);
                    mma_f16(acc[mt][2 * p + 1], aF[mt], bF[p][2], bF[p][3]);
                }
            }
        }
        __syncthreads();
        if (it + 2 < 16) load_stage(it + 2);
    }

    int r_lo = lane >> 2;
    int c_lo = (lane & 3) * 2;
    __half* Y = (row0 < 1024) ? Y1 : Y2;
    int rbase = (row0 < 1024) ? row0 : (row0 - 1024);
    #pragma unroll
    for (int mt = 0; mt < 2; mt++) {
        int r = rbase + wm * 32 + mt * 16 + r_lo;
        #pragma unroll
        for (int nt = 0; nt < 8; nt++) {
            int c = col0 + wn * 64 + nt * 8 + c_lo;
            st2h(Y, (size_t)r * LD + c,       acc[mt][nt][0], acc[mt][nt][1]);
            st2h(Y, (size_t)(r + 8) * LD + c, acc[mt][nt][2], acc[mt][nt][3]);
        }
    }
}

// ---------------- multi-node pipelined cell_mm ----------------
// GATE: z*h -> cat2 h-slot; r -> rbuf; copies cat1 slots [0,OFF) -> cat2.
// !GATE: GRU update -> h + next cat1 h-slot; writes next exogenous cols:
//        slot0 = nxt ? x[t=tn] : (PROJ ? go : 0);  slot1 = nyc ? ycov[t=tn] : (untouched)
template <int C, bool GATE, bool PROJ>
__global__ void __launch_bounds__(256, 2) cell_mm(
    const __half* __restrict__ F0, const __half* __restrict__ F1, const __half* __restrict__ F2,
    const __half* __restrict__ Wimg, const float* __restrict__ bias,
    const float* __restrict__ hin, float* __restrict__ rbuf,
    __half* __restrict__ outC, float* __restrict__ hout, int offn,
    const float* __restrict__ nxt, const float* __restrict__ nyc, int tn,
    const float* __restrict__ pW, const float* __restrict__ pb,
    float* __restrict__ out, int t)
{
    constexpr int Fall = GATE ? 128 : 64;
    constexpr int NP   = GATE ? 2 : 1;
    constexpr int BIMG = 208 * 128;
    constexpr int WIMG = Fall * 432;
    constexpr int OFF  = C - 64;
    constexpr int K3   = 3 * C;
    extern __shared__ __align__(16) char sm[];
    char* Bm0 = sm;
    char* Wm  = sm + 2 * BIMG;
    float* bs    = (float*)(Wm + WIMG);
    float* wproj = bs + Fall;
    float* sred  = wproj + 64;
    int tid = threadIdx.x;
    int lane = tid & 31, wid = tid >> 5;
    uint32_t bB0 = smem_u32(Bm0);
    uint32_t bW  = smem_u32(Wm);

    #pragma unroll 1
    for (int buf = 0; buf < 2; buf++)
        for (int i = tid; i < (208 - K3) * 8; i += 256) {
            int k = K3 + (i >> 3), ch = i & 7;
            *(uint4*)(Bm0 + buf * BIMG + swA((uint32_t)(k * 128 + ch * 16))) = make_uint4(0, 0, 0, 0);
        }
    for (int i = tid; i < Fall * 27; i += 256) {
        int f = i / 27, ch = i - f * 27;
        cpa16(bW + f * 432 + ch * 16, Wimg + f * 216 + ch * 8);
    }
    if (tid < Fall) {
        bs[tid] = bias[tid];
        if (PROJ && tid < 64) wproj[tid] = pW[tid];
    }

    auto load_feats = [&](int buf, int n) {
        const __half* s0 = F0 + (size_t)n * LD;
        const __half* s1 = F1 + (size_t)n * LD;
        const __half* s2 = F2 + (size_t)n * LD;
        uint32_t base = bB0 + buf * BIMG;
        for (int i = tid; i < K3 * 8; i += 256) {
            int k = i >> 3, ch = i & 7;
            int kk = k / C, c = k - kk * C;
            const __half* s = (kk == 0) ? s0 : ((kk == 1) ? s1 : s2);
            cpa16(base + swA((uint32_t)(k * 128 + ch * 16)), s + c * 64 + ch * 8);
        }
        asm volatile("cp.async.commit_group;" ::: "memory");
    };

    int nth = gridDim.x;
    int count = (NN - blockIdx.x + nth - 1) / nth;
    load_feats(0, blockIdx.x);

    int wm = GATE ? (wid & 3) : (wid & 1);
    int wn = GATE ? (wid >> 2) : (wid >> 1);
    int f0 = wm * 32;
    int nb0 = wn * (GATE ? 32 : 16);
    int bk  = (lane & 7) + ((lane >> 3) & 1) * 8;
    int bn8 = ((lane >> 4) & 1) * 8;
    int r_lo = lane >> 2, c_lo = (lane & 3) * 2;

    #pragma unroll 1
    for (int i = 0; i < count; i++) {
        int n = blockIdx.x + i * nth;
        int buf = i & 1;
        if (i + 1 < count) {
            load_feats(buf ^ 1, n + nth);
            asm volatile("cp.async.wait_group 1;" ::: "memory");
        } else {
            asm volatile("cp.async.wait_group 0;" ::: "memory");
        }
        __syncthreads();
        uint32_t bB = bB0 + buf * BIMG;

        float acc[2][2 * NP][4];
        #pragma unroll
        for (int mt = 0; mt < 2; mt++)
            #pragma unroll
            for (int nt = 0; nt < 2 * NP; nt++)
                #pragma unroll
                for (int j = 0; j < 4; j++) acc[mt][nt][j] = 0.f;

        #pragma unroll 1
        for (int kt = 0; kt < 13; kt++) {
            uint32_t aF[2][4];
            #pragma unroll
            for (int mt = 0; mt < 2; mt++) {
                uint32_t ao = (uint32_t)((f0 + mt * 16 + (lane & 15)) * 432 + kt * 32 + (lane >> 4) * 16);
                ldsm4(aF[mt], bW + ao);
            }
            #pragma unroll
            for (int p = 0; p < NP; p++) {
                uint32_t bo = swA((uint32_t)((kt * 16 + bk) * 128 + (nb0 + p * 16 + bn8) * 2));
                uint32_t bF[4];
                ldsm4t(bF, bB + bo);
                #pragma unroll
                for (int mt = 0; mt < 2; mt++) {
                    mma_f16(acc[mt][2 * p],     aF[mt], bF[0], bF[1]);
                    mma_f16(acc[mt][2 * p + 1], aF[mt], bF[2], bF[3]);
                }
            }
        }

        size_t nLD = (size_t)n * LD;
        size_t nH  = (size_t)n * 4096;
        float ps[4] = {0.f, 0.f, 0.f, 0.f};
        #pragma unroll
        for (int mt = 0; mt < 2; mt++) {
            int row = f0 + mt * 16 + r_lo;
            #pragma unroll
            for (int nt = 0; nt < 2 * NP; nt++) {
                int col = nb0 + nt * 8 + c_lo;
                float v0 = acc[mt][nt][0] + bs[row];
                float v1 = acc[mt][nt][1] + bs[row];
                float v2 = acc[mt][nt][2] + bs[row + 8];
                float v3 = acc[mt][nt][3] + bs[row + 8];
                if (GATE) {
                    if (row < 64) {
                        #pragma unroll
                        for (int q = 0; q < 2; q++) {
                            int f = row + q * 8;
                            float z0 = 1.f / (1.f + expf(-(q ? v2 : v0)));
                            float z1 = 1.f / (1.f + expf(-(q ? v3 : v1)));
                            float2 hv = *(const float2*)(hin + nH + (size_t)f * 64 + col);
                            st2h(outC, nLD + (size_t)(OFF + f) * 64 + col, z0 * hv.x, z1 * hv.y);
                        }
                    } else {
                        #pragma unroll
                        for (int q = 0; q < 2; q++) {
                            int f = row - 64 + q * 8;
                            float r0 = 1.f / (1.f + expf(-(q ? v2 : v0)));
                            float r1 = 1.f / (1.f + expf(-(q ? v3 : v1)));
                            *(float2*)(rbuf + nH + (size_t)f * 64 + col) = make_float2(r0, r1);
                        }
                    }
                } else {
                    #pragma unroll
                    for (int q = 0; q < 2; q++) {
                        int f = row + q * 8;
                        float hc0 = tanhf(q ? v2 : v0);
                        float hc1 = tanhf(q ? v3 : v1);
                        float2 rv = *(const float2*)(rbuf + nH + (size_t)f * 64 + col);
                        float2 hv = *(const float2*)(hin  + nH + (size_t)f * 64 + col);
                        float hn0 = rv.x * hv.x + (1.f - rv.x) * hc0;
                        float hn1 = rv.y * hv.y + (1.f - rv.y) * hc1;
                        *(float2*)(hout + nH + (size_t)f * 64 + col) = make_float2(hn0, hn1);
                        st2h(outC, nLD + (size_t)(offn + f) * 64 + col, hn0, hn1);
                        if (PROJ) {
                            float w = wproj[f];
                            ps[nt * 2 + 0] = fmaf(hn0, w, ps[nt * 2 + 0]);
                            ps[nt * 2 + 1] = fmaf(hn1, w, ps[nt * 2 + 1]);
                        }
                    }
                }
            }
        }
        if (GATE) {
            // copy exogenous slots [0, OFF*64) from cat1 (F0) into cat2 (outC)
            if (tid < OFF * 64)
                outC[nLD + tid] = F0[nLD + tid];
        } else if (PROJ) {
            #pragma unroll
            for (int j = 0; j < 4; j++) {
                #pragma unroll
                for (int o = 4; o <= 16; o <<= 1)
                    ps[j] += __shfl_xor_sync(0xffffffffu, ps[j], o);
            }
            if (lane < 4) {
                #pragma unroll
                for (int nt = 0; nt < 2; nt++) {
                    int col = nb0 + nt * 8 + (lane & 3) * 2;
                    sred[wm * 64 + col]     = ps[nt * 2 + 0];
                    sred[wm * 64 + col + 1] = ps[nt * 2 + 1];
                }
            }
            __syncthreads();
            if (tid < 64) {
                float v = sred[tid] + sred[64 + tid] + pb[0];
                out[(size_t)(tid * TT + t) * NN + n] = v;
                outC[nLD + tid] = __float2half(v);                 // next go -> slot 0
                if (nyc) outC[nLD + 64 + tid] =
                    __float2half(nyc[(size_t)(tid * TT + tn) * NN + n]);  // ycov -> slot 1
            }
        } else {
            // encoder update: write next step's exogenous columns into cat1
            if (tid < 64) {
                float xv = nxt ? nxt[(size_t)(tid * TT + tn) * NN + n] : 0.f;
                outC[nLD + tid] = __float2half(xv);
                if (nyc) outC[nLD + 64 + tid] =
                    __float2half(nyc[(size_t)(tid * TT + tn) * NN + n]);
            }
        }
        __syncthreads();
    }
}

// ---------------- bootstrap injection (t=0 only) ----------------
__global__ void inject_enc(const float* __restrict__ x, int t,
                           __half* __restrict__ c1, __half* __restrict__ c2) {
    int n = blockIdx.x, b = threadIdx.x;
    __half v = __float2half(x[(size_t)(b * TT + t) * NN + n]);
    size_t pos = (size_t)n * LD + b;
    c1[pos] = v;
    c2[pos] = v;
}

// ---------------- orchestration ----------------
extern "C" void kernel_launch(void* const* d_in, const int* in_sizes, int n_in,
                              void* d_out, int out_size) {
    const float* x    = (const float*)d_in[0];
    const float* ycov = (const float*)d_in[1];
    const float* emb  = (const float*)d_in[2];
    const float* egW  = (const float*)d_in[3];
    const float* egb  = (const float*)d_in[4];
    const float* euW  = (const float*)d_in[5];
    const float* eub  = (const float*)d_in[6];
    const float* dgW  = (const float*)d_in[7];
    const float* dgb  = (const float*)d_in[8];
    const float* duW  = (const float*)d_in[9];
    const float* dub  = (const float*)d_in[10];
    const float* pW   = (const float*)d_in[11];
    const float* pb   = (const float*)d_in[12];
    float* out = (float*)d_out;

    float *pM, *ph, *pr;
    __half *pMh, *pc1, *pc2, *pY1, *pY2, *pWgE, *pWgD, *pWuE, *pWuD;
    cudaGetSymbolAddress((void**)&pM,   g_M);
    cudaGetSymbolAddress((void**)&pMh,  g_Mh);
    cudaGetSymbolAddress((void**)&pc1,  g_c1);
    cudaGetSymbolAddress((void**)&pc2,  g_c2);
    cudaGetSymbolAddress((void**)&pY1,  g_Y1);
    cudaGetSymbolAddress((void**)&pY2,  g_Y2);
    cudaGetSymbolAddress((void**)&ph,   g_h);
    cudaGetSymbolAddress((void**)&pr,   g_r);
    cudaGetSymbolAddress((void**)&pWgE, g_WgE);
    cudaGetSymbolAddress((void**)&pWgD, g_WgD);
    cudaGetSymbolAddress((void**)&pWuE, g_WuE);
    cudaGetSymbolAddress((void**)&pWuD, g_WuD);

    const int smHM = 2 * STG;                                        // 65536
    const int smG  = 2 * (208 * 128) + 128 * 432 + (128 + 64 + 128) * 4;  // 109,824
    const int smU  = 2 * (208 * 128) + 64 * 432 + (64 + 64 + 128) * 4;    // 81,920
    cudaFuncSetAttribute((const void*)hmma_gemm,                  cudaFuncAttributeMaxDynamicSharedMemorySize, smHM);
    cudaFuncSetAttribute((const void*)cell_mm<65, true,  false>,  cudaFuncAttributeMaxDynamicSharedMemorySize, smG);
    cudaFuncSetAttribute((const void*)cell_mm<66, true,  false>,  cudaFuncAttributeMaxDynamicSharedMemorySize, smG);
    cudaFuncSetAttribute((const void*)cell_mm<65, false, false>,  cudaFuncAttributeMaxDynamicSharedMemorySize, smU);
    cudaFuncSetAttribute((const void*)cell_mm<66, false, true>,   cudaFuncAttributeMaxDynamicSharedMemorySize, smU);

    cudaMemsetAsync(ph,  0, (size_t)NN * 64 * 64 * sizeof(float));
    cudaMemsetAsync(pc1, 0, (size_t)NN * LD * sizeof(__half));
    cudaMemsetAsync(pc2, 0, (size_t)NN * LD * sizeof(__half));

    build_support_kernel<<<NN, 256>>>(emb, pM);
    gemmA2<<<dim3(8, 8), 256>>>(pM, pM + (size_t)NN * NN);
    convert_M<<<2 * NN * NN / 256, 256>>>(pM, pMh);
    prep_W<<<128, 64>>>(egW, 65, 128, pWgE);
    prep_W<<<128, 64>>>(dgW, 66, 128, pWgD);
    prep_W<<<64, 64>>>(euW, 65, 64, pWuE);
    prep_W<<<64, 64>>>(duW, 66, 64, pWuD);

    inject_enc<<<NN, 64>>>(x, 0, pc1, pc2);

    dim3 gg(33, 16);
    for (int t = 0; t < TT; t++) {
        hmma_gemm<<<gg, 256, smHM>>>(pMh, pc1, pY1, pY2);
        cell_mm<65, true, false><<<GRID_CELL, 256, smG>>>(
            pc1, pY1, pY2, pWgE, egb, ph, pr, pc2, nullptr, 0,
            nullptr, nullptr, 0, nullptr, nullptr, nullptr, 0);
        hmma_gemm<<<gg, 256, smHM>>>(pMh, pc2, pY1, pY2);
        bool last = (t == TT - 1);
        cell_mm<65, false, false><<<GRID_CELL, 256, smU>>>(
            pc2, pY1, pY2, pWuE, eub, ph, pr, pc1, ph, last ? 2 : 1,
            last ? nullptr : x, last ? ycov : nullptr, last ? 0 : (t + 1),
            nullptr, nullptr, nullptr, 0);
    }
    for (int t = 0; t < TT; t++) {
        hmma_gemm<<<gg, 256, smHM>>>(pMh, pc1, pY1, pY2);
        cell_mm<66, true, false><<<GRID_CELL, 256, smG>>>(
            pc1, pY1, pY2, pWgD, dgb, ph, pr, pc2, nullptr, 0,
            nullptr, nullptr, 0, nullptr, nullptr, nullptr, 0);
        hmma_gemm<<<gg, 256, smHM>>>(pMh, pc2, pY1, pY2);
        bool last = (t == TT - 1);
        cell_mm<66, false, true><<<GRID_CELL, 256, smU>>>(
            pc2, pY1, pY2, pWuD, dub, ph, pr, pc1, ph, 2,
            nullptr, last ? nullptr : ycov, t + 1,
            pW, pb, out, t);
    }
}